// round 1
// baseline (speedup 1.0000x reference)
#include <cuda_runtime.h>
#include <math.h>

#define Bsz 2
#define S 2048
#define H 1024
#define NH 16
#define HD 64

// Scratch (allocation-free rule: __device__ globals)
__device__ float g_tmp[Bsz * S * H];
__device__ float g_q[Bsz * S * H];
__device__ float g_k[Bsz * S * H];
__device__ float g_v[Bsz * S * H];
__device__ float g_ctx[Bsz * S * H];

// ---------------------------------------------------------------------------
// C[M,N] = A[M,K] * B[N,K]^T  (both row-major, K-contiguous; dims: M%128==0,
// N%128==0, K%16==0). 128x128 tile, 256 threads, 8x8 micro-tile per thread.
// ---------------------------------------------------------------------------
__global__ __launch_bounds__(256) void gemm_nt(const float* __restrict__ A,
                                               const float* __restrict__ Bw,
                                               float* __restrict__ C,
                                               int M, int N, int K) {
    __shared__ float As[16][132];
    __shared__ float Bs[16][132];
    const int tid = threadIdx.x;
    const int m0 = blockIdx.y * 128;
    const int n0 = blockIdx.x * 128;
    const int tx = tid & 15;
    const int ty = tid >> 4;

    float acc[8][8];
#pragma unroll
    for (int i = 0; i < 8; i++)
#pragma unroll
        for (int j = 0; j < 8; j++) acc[i][j] = 0.f;

    for (int k0 = 0; k0 < K; k0 += 16) {
#pragma unroll
        for (int i = 0; i < 2; i++) {
            int idx = tid + i * 256;      // 0..511
            int row = idx >> 2;           // 0..127
            int kc = (idx & 3) << 2;      // 0,4,8,12
            float4 va = *(const float4*)(A + (size_t)(m0 + row) * K + k0 + kc);
            As[kc + 0][row] = va.x; As[kc + 1][row] = va.y;
            As[kc + 2][row] = va.z; As[kc + 3][row] = va.w;
            float4 vb = *(const float4*)(Bw + (size_t)(n0 + row) * K + k0 + kc);
            Bs[kc + 0][row] = vb.x; Bs[kc + 1][row] = vb.y;
            Bs[kc + 2][row] = vb.z; Bs[kc + 3][row] = vb.w;
        }
        __syncthreads();
#pragma unroll
        for (int k = 0; k < 16; k++) {
            float a[8], bb[8];
#pragma unroll
            for (int i = 0; i < 8; i++) a[i] = As[k][ty * 8 + i];
#pragma unroll
            for (int j = 0; j < 8; j++) bb[j] = Bs[k][tx * 8 + j];
#pragma unroll
            for (int i = 0; i < 8; i++)
#pragma unroll
                for (int j = 0; j < 8; j++)
                    acc[i][j] = fmaf(a[i], bb[j], acc[i][j]);
        }
        __syncthreads();
    }

#pragma unroll
    for (int i = 0; i < 8; i++) {
        int m = m0 + ty * 8 + i;
#pragma unroll
        for (int j = 0; j < 8; j += 4) {
            float4 v = make_float4(acc[i][j], acc[i][j + 1], acc[i][j + 2], acc[i][j + 3]);
            *(float4*)(C + (size_t)m * N + n0 + tx * 8 + j) = v;
        }
    }
}

// ---------------------------------------------------------------------------
// src: [B, S, H] (H = nh*hd). dst: [B, nh, S, hd]. Optionally apply RoPE.
// One thread per (b,h,s, d<32) pair; handles dims d and d+32.
// ---------------------------------------------------------------------------
__global__ __launch_bounds__(256) void rope_transpose(const float* __restrict__ src,
                                                      float* __restrict__ dst,
                                                      int apply_rope) {
    int idx = blockIdx.x * blockDim.x + threadIdx.x;
    if (idx >= Bsz * NH * S * 32) return;
    int d = idx & 31;
    int s = (idx >> 5) & (S - 1);
    int h = (idx >> 16) & (NH - 1);
    int b = idx >> 20;

    const float* p = src + (size_t)(b * S + s) * H + h * HD;
    float v0 = p[d];
    float v1 = p[d + 32];

    if (apply_rope) {
        // inv_freq = 10000^{-2d/64}; compute angle in double for accuracy at s~2048
        double inv = pow(10000.0, -(double)(2 * d) / 64.0);
        double ang = (double)s * inv;
        double sd, cd;
        sincos(ang, &sd, &cd);
        float c = (float)cd, sn = (float)sd;
        float n0 = v0 * c - v1 * sn;   // q[d]   = q[d]*cos - q[d+32]*sin
        float n1 = v1 * c + v0 * sn;   // q[d+32]= q[d+32]*cos + q[d]*sin
        v0 = n0; v1 = n1;
    }

    float* o = dst + ((size_t)(b * NH + h) * S + s) * HD;
    o[d] = v0;
    o[d + 32] = v1;
}

// ---------------------------------------------------------------------------
// scores = (Q K^T)/8 + bias, pad-mask -> -1e30, written raw into attn buffer.
// Q,Kt: [B*NH, S, HD]. 128x128 tile; blocks entirely above causal diag exit.
// ---------------------------------------------------------------------------
__global__ __launch_bounds__(256) void scores_kernel(const float* __restrict__ Q,
                                                     const float* __restrict__ Kt,
                                                     const float* __restrict__ bias,
                                                     const int* __restrict__ mask,
                                                     float* __restrict__ attn) {
    const int bh = blockIdx.z;
    const int b = bh >> 4;
    const int m0 = blockIdx.y * 128;   // queries
    const int n0 = blockIdx.x * 128;   // keys
    if (n0 > m0 + 127) return;         // fully above diagonal -> never read

    __shared__ float Qs[32][132];
    __shared__ float Ks[32][132];
    const int tid = threadIdx.x;
    const int tx = tid & 15;
    const int ty = tid >> 4;
    const float* Qb = Q + (size_t)bh * S * HD;
    const float* Kb = Kt + (size_t)bh * S * HD;

    float acc[8][8];
#pragma unroll
    for (int i = 0; i < 8; i++)
#pragma unroll
        for (int j = 0; j < 8; j++) acc[i][j] = 0.f;

    for (int kk = 0; kk < HD; kk += 32) {
#pragma unroll
        for (int i = 0; i < 4; i++) {
            int idx = tid + i * 256;      // 0..1023
            int row = idx >> 3;           // 0..127
            int col = (idx & 7) << 2;     // 0..28
            float4 va = *(const float4*)(Qb + (size_t)(m0 + row) * HD + kk + col);
            Qs[col + 0][row] = va.x; Qs[col + 1][row] = va.y;
            Qs[col + 2][row] = va.z; Qs[col + 3][row] = va.w;
            float4 vb = *(const float4*)(Kb + (size_t)(n0 + row) * HD + kk + col);
            Ks[col + 0][row] = vb.x; Ks[col + 1][row] = vb.y;
            Ks[col + 2][row] = vb.z; Ks[col + 3][row] = vb.w;
        }
        __syncthreads();
#pragma unroll
        for (int k = 0; k < 32; k++) {
            float a[8], bb[8];
#pragma unroll
            for (int i = 0; i < 8; i++) a[i] = Qs[k][ty * 8 + i];
#pragma unroll
            for (int j = 0; j < 8; j++) bb[j] = Ks[k][tx * 8 + j];
#pragma unroll
            for (int i = 0; i < 8; i++)
#pragma unroll
                for (int j = 0; j < 8; j++)
                    acc[i][j] = fmaf(a[i], bb[j], acc[i][j]);
        }
        __syncthreads();
    }

    int mk[8];
#pragma unroll
    for (int j = 0; j < 8; j++) mk[j] = mask[b * S + n0 + tx * 8 + j];

#pragma unroll
    for (int i = 0; i < 8; i++) {
        int q = m0 + ty * 8 + i;
        float* arow = attn + ((size_t)bh * S + q) * S;
        const float* brow = bias + (size_t)q * S;
#pragma unroll
        for (int j = 0; j < 8; j++) {
            int key = n0 + tx * 8 + j;
            float val = acc[i][j] * 0.125f + brow[key];
            if (mk[j] == 0) val = -1e30f;
            arow[key] = val;
        }
    }
}

// ---------------------------------------------------------------------------
// Row-wise causal softmax in-place over attn rows. One block per (bh, q) row.
// Row cached in smem; keys > q written as 0 (d_out is poisoned).
// ---------------------------------------------------------------------------
__global__ __launch_bounds__(256) void softmax_kernel(float* __restrict__ attn) {
    __shared__ float sc[S];
    __shared__ float red[8];
    const int row = blockIdx.x;        // bh*S + q
    const int q = row & (S - 1);
    const int n = q + 1;
    float* a = attn + (size_t)row * S;
    const int tid = threadIdx.x;

    float m = -3e38f;
    for (int k = tid; k < n; k += 256) {
        float v = a[k];
        sc[k] = v;
        m = fmaxf(m, v);
    }
#pragma unroll
    for (int o = 16; o; o >>= 1) m = fmaxf(m, __shfl_xor_sync(0xffffffffu, m, o));
    if ((tid & 31) == 0) red[tid >> 5] = m;
    __syncthreads();
    m = red[0];
#pragma unroll
    for (int w = 1; w < 8; w++) m = fmaxf(m, red[w]);
    __syncthreads();

    float ssum = 0.f;
    for (int k = tid; k < n; k += 256) {
        float e = __expf(sc[k] - m);
        sc[k] = e;
        ssum += e;
    }
#pragma unroll
    for (int o = 16; o; o >>= 1) ssum += __shfl_xor_sync(0xffffffffu, ssum, o);
    if ((tid & 31) == 0) red[tid >> 5] = ssum;
    __syncthreads();
    ssum = 0.f;
#pragma unroll
    for (int w = 0; w < 8; w++) ssum += red[w];

    float inv = 1.f / ssum;
    for (int k = tid; k < S; k += 256) a[k] = (k < n) ? sc[k] * inv : 0.f;
}

// ---------------------------------------------------------------------------
// ctx[b,s,h,:] = attn[bh, s, :] @ V[bh, :, :]. 128 queries x 64 dims per block;
// k-loop bounded by causal structure (attn rows are 0 beyond m0+127).
// ---------------------------------------------------------------------------
__global__ __launch_bounds__(256) void av_kernel(const float* __restrict__ attn,
                                                 const float* __restrict__ V,
                                                 float* __restrict__ ctx) {
    const int bh = blockIdx.z;
    const int b = bh >> 4;
    const int h = bh & 15;
    const int m0 = blockIdx.x * 128;

    __shared__ float As[32][132];
    __shared__ float Vs[32][68];
    const int tid = threadIdx.x;
    const int tx = tid & 15;
    const int ty = tid >> 4;
    const float* Ab = attn + (size_t)bh * S * S;
    const float* Vb = V + (size_t)bh * S * HD;

    float acc[8][4];
#pragma unroll
    for (int i = 0; i < 8; i++)
#pragma unroll
        for (int j = 0; j < 4; j++) acc[i][j] = 0.f;

    const int kmax = m0 + 128;   // attn is exactly 0 for keys > q
    for (int k0 = 0; k0 < kmax; k0 += 32) {
#pragma unroll
        for (int i = 0; i < 4; i++) {
            int idx = tid + i * 256;      // 0..1023
            int row = idx >> 3;           // 0..127
            int col = (idx & 7) << 2;     // 0..28
            float4 va = *(const float4*)(Ab + (size_t)(m0 + row) * S + k0 + col);
            As[col + 0][row] = va.x; As[col + 1][row] = va.y;
            As[col + 2][row] = va.z; As[col + 3][row] = va.w;
        }
#pragma unroll
        for (int i = 0; i < 2; i++) {
            int idx = tid + i * 256;      // 0..511
            int row = idx >> 4;           // 0..31
            int col = (idx & 15) << 2;    // 0..60
            *(float4*)(&Vs[row][col]) =
                *(const float4*)(Vb + (size_t)(k0 + row) * HD + col);
        }
        __syncthreads();
#pragma unroll
        for (int k = 0; k < 32; k++) {
            float a[8], vv[4];
#pragma unroll
            for (int i = 0; i < 8; i++) a[i] = As[k][ty * 8 + i];
#pragma unroll
            for (int j = 0; j < 4; j++) vv[j] = Vs[k][tx * 4 + j];
#pragma unroll
            for (int i = 0; i < 8; i++)
#pragma unroll
                for (int j = 0; j < 4; j++)
                    acc[i][j] = fmaf(a[i], vv[j], acc[i][j]);
        }
        __syncthreads();
    }

#pragma unroll
    for (int i = 0; i < 8; i++) {
        int s = m0 + ty * 8 + i;
        float4 v = make_float4(acc[i][0], acc[i][1], acc[i][2], acc[i][3]);
        *(float4*)(ctx + ((size_t)(b * S + s) * NH + h) * HD + tx * 4) = v;
    }
}

// ---------------------------------------------------------------------------
extern "C" void kernel_launch(void* const* d_in, const int* in_sizes, int n_in,
                              void* d_out, int out_size) {
    const float* x    = (const float*)d_in[0];
    const int*   mask = (const int*)d_in[1];
    const float* Wq   = (const float*)d_in[2];
    const float* Wk   = (const float*)d_in[3];
    const float* Wv   = (const float*)d_in[4];
    const float* Wo   = (const float*)d_in[5];
    const float* bias = (const float*)d_in[6];

    float* out  = (float*)d_out;
    float* attn = out + (size_t)Bsz * S * H;   // output first, then attn

    float *tmp, *q, *k, *v, *ctx;
    cudaGetSymbolAddress((void**)&tmp, g_tmp);
    cudaGetSymbolAddress((void**)&q,   g_q);
    cudaGetSymbolAddress((void**)&k,   g_k);
    cudaGetSymbolAddress((void**)&v,   g_v);
    cudaGetSymbolAddress((void**)&ctx, g_ctx);

    const int M = Bsz * S;                 // 4096
    dim3 gproj(H / 128, M / 128);          // (8, 32)
    const int rope_threads = Bsz * NH * S * 32;

    gemm_nt<<<gproj, 256>>>(x, Wq, tmp, M, H, H);
    rope_transpose<<<rope_threads / 256, 256>>>(tmp, q, 1);

    gemm_nt<<<gproj, 256>>>(x, Wk, tmp, M, H, H);
    rope_transpose<<<rope_threads / 256, 256>>>(tmp, k, 1);

    gemm_nt<<<gproj, 256>>>(x, Wv, tmp, M, H, H);
    rope_transpose<<<rope_threads / 256, 256>>>(tmp, v, 0);

    scores_kernel<<<dim3(S / 128, S / 128, Bsz * NH), 256>>>(q, k, bias, mask, attn);
    softmax_kernel<<<Bsz * NH * S, 256>>>(attn);
    av_kernel<<<dim3(S / 128, 1, Bsz * NH), 256>>>(attn, v, ctx);
    gemm_nt<<<gproj, 256>>>(ctx, Wo, out, M, H, H);
}

// round 2
// speedup vs baseline: 1.4550x; 1.4550x over previous
#include <cuda_runtime.h>
#include <math.h>

#define Bsz 2
#define S 2048
#define H 1024
#define NH 16
#define HD 64

// Scratch (allocation-free rule: __device__ globals)
__device__ float g_tmp[Bsz * S * H];
__device__ float g_q[Bsz * S * H];
__device__ float g_k[Bsz * S * H];
__device__ float g_v[Bsz * S * H];
__device__ float g_ctx[Bsz * S * H];
__device__ float g_cos[S * 32];
__device__ float g_sin[S * 32];

// ---------------------------------------------------------------------------
// RoPE cos/sin table: 2048 positions x 32 freq pairs, computed in double once
// per launch (65536 threads total — negligible), matching reference accuracy.
// ---------------------------------------------------------------------------
__global__ __launch_bounds__(256) void rope_table_kernel() {
    int idx = blockIdx.x * blockDim.x + threadIdx.x;
    if (idx >= S * 32) return;
    int d = idx & 31;
    int s = idx >> 5;
    double inv = pow(10000.0, -(double)(2 * d) / 64.0);
    double ang = (double)s * inv;
    double sd, cd;
    sincos(ang, &sd, &cd);
    g_cos[idx] = (float)cd;
    g_sin[idx] = (float)sd;
}

// ---------------------------------------------------------------------------
// C[M,N] = A[M,K] * B[N,K]^T  (both row-major, K-contiguous; dims: M%128==0,
// N%128==0, K%16==0). 128x128 tile, 256 threads, 8x8 micro-tile per thread.
// ---------------------------------------------------------------------------
__global__ __launch_bounds__(256) void gemm_nt(const float* __restrict__ A,
                                               const float* __restrict__ Bw,
                                               float* __restrict__ C,
                                               int M, int N, int K) {
    __shared__ float As[16][132];
    __shared__ float Bs[16][132];
    const int tid = threadIdx.x;
    const int m0 = blockIdx.y * 128;
    const int n0 = blockIdx.x * 128;
    const int tx = tid & 15;
    const int ty = tid >> 4;

    float acc[8][8];
#pragma unroll
    for (int i = 0; i < 8; i++)
#pragma unroll
        for (int j = 0; j < 8; j++) acc[i][j] = 0.f;

    for (int k0 = 0; k0 < K; k0 += 16) {
#pragma unroll
        for (int i = 0; i < 2; i++) {
            int idx = tid + i * 256;      // 0..511
            int row = idx >> 2;           // 0..127
            int kc = (idx & 3) << 2;      // 0,4,8,12
            float4 va = *(const float4*)(A + (size_t)(m0 + row) * K + k0 + kc);
            As[kc + 0][row] = va.x; As[kc + 1][row] = va.y;
            As[kc + 2][row] = va.z; As[kc + 3][row] = va.w;
            float4 vb = *(const float4*)(Bw + (size_t)(n0 + row) * K + k0 + kc);
            Bs[kc + 0][row] = vb.x; Bs[kc + 1][row] = vb.y;
            Bs[kc + 2][row] = vb.z; Bs[kc + 3][row] = vb.w;
        }
        __syncthreads();
#pragma unroll
        for (int k = 0; k < 16; k++) {
            float a[8], bb[8];
#pragma unroll
            for (int i = 0; i < 8; i++) a[i] = As[k][ty * 8 + i];
#pragma unroll
            for (int j = 0; j < 8; j++) bb[j] = Bs[k][tx * 8 + j];
#pragma unroll
            for (int i = 0; i < 8; i++)
#pragma unroll
                for (int j = 0; j < 8; j++)
                    acc[i][j] = fmaf(a[i], bb[j], acc[i][j]);
        }
        __syncthreads();
    }

#pragma unroll
    for (int i = 0; i < 8; i++) {
        int m = m0 + ty * 8 + i;
#pragma unroll
        for (int j = 0; j < 8; j += 4) {
            float4 v = make_float4(acc[i][j], acc[i][j + 1], acc[i][j + 2], acc[i][j + 3]);
            *(float4*)(C + (size_t)m * N + n0 + tx * 8 + j) = v;
        }
    }
}

// ---------------------------------------------------------------------------
// src: [B, S, H] (H = nh*hd). dst: [B, nh, S, hd]. Optionally apply RoPE
// using the precomputed table. One thread per (b,h,s, d<32); handles d, d+32.
// ---------------------------------------------------------------------------
__global__ __launch_bounds__(256) void rope_transpose(const float* __restrict__ src,
                                                      float* __restrict__ dst,
                                                      int apply_rope) {
    int idx = blockIdx.x * blockDim.x + threadIdx.x;
    if (idx >= Bsz * NH * S * 32) return;
    int d = idx & 31;
    int s = (idx >> 5) & (S - 1);
    int h = (idx >> 16) & (NH - 1);
    int b = idx >> 20;

    const float* p = src + (size_t)(b * S + s) * H + h * HD;
    float v0 = p[d];
    float v1 = p[d + 32];

    if (apply_rope) {
        float c = g_cos[s * 32 + d];
        float sn = g_sin[s * 32 + d];
        float n0 = v0 * c - v1 * sn;   // q[d]   = q[d]*cos - q[d+32]*sin
        float n1 = v1 * c + v0 * sn;   // q[d+32]= q[d+32]*cos + q[d]*sin
        v0 = n0; v1 = n1;
    }

    float* o = dst + ((size_t)(b * NH + h) * S + s) * HD;
    o[d] = v0;
    o[d + 32] = v1;
}

// ---------------------------------------------------------------------------
// scores = (Q K^T)/8 + bias, pad-mask -> -1e30, written raw into attn buffer.
// Q,Kt: [B*NH, S, HD]. 128x128 tile; blocks entirely above causal diag exit.
// ---------------------------------------------------------------------------
__global__ __launch_bounds__(256) void scores_kernel(const float* __restrict__ Q,
                                                     const float* __restrict__ Kt,
                                                     const float* __restrict__ bias,
                                                     const int* __restrict__ mask,
                                                     float* __restrict__ attn) {
    const int bh = blockIdx.z;
    const int b = bh >> 4;
    const int m0 = blockIdx.y * 128;   // queries
    const int n0 = blockIdx.x * 128;   // keys
    if (n0 > m0 + 127) return;         // fully above diagonal -> never read

    __shared__ float Qs[32][132];
    __shared__ float Ks[32][132];
    const int tid = threadIdx.x;
    const int tx = tid & 15;
    const int ty = tid >> 4;
    const float* Qb = Q + (size_t)bh * S * HD;
    const float* Kb = Kt + (size_t)bh * S * HD;

    float acc[8][8];
#pragma unroll
    for (int i = 0; i < 8; i++)
#pragma unroll
        for (int j = 0; j < 8; j++) acc[i][j] = 0.f;

    for (int kk = 0; kk < HD; kk += 32) {
#pragma unroll
        for (int i = 0; i < 4; i++) {
            int idx = tid + i * 256;      // 0..1023
            int row = idx >> 3;           // 0..127
            int col = (idx & 7) << 2;     // 0..28
            float4 va = *(const float4*)(Qb + (size_t)(m0 + row) * HD + kk + col);
            Qs[col + 0][row] = va.x; Qs[col + 1][row] = va.y;
            Qs[col + 2][row] = va.z; Qs[col + 3][row] = va.w;
            float4 vb = *(const float4*)(Kb + (size_t)(n0 + row) * HD + kk + col);
            Ks[col + 0][row] = vb.x; Ks[col + 1][row] = vb.y;
            Ks[col + 2][row] = vb.z; Ks[col + 3][row] = vb.w;
        }
        __syncthreads();
#pragma unroll
        for (int k = 0; k < 32; k++) {
            float a[8], bb[8];
#pragma unroll
            for (int i = 0; i < 8; i++) a[i] = Qs[k][ty * 8 + i];
#pragma unroll
            for (int j = 0; j < 8; j++) bb[j] = Ks[k][tx * 8 + j];
#pragma unroll
            for (int i = 0; i < 8; i++)
#pragma unroll
                for (int j = 0; j < 8; j++)
                    acc[i][j] = fmaf(a[i], bb[j], acc[i][j]);
        }
        __syncthreads();
    }

    int mk[8];
#pragma unroll
    for (int j = 0; j < 8; j++) mk[j] = mask[b * S + n0 + tx * 8 + j];

#pragma unroll
    for (int i = 0; i < 8; i++) {
        int q = m0 + ty * 8 + i;
        float* arow = attn + ((size_t)bh * S + q) * S;
        const float* brow = bias + (size_t)q * S;
#pragma unroll
        for (int j = 0; j < 8; j++) {
            int key = n0 + tx * 8 + j;
            float val = acc[i][j] * 0.125f + brow[key];
            if (mk[j] == 0) val = -1e30f;
            arow[key] = val;
        }
    }
}

// ---------------------------------------------------------------------------
// Row-wise causal softmax in-place over attn rows. One block per (bh, q) row.
// Row cached in smem; keys > q written as 0 (d_out is poisoned).
// ---------------------------------------------------------------------------
__global__ __launch_bounds__(256) void softmax_kernel(float* __restrict__ attn) {
    __shared__ float sc[S];
    __shared__ float red[8];
    const int row = blockIdx.x;        // bh*S + q
    const int q = row & (S - 1);
    const int n = q + 1;
    float* a = attn + (size_t)row * S;
    const int tid = threadIdx.x;

    float m = -3e38f;
    for (int k = tid; k < n; k += 256) {
        float v = a[k];
        sc[k] = v;
        m = fmaxf(m, v);
    }
#pragma unroll
    for (int o = 16; o; o >>= 1) m = fmaxf(m, __shfl_xor_sync(0xffffffffu, m, o));
    if ((tid & 31) == 0) red[tid >> 5] = m;
    __syncthreads();
    m = red[0];
#pragma unroll
    for (int w = 1; w < 8; w++) m = fmaxf(m, red[w]);
    __syncthreads();

    float ssum = 0.f;
    for (int k = tid; k < n; k += 256) {
        float e = __expf(sc[k] - m);
        sc[k] = e;
        ssum += e;
    }
#pragma unroll
    for (int o = 16; o; o >>= 1) ssum += __shfl_xor_sync(0xffffffffu, ssum, o);
    if ((tid & 31) == 0) red[tid >> 5] = ssum;
    __syncthreads();
    ssum = 0.f;
#pragma unroll
    for (int w = 0; w < 8; w++) ssum += red[w];

    float inv = 1.f / ssum;
    for (int k = tid; k < S; k += 256) a[k] = (k < n) ? sc[k] * inv : 0.f;
}

// ---------------------------------------------------------------------------
// ctx[b,s,h,:] = attn[bh, s, :] @ V[bh, :, :]. 128 queries x 64 dims per block;
// k-loop bounded by causal structure (attn rows are 0 beyond m0+127).
// ---------------------------------------------------------------------------
__global__ __launch_bounds__(256) void av_kernel(const float* __restrict__ attn,
                                                 const float* __restrict__ V,
                                                 float* __restrict__ ctx) {
    const int bh = blockIdx.z;
    const int b = bh >> 4;
    const int h = bh & 15;
    const int m0 = blockIdx.x * 128;

    __shared__ float As[32][132];
    __shared__ float Vs[32][68];
    const int tid = threadIdx.x;
    const int tx = tid & 15;
    const int ty = tid >> 4;
    const float* Ab = attn + (size_t)bh * S * S;
    const float* Vb = V + (size_t)bh * S * HD;

    float acc[8][4];
#pragma unroll
    for (int i = 0; i < 8; i++)
#pragma unroll
        for (int j = 0; j < 4; j++) acc[i][j] = 0.f;

    const int kmax = m0 + 128;   // attn is exactly 0 for keys > q
    for (int k0 = 0; k0 < kmax; k0 += 32) {
#pragma unroll
        for (int i = 0; i < 4; i++) {
            int idx = tid + i * 256;      // 0..1023
            int row = idx >> 3;           // 0..127
            int col = (idx & 7) << 2;     // 0..28
            float4 va = *(const float4*)(Ab + (size_t)(m0 + row) * S + k0 + col);
            As[col + 0][row] = va.x; As[col + 1][row] = va.y;
            As[col + 2][row] = va.z; As[col + 3][row] = va.w;
        }
#pragma unroll
        for (int i = 0; i < 2; i++) {
            int idx = tid + i * 256;      // 0..511
            int row = idx >> 4;           // 0..31
            int col = (idx & 15) << 2;    // 0..60
            *(float4*)(&Vs[row][col]) =
                *(const float4*)(Vb + (size_t)(k0 + row) * HD + col);
        }
        __syncthreads();
#pragma unroll
        for (int k = 0; k < 32; k++) {
            float a[8], vv[4];
#pragma unroll
            for (int i = 0; i < 8; i++) a[i] = As[k][ty * 8 + i];
#pragma unroll
            for (int j = 0; j < 4; j++) vv[j] = Vs[k][tx * 4 + j];
#pragma unroll
            for (int i = 0; i < 8; i++)
#pragma unroll
                for (int j = 0; j < 4; j++)
                    acc[i][j] = fmaf(a[i], vv[j], acc[i][j]);
        }
        __syncthreads();
    }

#pragma unroll
    for (int i = 0; i < 8; i++) {
        int s = m0 + ty * 8 + i;
        float4 v = make_float4(acc[i][0], acc[i][1], acc[i][2], acc[i][3]);
        *(float4*)(ctx + ((size_t)(b * S + s) * NH + h) * HD + tx * 4) = v;
    }
}

// ---------------------------------------------------------------------------
extern "C" void kernel_launch(void* const* d_in, const int* in_sizes, int n_in,
                              void* d_out, int out_size) {
    const float* x    = (const float*)d_in[0];
    const int*   mask = (const int*)d_in[1];
    const float* Wq   = (const float*)d_in[2];
    const float* Wk   = (const float*)d_in[3];
    const float* Wv   = (const float*)d_in[4];
    const float* Wo   = (const float*)d_in[5];
    const float* bias = (const float*)d_in[6];

    float* out  = (float*)d_out;
    float* attn = out + (size_t)Bsz * S * H;   // output first, then attn

    float *tmp, *q, *k, *v, *ctx;
    cudaGetSymbolAddress((void**)&tmp, g_tmp);
    cudaGetSymbolAddress((void**)&q,   g_q);
    cudaGetSymbolAddress((void**)&k,   g_k);
    cudaGetSymbolAddress((void**)&v,   g_v);
    cudaGetSymbolAddress((void**)&ctx, g_ctx);

    const int M = Bsz * S;                 // 4096
    dim3 gproj(H / 128, M / 128);          // (8, 32)
    const int rope_threads = Bsz * NH * S * 32;

    rope_table_kernel<<<(S * 32) / 256, 256>>>();

    gemm_nt<<<gproj, 256>>>(x, Wq, tmp, M, H, H);
    rope_transpose<<<rope_threads / 256, 256>>>(tmp, q, 1);

    gemm_nt<<<gproj, 256>>>(x, Wk, tmp, M, H, H);
    rope_transpose<<<rope_threads / 256, 256>>>(tmp, k, 1);

    gemm_nt<<<gproj, 256>>>(x, Wv, tmp, M, H, H);
    rope_transpose<<<rope_threads / 256, 256>>>(tmp, v, 0);

    scores_kernel<<<dim3(S / 128, S / 128, Bsz * NH), 256>>>(q, k, bias, mask, attn);
    softmax_kernel<<<Bsz * NH * S, 256>>>(attn);
    av_kernel<<<dim3(S / 128, 1, Bsz * NH), 256>>>(attn, v, ctx);
    gemm_nt<<<gproj, 256>>>(ctx, Wo, out, M, H, H);
}

// round 3
// speedup vs baseline: 1.8561x; 1.2757x over previous
#include <cuda_runtime.h>
#include <cuda_bf16.h>
#include <math.h>
#include <stdint.h>

#define Bsz 2
#define S 2048
#define H 1024
#define NH 16
#define HD 64

// Scratch (allocation-free rule: __device__ globals)
__device__ float g_tmp[Bsz * S * H];
__device__ float g_q[Bsz * S * H];
__device__ float g_k[Bsz * S * H];
__device__ float g_v[Bsz * S * H];
__device__ float g_ctx[Bsz * S * H];
__device__ float g_cos[S * 32];
__device__ float g_sin[S * 32];
// split-bf16 buffers
__device__ __nv_bfloat16 g_xh[Bsz * S * H];
__device__ __nv_bfloat16 g_xl[Bsz * S * H];
__device__ __nv_bfloat16 g_ch[Bsz * S * H];
__device__ __nv_bfloat16 g_cl[Bsz * S * H];
__device__ __nv_bfloat16 g_wh[4 * H * H];
__device__ __nv_bfloat16 g_wl[4 * H * H];

// ---------------------------------------------------------------------------
// RoPE cos/sin table (double precision, once per launch).
// ---------------------------------------------------------------------------
__global__ __launch_bounds__(256) void rope_table_kernel() {
    int idx = blockIdx.x * blockDim.x + threadIdx.x;
    if (idx >= S * 32) return;
    int d = idx & 31;
    int s = idx >> 5;
    double inv = pow(10000.0, -(double)(2 * d) / 64.0);
    double ang = (double)s * inv;
    double sd, cd;
    sincos(ang, &sd, &cd);
    g_cos[idx] = (float)cd;
    g_sin[idx] = (float)sd;
}

// ---------------------------------------------------------------------------
// fp32 -> (bf16 hi, bf16 lo) split. n % 4 == 0.
// ---------------------------------------------------------------------------
__global__ __launch_bounds__(256) void split_kernel(const float* __restrict__ src,
                                                    __nv_bfloat16* __restrict__ hi,
                                                    __nv_bfloat16* __restrict__ lo,
                                                    int n) {
    int i = (blockIdx.x * 256 + threadIdx.x) * 4;
    if (i >= n) return;
    float4 v = *(const float4*)(src + i);
    __nv_bfloat16 h0 = __float2bfloat16(v.x);
    __nv_bfloat16 h1 = __float2bfloat16(v.y);
    __nv_bfloat16 h2 = __float2bfloat16(v.z);
    __nv_bfloat16 h3 = __float2bfloat16(v.w);
    __nv_bfloat16 l0 = __float2bfloat16(v.x - __bfloat162float(h0));
    __nv_bfloat16 l1 = __float2bfloat16(v.y - __bfloat162float(h1));
    __nv_bfloat16 l2 = __float2bfloat16(v.z - __bfloat162float(h2));
    __nv_bfloat16 l3 = __float2bfloat16(v.w - __bfloat162float(h3));
    *(__nv_bfloat162*)(hi + i)     = __halves2bfloat162(h0, h1);
    *(__nv_bfloat162*)(hi + i + 2) = __halves2bfloat162(h2, h3);
    *(__nv_bfloat162*)(lo + i)     = __halves2bfloat162(l0, l1);
    *(__nv_bfloat162*)(lo + i + 2) = __halves2bfloat162(l2, l3);
}

// ---------------------------------------------------------------------------
// Tensor-core split-bf16 GEMM: C[M,N] = A[M,K] @ B[N,K]^T in ~fp32 accuracy.
// C ~= Ahi Bhi^T + Alo Bhi^T + Ahi Blo^T   (lo*lo dropped, ~2^-18)
// Block tile 128x64, 256 threads (8 warps, 4x2), warp tile 32x32, k-step 32.
// ---------------------------------------------------------------------------
__device__ __forceinline__ void ldsm_x4(uint32_t (&r)[4], uint32_t addr) {
    asm volatile("ldmatrix.sync.aligned.m8n8.x4.shared.b16 {%0,%1,%2,%3}, [%4];"
                 : "=r"(r[0]), "=r"(r[1]), "=r"(r[2]), "=r"(r[3]) : "r"(addr));
}
__device__ __forceinline__ void mma16816(float (&c)[4], const uint32_t (&a)[4],
                                         uint32_t b0, uint32_t b1) {
    asm volatile(
        "mma.sync.aligned.m16n8k16.row.col.f32.bf16.bf16.f32 "
        "{%0,%1,%2,%3}, {%4,%5,%6,%7}, {%8,%9}, {%0,%1,%2,%3};"
        : "+f"(c[0]), "+f"(c[1]), "+f"(c[2]), "+f"(c[3])
        : "r"(a[0]), "r"(a[1]), "r"(a[2]), "r"(a[3]), "r"(b0), "r"(b1));
}

__global__ __launch_bounds__(256) void gemm_nt_split(
    const __nv_bfloat16* __restrict__ Ah, const __nv_bfloat16* __restrict__ Al,
    const __nv_bfloat16* __restrict__ Bh, const __nv_bfloat16* __restrict__ Bl,
    float* __restrict__ C, int M, int N, int K) {
    __shared__ __align__(16) __nv_bfloat16 sA[2][128][40];  // [hi/lo][row][k], 80B stride
    __shared__ __align__(16) __nv_bfloat16 sB[2][64][40];

    const int tid = threadIdx.x;
    const int wid = tid >> 5, lane = tid & 31;
    const int wm = (wid & 3) * 32;   // warp m offset within block tile
    const int wn = (wid >> 2) * 32;  // warp n offset
    const int m0 = blockIdx.y * 128, n0 = blockIdx.x * 64;

    float acc[2][4][4] = {};

    const uint32_t aBase = (uint32_t)__cvta_generic_to_shared(&sA[0][0][0]);
    const uint32_t bBase = (uint32_t)__cvta_generic_to_shared(&sB[0][0][0]);

    for (int k0 = 0; k0 < K; k0 += 32) {
#pragma unroll
        for (int i = 0; i < 2; i++) {  // A: 512 chunks of 8 bf16
            int c = tid + i * 256;
            int row = c >> 2, kc = (c & 3) * 8;
            *(uint4*)&sA[0][row][kc] = *(const uint4*)(Ah + (size_t)(m0 + row) * K + k0 + kc);
            *(uint4*)&sA[1][row][kc] = *(const uint4*)(Al + (size_t)(m0 + row) * K + k0 + kc);
        }
        {   // B: 256 chunks
            int row = tid >> 2, kc = (tid & 3) * 8;
            *(uint4*)&sB[0][row][kc] = *(const uint4*)(Bh + (size_t)(n0 + row) * K + k0 + kc);
            *(uint4*)&sB[1][row][kc] = *(const uint4*)(Bl + (size_t)(n0 + row) * K + k0 + kc);
        }
        __syncthreads();

#pragma unroll
        for (int s = 0; s < 2; s++) {   // two k16 steps
            uint32_t aH[2][4], aL[2][4], bF[2][4];
#pragma unroll
            for (int mt = 0; mt < 2; mt++) {
                int row = wm + mt * 16 + (lane & 15);
                int koff = s * 16 + (lane >> 4) * 8;
                uint32_t ad = aBase + (uint32_t)(row * 40 + koff) * 2;
                ldsm_x4(aH[mt], ad);
                ldsm_x4(aL[mt], ad + 128 * 40 * 2);
            }
            {   // B hi: two x4 loads cover 4 n8-tiles
                int rowp = wn + ((lane >> 4) & 1) * 8 + (lane & 7);
                int koff = s * 16 + ((lane >> 3) & 1) * 8;
#pragma unroll
                for (int p = 0; p < 2; p++) {
                    uint32_t bd = bBase + (uint32_t)((rowp + p * 16) * 40 + koff) * 2;
                    ldsm_x4(bF[p], bd);
                }
            }
#pragma unroll
            for (int mt = 0; mt < 2; mt++)
#pragma unroll
                for (int nt = 0; nt < 4; nt++) {
                    uint32_t b0 = bF[nt >> 1][(nt & 1) * 2];
                    uint32_t b1 = bF[nt >> 1][(nt & 1) * 2 + 1];
                    mma16816(acc[mt][nt], aH[mt], b0, b1);   // hi*hi
                    mma16816(acc[mt][nt], aL[mt], b0, b1);   // lo*hi
                }
            {   // B lo
                int rowp = wn + ((lane >> 4) & 1) * 8 + (lane & 7);
                int koff = s * 16 + ((lane >> 3) & 1) * 8;
#pragma unroll
                for (int p = 0; p < 2; p++) {
                    uint32_t bd = bBase + (uint32_t)((rowp + p * 16) * 40 + koff) * 2 + 64 * 40 * 2;
                    ldsm_x4(bF[p], bd);
                }
            }
#pragma unroll
            for (int mt = 0; mt < 2; mt++)
#pragma unroll
                for (int nt = 0; nt < 4; nt++) {
                    uint32_t b0 = bF[nt >> 1][(nt & 1) * 2];
                    uint32_t b1 = bF[nt >> 1][(nt & 1) * 2 + 1];
                    mma16816(acc[mt][nt], aH[mt], b0, b1);   // hi*lo
                }
        }
        __syncthreads();
    }

#pragma unroll
    for (int mt = 0; mt < 2; mt++)
#pragma unroll
        for (int nt = 0; nt < 4; nt++) {
            int r = m0 + wm + mt * 16 + (lane >> 2);
            int cc = n0 + wn + nt * 8 + (lane & 3) * 2;
            *(float2*)(C + (size_t)r * N + cc) = make_float2(acc[mt][nt][0], acc[mt][nt][1]);
            *(float2*)(C + (size_t)(r + 8) * N + cc) = make_float2(acc[mt][nt][2], acc[mt][nt][3]);
        }
}

// ---------------------------------------------------------------------------
// src: [B, S, H] -> dst: [B, nh, S, hd], optional RoPE from table.
// ---------------------------------------------------------------------------
__global__ __launch_bounds__(256) void rope_transpose(const float* __restrict__ src,
                                                      float* __restrict__ dst,
                                                      int apply_rope) {
    int idx = blockIdx.x * blockDim.x + threadIdx.x;
    if (idx >= Bsz * NH * S * 32) return;
    int d = idx & 31;
    int s = (idx >> 5) & (S - 1);
    int h = (idx >> 16) & (NH - 1);
    int b = idx >> 20;

    const float* p = src + (size_t)(b * S + s) * H + h * HD;
    float v0 = p[d];
    float v1 = p[d + 32];

    if (apply_rope) {
        float c = g_cos[s * 32 + d];
        float sn = g_sin[s * 32 + d];
        float n0 = v0 * c - v1 * sn;
        float n1 = v1 * c + v0 * sn;
        v0 = n0; v1 = n1;
    }

    float* o = dst + ((size_t)(b * NH + h) * S + s) * HD;
    o[d] = v0;
    o[d + 32] = v1;
}

// ---------------------------------------------------------------------------
// scores = (Q K^T)/8 + bias, pad-mask -> -1e30, causal blocks skipped.
// ---------------------------------------------------------------------------
__global__ __launch_bounds__(256) void scores_kernel(const float* __restrict__ Q,
                                                     const float* __restrict__ Kt,
                                                     const float* __restrict__ bias,
                                                     const int* __restrict__ mask,
                                                     float* __restrict__ attn) {
    const int bh = blockIdx.z;
    const int b = bh >> 4;
    const int m0 = blockIdx.y * 128;
    const int n0 = blockIdx.x * 128;
    if (n0 > m0 + 127) return;

    __shared__ float Qs[32][132];
    __shared__ float Ks[32][132];
    const int tid = threadIdx.x;
    const int tx = tid & 15;
    const int ty = tid >> 4;
    const float* Qb = Q + (size_t)bh * S * HD;
    const float* Kb = Kt + (size_t)bh * S * HD;

    float acc[8][8];
#pragma unroll
    for (int i = 0; i < 8; i++)
#pragma unroll
        for (int j = 0; j < 8; j++) acc[i][j] = 0.f;

    for (int kk = 0; kk < HD; kk += 32) {
#pragma unroll
        for (int i = 0; i < 4; i++) {
            int idx = tid + i * 256;
            int row = idx >> 3;
            int col = (idx & 7) << 2;
            float4 va = *(const float4*)(Qb + (size_t)(m0 + row) * HD + kk + col);
            Qs[col + 0][row] = va.x; Qs[col + 1][row] = va.y;
            Qs[col + 2][row] = va.z; Qs[col + 3][row] = va.w;
            float4 vb = *(const float4*)(Kb + (size_t)(n0 + row) * HD + kk + col);
            Ks[col + 0][row] = vb.x; Ks[col + 1][row] = vb.y;
            Ks[col + 2][row] = vb.z; Ks[col + 3][row] = vb.w;
        }
        __syncthreads();
#pragma unroll
        for (int k = 0; k < 32; k++) {
            float a[8], bb[8];
#pragma unroll
            for (int i = 0; i < 8; i++) a[i] = Qs[k][ty * 8 + i];
#pragma unroll
            for (int j = 0; j < 8; j++) bb[j] = Ks[k][tx * 8 + j];
#pragma unroll
            for (int i = 0; i < 8; i++)
#pragma unroll
                for (int j = 0; j < 8; j++)
                    acc[i][j] = fmaf(a[i], bb[j], acc[i][j]);
        }
        __syncthreads();
    }

    int mk[8];
#pragma unroll
    for (int j = 0; j < 8; j++) mk[j] = mask[b * S + n0 + tx * 8 + j];

#pragma unroll
    for (int i = 0; i < 8; i++) {
        int q = m0 + ty * 8 + i;
        float* arow = attn + ((size_t)bh * S + q) * S;
        const float* brow = bias + (size_t)q * S;
#pragma unroll
        for (int j = 0; j < 8; j++) {
            int key = n0 + tx * 8 + j;
            float val = acc[i][j] * 0.125f + brow[key];
            if (mk[j] == 0) val = -1e30f;
            arow[key] = val;
        }
    }
}

// ---------------------------------------------------------------------------
// Row-wise causal softmax in-place.
// ---------------------------------------------------------------------------
__global__ __launch_bounds__(256) void softmax_kernel(float* __restrict__ attn) {
    __shared__ float sc[S];
    __shared__ float red[8];
    const int row = blockIdx.x;
    const int q = row & (S - 1);
    const int n = q + 1;
    float* a = attn + (size_t)row * S;
    const int tid = threadIdx.x;

    float m = -3e38f;
    for (int k = tid; k < n; k += 256) {
        float v = a[k];
        sc[k] = v;
        m = fmaxf(m, v);
    }
#pragma unroll
    for (int o = 16; o; o >>= 1) m = fmaxf(m, __shfl_xor_sync(0xffffffffu, m, o));
    if ((tid & 31) == 0) red[tid >> 5] = m;
    __syncthreads();
    m = red[0];
#pragma unroll
    for (int w = 1; w < 8; w++) m = fmaxf(m, red[w]);
    __syncthreads();

    float ssum = 0.f;
    for (int k = tid; k < n; k += 256) {
        float e = __expf(sc[k] - m);
        sc[k] = e;
        ssum += e;
    }
#pragma unroll
    for (int o = 16; o; o >>= 1) ssum += __shfl_xor_sync(0xffffffffu, ssum, o);
    if ((tid & 31) == 0) red[tid >> 5] = ssum;
    __syncthreads();
    ssum = 0.f;
#pragma unroll
    for (int w = 0; w < 8; w++) ssum += red[w];

    float inv = 1.f / ssum;
    for (int k = tid; k < S; k += 256) a[k] = (k < n) ? sc[k] * inv : 0.f;
}

// ---------------------------------------------------------------------------
// ctx = attn @ V with causal k bound.
// ---------------------------------------------------------------------------
__global__ __launch_bounds__(256) void av_kernel(const float* __restrict__ attn,
                                                 const float* __restrict__ V,
                                                 float* __restrict__ ctx) {
    const int bh = blockIdx.z;
    const int b = bh >> 4;
    const int h = bh & 15;
    const int m0 = blockIdx.x * 128;

    __shared__ float As[32][132];
    __shared__ float Vs[32][68];
    const int tid = threadIdx.x;
    const int tx = tid & 15;
    const int ty = tid >> 4;
    const float* Ab = attn + (size_t)bh * S * S;
    const float* Vb = V + (size_t)bh * S * HD;

    float acc[8][4];
#pragma unroll
    for (int i = 0; i < 8; i++)
#pragma unroll
        for (int j = 0; j < 4; j++) acc[i][j] = 0.f;

    const int kmax = m0 + 128;
    for (int k0 = 0; k0 < kmax; k0 += 32) {
#pragma unroll
        for (int i = 0; i < 4; i++) {
            int idx = tid + i * 256;
            int row = idx >> 3;
            int col = (idx & 7) << 2;
            float4 va = *(const float4*)(Ab + (size_t)(m0 + row) * S + k0 + col);
            As[col + 0][row] = va.x; As[col + 1][row] = va.y;
            As[col + 2][row] = va.z; As[col + 3][row] = va.w;
        }
#pragma unroll
        for (int i = 0; i < 2; i++) {
            int idx = tid + i * 256;
            int row = idx >> 4;
            int col = (idx & 15) << 2;
            *(float4*)(&Vs[row][col]) =
                *(const float4*)(Vb + (size_t)(k0 + row) * HD + col);
        }
        __syncthreads();
#pragma unroll
        for (int k = 0; k < 32; k++) {
            float a[8], vv[4];
#pragma unroll
            for (int i = 0; i < 8; i++) a[i] = As[k][ty * 8 + i];
#pragma unroll
            for (int j = 0; j < 4; j++) vv[j] = Vs[k][tx * 4 + j];
#pragma unroll
            for (int i = 0; i < 8; i++)
#pragma unroll
                for (int j = 0; j < 4; j++)
                    acc[i][j] = fmaf(a[i], vv[j], acc[i][j]);
        }
        __syncthreads();
    }

#pragma unroll
    for (int i = 0; i < 8; i++) {
        int s = m0 + ty * 8 + i;
        float4 v = make_float4(acc[i][0], acc[i][1], acc[i][2], acc[i][3]);
        *(float4*)(ctx + ((size_t)(b * S + s) * NH + h) * HD + tx * 4) = v;
    }
}

// ---------------------------------------------------------------------------
extern "C" void kernel_launch(void* const* d_in, const int* in_sizes, int n_in,
                              void* d_out, int out_size) {
    const float* x    = (const float*)d_in[0];
    const int*   mask = (const int*)d_in[1];
    const float* Wq   = (const float*)d_in[2];
    const float* Wk   = (const float*)d_in[3];
    const float* Wv   = (const float*)d_in[4];
    const float* Wo   = (const float*)d_in[5];
    const float* bias = (const float*)d_in[6];

    float* out  = (float*)d_out;
    float* attn = out + (size_t)Bsz * S * H;

    float *tmp, *q, *k, *v, *ctx;
    cudaGetSymbolAddress((void**)&tmp, g_tmp);
    cudaGetSymbolAddress((void**)&q,   g_q);
    cudaGetSymbolAddress((void**)&k,   g_k);
    cudaGetSymbolAddress((void**)&v,   g_v);
    cudaGetSymbolAddress((void**)&ctx, g_ctx);
    __nv_bfloat16 *xh, *xl, *ch, *cl, *wh, *wl;
    cudaGetSymbolAddress((void**)&xh, g_xh);
    cudaGetSymbolAddress((void**)&xl, g_xl);
    cudaGetSymbolAddress((void**)&ch, g_ch);
    cudaGetSymbolAddress((void**)&cl, g_cl);
    cudaGetSymbolAddress((void**)&wh, g_wh);
    cudaGetSymbolAddress((void**)&wl, g_wl);

    const int M = Bsz * S;                        // 4096
    const int MH = M * H;                         // 4,194,304
    const int HH = H * H;                         // 1,048,576
    dim3 gproj(H / 64, M / 128);                  // (16, 32)
    const int rope_threads = Bsz * NH * S * 32;

    rope_table_kernel<<<(S * 32) / 256, 256>>>();
    split_kernel<<<MH / 4 / 256, 256>>>(x, xh, xl, MH);
    split_kernel<<<HH / 4 / 256, 256>>>(Wq, wh + 0 * HH, wl + 0 * HH, HH);
    split_kernel<<<HH / 4 / 256, 256>>>(Wk, wh + 1 * HH, wl + 1 * HH, HH);
    split_kernel<<<HH / 4 / 256, 256>>>(Wv, wh + 2 * HH, wl + 2 * HH, HH);
    split_kernel<<<HH / 4 / 256, 256>>>(Wo, wh + 3 * HH, wl + 3 * HH, HH);

    gemm_nt_split<<<gproj, 256>>>(xh, xl, wh + 0 * HH, wl + 0 * HH, tmp, M, H, H);
    rope_transpose<<<rope_threads / 256, 256>>>(tmp, q, 1);

    gemm_nt_split<<<gproj, 256>>>(xh, xl, wh + 1 * HH, wl + 1 * HH, tmp, M, H, H);
    rope_transpose<<<rope_threads / 256, 256>>>(tmp, k, 1);

    gemm_nt_split<<<gproj, 256>>>(xh, xl, wh + 2 * HH, wl + 2 * HH, tmp, M, H, H);
    rope_transpose<<<rope_threads / 256, 256>>>(tmp, v, 0);

    scores_kernel<<<dim3(S / 128, S / 128, Bsz * NH), 256>>>(q, k, bias, mask, attn);
    softmax_kernel<<<Bsz * NH * S, 256>>>(attn);
    av_kernel<<<dim3(S / 128, 1, Bsz * NH), 256>>>(attn, v, ctx);

    split_kernel<<<MH / 4 / 256, 256>>>(ctx, ch, cl, MH);
    gemm_nt_split<<<gproj, 256>>>(ch, cl, wh + 3 * HH, wl + 3 * HH, out, M, H, H);
}

// round 4
// speedup vs baseline: 2.4467x; 1.3182x over previous
#include <cuda_runtime.h>
#include <cuda_bf16.h>
#include <math.h>
#include <stdint.h>

#define Bsz 2
#define S 2048
#define H 1024
#define NH 16
#define HD 64

// Scratch (allocation-free rule: __device__ globals)
__device__ float g_tmp[Bsz * S * H];
__device__ float g_ctx[Bsz * S * H];
__device__ float g_cos[S * 32];
__device__ float g_sin[S * 32];
// split-bf16 buffers
__device__ __nv_bfloat16 g_xh[Bsz * S * H];
__device__ __nv_bfloat16 g_xl[Bsz * S * H];
__device__ __nv_bfloat16 g_ch[Bsz * S * H];
__device__ __nv_bfloat16 g_cl[Bsz * S * H];
__device__ __nv_bfloat16 g_wh[4 * H * H];
__device__ __nv_bfloat16 g_wl[4 * H * H];
__device__ __nv_bfloat16 g_qh[Bsz * S * H];
__device__ __nv_bfloat16 g_ql[Bsz * S * H];
__device__ __nv_bfloat16 g_kh[Bsz * S * H];
__device__ __nv_bfloat16 g_kl[Bsz * S * H];
__device__ __nv_bfloat16 g_vh[Bsz * S * H];
__device__ __nv_bfloat16 g_vl[Bsz * S * H];
// attn probabilities in split-bf16 (256 MB each)
__device__ __nv_bfloat16 g_ah[(size_t)Bsz * NH * S * S];
__device__ __nv_bfloat16 g_al[(size_t)Bsz * NH * S * S];

// ---------------------------------------------------------------------------
__global__ __launch_bounds__(256) void rope_table_kernel() {
    int idx = blockIdx.x * blockDim.x + threadIdx.x;
    if (idx >= S * 32) return;
    int d = idx & 31;
    int s = idx >> 5;
    double inv = pow(10000.0, -(double)(2 * d) / 64.0);
    double ang = (double)s * inv;
    double sd, cd;
    sincos(ang, &sd, &cd);
    g_cos[idx] = (float)cd;
    g_sin[idx] = (float)sd;
}

// ---------------------------------------------------------------------------
__global__ __launch_bounds__(256) void split_kernel(const float* __restrict__ src,
                                                    __nv_bfloat16* __restrict__ hi,
                                                    __nv_bfloat16* __restrict__ lo,
                                                    int n) {
    int i = (blockIdx.x * 256 + threadIdx.x) * 4;
    if (i >= n) return;
    float4 v = *(const float4*)(src + i);
    __nv_bfloat16 h0 = __float2bfloat16(v.x);
    __nv_bfloat16 h1 = __float2bfloat16(v.y);
    __nv_bfloat16 h2 = __float2bfloat16(v.z);
    __nv_bfloat16 h3 = __float2bfloat16(v.w);
    __nv_bfloat16 l0 = __float2bfloat16(v.x - __bfloat162float(h0));
    __nv_bfloat16 l1 = __float2bfloat16(v.y - __bfloat162float(h1));
    __nv_bfloat16 l2 = __float2bfloat16(v.z - __bfloat162float(h2));
    __nv_bfloat16 l3 = __float2bfloat16(v.w - __bfloat162float(h3));
    *(__nv_bfloat162*)(hi + i)     = __halves2bfloat162(h0, h1);
    *(__nv_bfloat162*)(hi + i + 2) = __halves2bfloat162(h2, h3);
    *(__nv_bfloat162*)(lo + i)     = __halves2bfloat162(l0, l1);
    *(__nv_bfloat162*)(lo + i + 2) = __halves2bfloat162(l2, l3);
}

// ---------------------------------------------------------------------------
// MMA helpers
// ---------------------------------------------------------------------------
__device__ __forceinline__ void ldsm_x4(uint32_t (&r)[4], uint32_t addr) {
    asm volatile("ldmatrix.sync.aligned.m8n8.x4.shared.b16 {%0,%1,%2,%3}, [%4];"
                 : "=r"(r[0]), "=r"(r[1]), "=r"(r[2]), "=r"(r[3]) : "r"(addr));
}
__device__ __forceinline__ void ldsm_x4_t(uint32_t (&r)[4], uint32_t addr) {
    asm volatile("ldmatrix.sync.aligned.m8n8.x4.trans.shared.b16 {%0,%1,%2,%3}, [%4];"
                 : "=r"(r[0]), "=r"(r[1]), "=r"(r[2]), "=r"(r[3]) : "r"(addr));
}
__device__ __forceinline__ void mma16816(float (&c)[4], const uint32_t (&a)[4],
                                         uint32_t b0, uint32_t b1) {
    asm volatile(
        "mma.sync.aligned.m16n8k16.row.col.f32.bf16.bf16.f32 "
        "{%0,%1,%2,%3}, {%4,%5,%6,%7}, {%8,%9}, {%0,%1,%2,%3};"
        : "+f"(c[0]), "+f"(c[1]), "+f"(c[2]), "+f"(c[3])
        : "r"(a[0]), "r"(a[1]), "r"(a[2]), "r"(a[3]), "r"(b0), "r"(b1));
}

// ---------------------------------------------------------------------------
// Split-bf16 GEMM (projections): C[M,N] = A[M,K] @ B[N,K]^T.
// ---------------------------------------------------------------------------
__global__ __launch_bounds__(256) void gemm_nt_split(
    const __nv_bfloat16* __restrict__ Ah, const __nv_bfloat16* __restrict__ Al,
    const __nv_bfloat16* __restrict__ Bh, const __nv_bfloat16* __restrict__ Bl,
    float* __restrict__ C, int M, int N, int K) {
    __shared__ __align__(16) __nv_bfloat16 sA[2][128][40];
    __shared__ __align__(16) __nv_bfloat16 sB[2][64][40];

    const int tid = threadIdx.x;
    const int wid = tid >> 5, lane = tid & 31;
    const int wm = (wid & 3) * 32;
    const int wn = (wid >> 2) * 32;
    const int m0 = blockIdx.y * 128, n0 = blockIdx.x * 64;

    float acc[2][4][4] = {};

    const uint32_t aBase = (uint32_t)__cvta_generic_to_shared(&sA[0][0][0]);
    const uint32_t bBase = (uint32_t)__cvta_generic_to_shared(&sB[0][0][0]);

    for (int k0 = 0; k0 < K; k0 += 32) {
#pragma unroll
        for (int i = 0; i < 2; i++) {
            int c = tid + i * 256;
            int row = c >> 2, kc = (c & 3) * 8;
            *(uint4*)&sA[0][row][kc] = *(const uint4*)(Ah + (size_t)(m0 + row) * K + k0 + kc);
            *(uint4*)&sA[1][row][kc] = *(const uint4*)(Al + (size_t)(m0 + row) * K + k0 + kc);
        }
        {
            int row = tid >> 2, kc = (tid & 3) * 8;
            *(uint4*)&sB[0][row][kc] = *(const uint4*)(Bh + (size_t)(n0 + row) * K + k0 + kc);
            *(uint4*)&sB[1][row][kc] = *(const uint4*)(Bl + (size_t)(n0 + row) * K + k0 + kc);
        }
        __syncthreads();

#pragma unroll
        for (int s = 0; s < 2; s++) {
            uint32_t aH[2][4], aL[2][4], bF[2][4];
#pragma unroll
            for (int mt = 0; mt < 2; mt++) {
                int row = wm + mt * 16 + (lane & 15);
                int koff = s * 16 + (lane >> 4) * 8;
                uint32_t ad = aBase + (uint32_t)(row * 40 + koff) * 2;
                ldsm_x4(aH[mt], ad);
                ldsm_x4(aL[mt], ad + 128 * 40 * 2);
            }
            {
                int rowp = wn + ((lane >> 4) & 1) * 8 + (lane & 7);
                int koff = s * 16 + ((lane >> 3) & 1) * 8;
#pragma unroll
                for (int p = 0; p < 2; p++) {
                    uint32_t bd = bBase + (uint32_t)((rowp + p * 16) * 40 + koff) * 2;
                    ldsm_x4(bF[p], bd);
                }
            }
#pragma unroll
            for (int mt = 0; mt < 2; mt++)
#pragma unroll
                for (int nt = 0; nt < 4; nt++) {
                    uint32_t b0 = bF[nt >> 1][(nt & 1) * 2];
                    uint32_t b1 = bF[nt >> 1][(nt & 1) * 2 + 1];
                    mma16816(acc[mt][nt], aH[mt], b0, b1);
                    mma16816(acc[mt][nt], aL[mt], b0, b1);
                }
            {
                int rowp = wn + ((lane >> 4) & 1) * 8 + (lane & 7);
                int koff = s * 16 + ((lane >> 3) & 1) * 8;
#pragma unroll
                for (int p = 0; p < 2; p++) {
                    uint32_t bd = bBase + (uint32_t)((rowp + p * 16) * 40 + koff) * 2 + 64 * 40 * 2;
                    ldsm_x4(bF[p], bd);
                }
            }
#pragma unroll
            for (int mt = 0; mt < 2; mt++)
#pragma unroll
                for (int nt = 0; nt < 4; nt++) {
                    uint32_t b0 = bF[nt >> 1][(nt & 1) * 2];
                    uint32_t b1 = bF[nt >> 1][(nt & 1) * 2 + 1];
                    mma16816(acc[mt][nt], aH[mt], b0, b1);
                }
        }
        __syncthreads();
    }

#pragma unroll
    for (int mt = 0; mt < 2; mt++)
#pragma unroll
        for (int nt = 0; nt < 4; nt++) {
            int r = m0 + wm + mt * 16 + (lane >> 2);
            int cc = n0 + wn + nt * 8 + (lane & 3) * 2;
            *(float2*)(C + (size_t)r * N + cc) = make_float2(acc[mt][nt][0], acc[mt][nt][1]);
            *(float2*)(C + (size_t)(r + 8) * N + cc) = make_float2(acc[mt][nt][2], acc[mt][nt][3]);
        }
}

// ---------------------------------------------------------------------------
// src: [B,S,H] fp32 -> hi/lo bf16 [B,nh,S,hd], optional RoPE.
// ---------------------------------------------------------------------------
__global__ __launch_bounds__(256) void rope_split(const float* __restrict__ src,
                                                  __nv_bfloat16* __restrict__ dh,
                                                  __nv_bfloat16* __restrict__ dl,
                                                  int apply_rope) {
    int idx = blockIdx.x * blockDim.x + threadIdx.x;
    if (idx >= Bsz * NH * S * 32) return;
    int d = idx & 31;
    int s = (idx >> 5) & (S - 1);
    int h = (idx >> 16) & (NH - 1);
    int b = idx >> 20;

    const float* p = src + (size_t)(b * S + s) * H + h * HD;
    float v0 = p[d];
    float v1 = p[d + 32];

    if (apply_rope) {
        float c = g_cos[s * 32 + d];
        float sn = g_sin[s * 32 + d];
        float n0 = v0 * c - v1 * sn;
        float n1 = v1 * c + v0 * sn;
        v0 = n0; v1 = n1;
    }

    size_t o = ((size_t)(b * NH + h) * S + s) * HD;
    __nv_bfloat16 h0 = __float2bfloat16(v0);
    __nv_bfloat16 h1 = __float2bfloat16(v1);
    dh[o + d] = h0;
    dh[o + d + 32] = h1;
    dl[o + d] = __float2bfloat16(v0 - __bfloat162float(h0));
    dl[o + d + 32] = __float2bfloat16(v1 - __bfloat162float(h1));
}

// ---------------------------------------------------------------------------
// Tensor-core scores: attn_raw = (Q K^T)/8 + bias, pad-mask -> -1e30.
// 128x128 tile, 8 warps (4x2), warp tile 32x64, K=64 in two k32 chunks.
// ---------------------------------------------------------------------------
__global__ __launch_bounds__(256) void scores_mma(
    const __nv_bfloat16* __restrict__ Qh, const __nv_bfloat16* __restrict__ Ql,
    const __nv_bfloat16* __restrict__ Kh, const __nv_bfloat16* __restrict__ Kl,
    const float* __restrict__ bias, const int* __restrict__ mask,
    float* __restrict__ attn) {
    const int bh = blockIdx.z;
    const int b = bh >> 4;
    const int m0 = blockIdx.y * 128;
    const int n0 = blockIdx.x * 128;
    if (n0 > m0 + 127) return;

    __shared__ __align__(16) __nv_bfloat16 sQ[2][128][40];
    __shared__ __align__(16) __nv_bfloat16 sK[2][128][40];

    const int tid = threadIdx.x;
    const int wid = tid >> 5, lane = tid & 31;
    const int wm = (wid & 3) * 32;
    const int wn = (wid >> 2) * 64;
    const __nv_bfloat16* Qhb = Qh + (size_t)bh * S * HD;
    const __nv_bfloat16* Qlb = Ql + (size_t)bh * S * HD;
    const __nv_bfloat16* Khb = Kh + (size_t)bh * S * HD;
    const __nv_bfloat16* Klb = Kl + (size_t)bh * S * HD;

    float acc[2][8][4] = {};
    const uint32_t qBase = (uint32_t)__cvta_generic_to_shared(&sQ[0][0][0]);
    const uint32_t kBase = (uint32_t)__cvta_generic_to_shared(&sK[0][0][0]);

    for (int kk = 0; kk < HD; kk += 32) {
#pragma unroll
        for (int i = 0; i < 2; i++) {
            int c = tid + i * 256;
            int row = c >> 2, kc = (c & 3) * 8;
            *(uint4*)&sQ[0][row][kc] = *(const uint4*)(Qhb + (size_t)(m0 + row) * HD + kk + kc);
            *(uint4*)&sQ[1][row][kc] = *(const uint4*)(Qlb + (size_t)(m0 + row) * HD + kk + kc);
            *(uint4*)&sK[0][row][kc] = *(const uint4*)(Khb + (size_t)(n0 + row) * HD + kk + kc);
            *(uint4*)&sK[1][row][kc] = *(const uint4*)(Klb + (size_t)(n0 + row) * HD + kk + kc);
        }
        __syncthreads();

#pragma unroll
        for (int s = 0; s < 2; s++) {
            uint32_t aH[2][4], aL[2][4], bF[4][4];
#pragma unroll
            for (int mt = 0; mt < 2; mt++) {
                int row = wm + mt * 16 + (lane & 15);
                int koff = s * 16 + (lane >> 4) * 8;
                uint32_t ad = qBase + (uint32_t)(row * 40 + koff) * 2;
                ldsm_x4(aH[mt], ad);
                ldsm_x4(aL[mt], ad + 128 * 40 * 2);
            }
            {
                int rowp = wn + ((lane >> 4) & 1) * 8 + (lane & 7);
                int koff = s * 16 + ((lane >> 3) & 1) * 8;
#pragma unroll
                for (int p = 0; p < 4; p++) {
                    uint32_t bd = kBase + (uint32_t)((rowp + p * 16) * 40 + koff) * 2;
                    ldsm_x4(bF[p], bd);
                }
            }
#pragma unroll
            for (int mt = 0; mt < 2; mt++)
#pragma unroll
                for (int nt = 0; nt < 8; nt++) {
                    uint32_t b0 = bF[nt >> 1][(nt & 1) * 2];
                    uint32_t b1 = bF[nt >> 1][(nt & 1) * 2 + 1];
                    mma16816(acc[mt][nt], aH[mt], b0, b1);   // hi*hi
                    mma16816(acc[mt][nt], aL[mt], b0, b1);   // lo*hi
                }
            {
                int rowp = wn + ((lane >> 4) & 1) * 8 + (lane & 7);
                int koff = s * 16 + ((lane >> 3) & 1) * 8;
#pragma unroll
                for (int p = 0; p < 4; p++) {
                    uint32_t bd = kBase + (uint32_t)((rowp + p * 16) * 40 + koff) * 2 + 128 * 40 * 2;
                    ldsm_x4(bF[p], bd);
                }
            }
#pragma unroll
            for (int mt = 0; mt < 2; mt++)
#pragma unroll
                for (int nt = 0; nt < 8; nt++) {
                    uint32_t b0 = bF[nt >> 1][(nt & 1) * 2];
                    uint32_t b1 = bF[nt >> 1][(nt & 1) * 2 + 1];
                    mma16816(acc[mt][nt], aH[mt], b0, b1);   // hi*lo
                }
        }
        __syncthreads();
    }

#pragma unroll
    for (int mt = 0; mt < 2; mt++)
#pragma unroll
        for (int nt = 0; nt < 8; nt++) {
            int c = n0 + wn + nt * 8 + (lane & 3) * 2;
            int mk0 = mask[b * S + c];
            int mk1 = mask[b * S + c + 1];
#pragma unroll
            for (int half = 0; half < 2; half++) {
                int r = m0 + wm + mt * 16 + (lane >> 2) + half * 8;
                const float* brow = bias + (size_t)r * S;
                float v0 = acc[mt][nt][half * 2 + 0] * 0.125f + brow[c];
                float v1 = acc[mt][nt][half * 2 + 1] * 0.125f + brow[c + 1];
                if (mk0 == 0) v0 = -1e30f;
                if (mk1 == 0) v1 = -1e30f;
                *(float2*)(attn + ((size_t)bh * S + r) * S + c) = make_float2(v0, v1);
            }
        }
}

// ---------------------------------------------------------------------------
// Row-wise causal softmax; writes normalized fp32 (full row, zeros beyond q)
// and split-bf16 attn up to the 128-aligned causal boundary for av_mma.
// ---------------------------------------------------------------------------
__global__ __launch_bounds__(256) void softmax_kernel(float* __restrict__ attn,
                                                      __nv_bfloat16* __restrict__ ah,
                                                      __nv_bfloat16* __restrict__ al) {
    __shared__ float sc[S];
    __shared__ float red[8];
    const int row = blockIdx.x;
    const int q = row & (S - 1);
    const int n = q + 1;
    const int ke = (q + 128) & ~127;   // round_up(q+1, 128)
    float* a = attn + (size_t)row * S;
    __nv_bfloat16* hh = ah + (size_t)row * S;
    __nv_bfloat16* ll = al + (size_t)row * S;
    const int tid = threadIdx.x;

    float m = -3e38f;
    for (int k = tid; k < n; k += 256) {
        float v = a[k];
        sc[k] = v;
        m = fmaxf(m, v);
    }
#pragma unroll
    for (int o = 16; o; o >>= 1) m = fmaxf(m, __shfl_xor_sync(0xffffffffu, m, o));
    if ((tid & 31) == 0) red[tid >> 5] = m;
    __syncthreads();
    m = red[0];
#pragma unroll
    for (int w = 1; w < 8; w++) m = fmaxf(m, red[w]);
    __syncthreads();

    float ssum = 0.f;
    for (int k = tid; k < n; k += 256) {
        float e = __expf(sc[k] - m);
        sc[k] = e;
        ssum += e;
    }
#pragma unroll
    for (int o = 16; o; o >>= 1) ssum += __shfl_xor_sync(0xffffffffu, ssum, o);
    if ((tid & 31) == 0) red[tid >> 5] = ssum;
    __syncthreads();
    ssum = 0.f;
#pragma unroll
    for (int w = 0; w < 8; w++) ssum += red[w];

    float inv = 1.f / ssum;
    for (int k = tid; k < S; k += 256) {
        float val = (k < n) ? sc[k] * inv : 0.f;
        a[k] = val;
        if (k < ke) {
            __nv_bfloat16 h = __float2bfloat16(val);
            hh[k] = h;
            ll[k] = __float2bfloat16(val - __bfloat162float(h));
        }
    }
}

// ---------------------------------------------------------------------------
// Tensor-core AV: ctx[b,s,h,:] = attn[bh,s,:] @ V[bh,:,:], causal k bound.
// 128x64 output, 8 warps (4x2), warp tile 32x32.
// ---------------------------------------------------------------------------
__global__ __launch_bounds__(256) void av_mma(
    const __nv_bfloat16* __restrict__ Ah, const __nv_bfloat16* __restrict__ Al,
    const __nv_bfloat16* __restrict__ Vh, const __nv_bfloat16* __restrict__ Vl,
    float* __restrict__ ctx) {
    const int bh = blockIdx.z;
    const int b = bh >> 4;
    const int h = bh & 15;
    const int m0 = blockIdx.x * 128;

    __shared__ __align__(16) __nv_bfloat16 sA[2][128][40];   // attn q x k32
    __shared__ __align__(16) __nv_bfloat16 sV[2][32][72];    // k32 x 64dim

    const int tid = threadIdx.x;
    const int wid = tid >> 5, lane = tid & 31;
    const int wm = (wid & 3) * 32;
    const int wn = (wid >> 2) * 32;
    const __nv_bfloat16* Ahb = Ah + (size_t)bh * S * S;
    const __nv_bfloat16* Alb = Al + (size_t)bh * S * S;
    const __nv_bfloat16* Vhb = Vh + (size_t)bh * S * HD;
    const __nv_bfloat16* Vlb = Vl + (size_t)bh * S * HD;

    float acc[2][4][4] = {};
    const uint32_t aBase = (uint32_t)__cvta_generic_to_shared(&sA[0][0][0]);
    const uint32_t vBase = (uint32_t)__cvta_generic_to_shared(&sV[0][0][0]);

    const int kmax = m0 + 128;
    for (int k0 = 0; k0 < kmax; k0 += 32) {
#pragma unroll
        for (int i = 0; i < 2; i++) {
            int c = tid + i * 256;
            int row = c >> 2, kc = (c & 3) * 8;
            *(uint4*)&sA[0][row][kc] = *(const uint4*)(Ahb + ((size_t)(m0 + row)) * S + k0 + kc);
            *(uint4*)&sA[1][row][kc] = *(const uint4*)(Alb + ((size_t)(m0 + row)) * S + k0 + kc);
        }
        {
            int row = tid >> 3, col = (tid & 7) * 8;
            *(uint4*)&sV[0][row][col] = *(const uint4*)(Vhb + (size_t)(k0 + row) * HD + col);
            *(uint4*)&sV[1][row][col] = *(const uint4*)(Vlb + (size_t)(k0 + row) * HD + col);
        }
        __syncthreads();

#pragma unroll
        for (int s = 0; s < 2; s++) {
            uint32_t aH[2][4], aL[2][4], bF[2][4];
#pragma unroll
            for (int mt = 0; mt < 2; mt++) {
                int row = wm + mt * 16 + (lane & 15);
                int koff = s * 16 + (lane >> 4) * 8;
                uint32_t ad = aBase + (uint32_t)(row * 40 + koff) * 2;
                ldsm_x4(aH[mt], ad);
                ldsm_x4(aL[mt], ad + 128 * 40 * 2);
            }
            {
                int krow = s * 16 + (lane & 7) + ((lane >> 3) & 1) * 8;
                int col = wn + (lane >> 4) * 8;
#pragma unroll
                for (int p = 0; p < 2; p++) {
                    uint32_t bd = vBase + (uint32_t)(krow * 72 + col + p * 16) * 2;
                    ldsm_x4_t(bF[p], bd);
                }
            }
#pragma unroll
            for (int mt = 0; mt < 2; mt++)
#pragma unroll
                for (int nt = 0; nt < 4; nt++) {
                    uint32_t b0 = bF[nt >> 1][(nt & 1) * 2];
                    uint32_t b1 = bF[nt >> 1][(nt & 1) * 2 + 1];
                    mma16816(acc[mt][nt], aH[mt], b0, b1);   // hi*hi
                    mma16816(acc[mt][nt], aL[mt], b0, b1);   // lo*hi
                }
            {
                int krow = s * 16 + (lane & 7) + ((lane >> 3) & 1) * 8;
                int col = wn + (lane >> 4) * 8;
#pragma unroll
                for (int p = 0; p < 2; p++) {
                    uint32_t bd = vBase + (uint32_t)(krow * 72 + col + p * 16) * 2 + 32 * 72 * 2;
                    ldsm_x4_t(bF[p], bd);
                }
            }
#pragma unroll
            for (int mt = 0; mt < 2; mt++)
#pragma unroll
                for (int nt = 0; nt < 4; nt++) {
                    uint32_t b0 = bF[nt >> 1][(nt & 1) * 2];
                    uint32_t b1 = bF[nt >> 1][(nt & 1) * 2 + 1];
                    mma16816(acc[mt][nt], aH[mt], b0, b1);   // hi*lo
                }
        }
        __syncthreads();
    }

#pragma unroll
    for (int mt = 0; mt < 2; mt++)
#pragma unroll
        for (int nt = 0; nt < 4; nt++) {
            int c = wn + nt * 8 + (lane & 3) * 2;
#pragma unroll
            for (int half = 0; half < 2; half++) {
                int r = m0 + wm + mt * 16 + (lane >> 2) + half * 8;
                *(float2*)(ctx + ((size_t)(b * S + r) * NH + h) * HD + c) =
                    make_float2(acc[mt][nt][half * 2 + 0], acc[mt][nt][half * 2 + 1]);
            }
        }
}

// ---------------------------------------------------------------------------
extern "C" void kernel_launch(void* const* d_in, const int* in_sizes, int n_in,
                              void* d_out, int out_size) {
    const float* x    = (const float*)d_in[0];
    const int*   mask = (const int*)d_in[1];
    const float* Wq   = (const float*)d_in[2];
    const float* Wk   = (const float*)d_in[3];
    const float* Wv   = (const float*)d_in[4];
    const float* Wo   = (const float*)d_in[5];
    const float* bias = (const float*)d_in[6];

    float* out  = (float*)d_out;
    float* attn = out + (size_t)Bsz * S * H;

    float *tmp, *ctx;
    cudaGetSymbolAddress((void**)&tmp, g_tmp);
    cudaGetSymbolAddress((void**)&ctx, g_ctx);
    __nv_bfloat16 *xh, *xl, *ch, *cl, *wh, *wl;
    __nv_bfloat16 *qh, *ql, *kh, *kl, *vh, *vl, *ah, *al;
    cudaGetSymbolAddress((void**)&xh, g_xh);
    cudaGetSymbolAddress((void**)&xl, g_xl);
    cudaGetSymbolAddress((void**)&ch, g_ch);
    cudaGetSymbolAddress((void**)&cl, g_cl);
    cudaGetSymbolAddress((void**)&wh, g_wh);
    cudaGetSymbolAddress((void**)&wl, g_wl);
    cudaGetSymbolAddress((void**)&qh, g_qh);
    cudaGetSymbolAddress((void**)&ql, g_ql);
    cudaGetSymbolAddress((void**)&kh, g_kh);
    cudaGetSymbolAddress((void**)&kl, g_kl);
    cudaGetSymbolAddress((void**)&vh, g_vh);
    cudaGetSymbolAddress((void**)&vl, g_vl);
    cudaGetSymbolAddress((void**)&ah, g_ah);
    cudaGetSymbolAddress((void**)&al, g_al);

    const int M = Bsz * S;                        // 4096
    const int MH = M * H;
    const int HH = H * H;
    dim3 gproj(H / 64, M / 128);                  // (16, 32)
    const int rope_threads = Bsz * NH * S * 32;

    rope_table_kernel<<<(S * 32) / 256, 256>>>();
    split_kernel<<<MH / 4 / 256, 256>>>(x, xh, xl, MH);
    split_kernel<<<HH / 4 / 256, 256>>>(Wq, wh + 0 * HH, wl + 0 * HH, HH);
    split_kernel<<<HH / 4 / 256, 256>>>(Wk, wh + 1 * HH, wl + 1 * HH, HH);
    split_kernel<<<HH / 4 / 256, 256>>>(Wv, wh + 2 * HH, wl + 2 * HH, HH);
    split_kernel<<<HH / 4 / 256, 256>>>(Wo, wh + 3 * HH, wl + 3 * HH, HH);

    gemm_nt_split<<<gproj, 256>>>(xh, xl, wh + 0 * HH, wl + 0 * HH, tmp, M, H, H);
    rope_split<<<rope_threads / 256, 256>>>(tmp, qh, ql, 1);

    gemm_nt_split<<<gproj, 256>>>(xh, xl, wh + 1 * HH, wl + 1 * HH, tmp, M, H, H);
    rope_split<<<rope_threads / 256, 256>>>(tmp, kh, kl, 1);

    gemm_nt_split<<<gproj, 256>>>(xh, xl, wh + 2 * HH, wl + 2 * HH, tmp, M, H, H);
    rope_split<<<rope_threads / 256, 256>>>(tmp, vh, vl, 0);

    scores_mma<<<dim3(S / 128, S / 128, Bsz * NH), 256>>>(qh, ql, kh, kl, bias, mask, attn);
    softmax_kernel<<<Bsz * NH * S, 256>>>(attn, ah, al);
    av_mma<<<dim3(S / 128, 1, Bsz * NH), 256>>>(ah, al, vh, vl, ctx);

    split_kernel<<<MH / 4 / 256, 256>>>(ctx, ch, cl, MH);
    gemm_nt_split<<<gproj, 256>>>(ch, cl, wh + 3 * HH, wl + 3 * HH, out, M, H, H);
}

// round 5
// speedup vs baseline: 2.4902x; 1.0178x over previous
#include <cuda_runtime.h>
#include <cuda_bf16.h>
#include <math.h>
#include <stdint.h>

#define Bsz 2
#define S 2048
#define H 1024
#define NH 16
#define HD 64

// Scratch (allocation-free rule: __device__ globals)
__device__ float g_tmp[Bsz * S * H];
__device__ float g_ctx[Bsz * S * H];
__device__ float g_cos[S * 32];
__device__ float g_sin[S * 32];
// split-bf16 buffers
__device__ __nv_bfloat16 g_xh[Bsz * S * H];
__device__ __nv_bfloat16 g_xl[Bsz * S * H];
__device__ __nv_bfloat16 g_ch[Bsz * S * H];
__device__ __nv_bfloat16 g_cl[Bsz * S * H];
__device__ __nv_bfloat16 g_wh[4 * H * H];
__device__ __nv_bfloat16 g_wl[4 * H * H];
__device__ __nv_bfloat16 g_qh[Bsz * S * H];
__device__ __nv_bfloat16 g_ql[Bsz * S * H];
__device__ __nv_bfloat16 g_kh[Bsz * S * H];
__device__ __nv_bfloat16 g_kl[Bsz * S * H];
__device__ __nv_bfloat16 g_vh[Bsz * S * H];
__device__ __nv_bfloat16 g_vl[Bsz * S * H];

// ---------------------------------------------------------------------------
__global__ __launch_bounds__(256) void rope_table_kernel() {
    int idx = blockIdx.x * blockDim.x + threadIdx.x;
    if (idx >= S * 32) return;
    int d = idx & 31;
    int s = idx >> 5;
    double inv = pow(10000.0, -(double)(2 * d) / 64.0);
    double ang = (double)s * inv;
    double sd, cd;
    sincos(ang, &sd, &cd);
    g_cos[idx] = (float)cd;
    g_sin[idx] = (float)sd;
}

// ---------------------------------------------------------------------------
__global__ __launch_bounds__(256) void split_kernel(const float* __restrict__ src,
                                                    __nv_bfloat16* __restrict__ hi,
                                                    __nv_bfloat16* __restrict__ lo,
                                                    int n) {
    int i = (blockIdx.x * 256 + threadIdx.x) * 4;
    if (i >= n) return;
    float4 v = *(const float4*)(src + i);
    __nv_bfloat16 h0 = __float2bfloat16(v.x);
    __nv_bfloat16 h1 = __float2bfloat16(v.y);
    __nv_bfloat16 h2 = __float2bfloat16(v.z);
    __nv_bfloat16 h3 = __float2bfloat16(v.w);
    __nv_bfloat16 l0 = __float2bfloat16(v.x - __bfloat162float(h0));
    __nv_bfloat16 l1 = __float2bfloat16(v.y - __bfloat162float(h1));
    __nv_bfloat16 l2 = __float2bfloat16(v.z - __bfloat162float(h2));
    __nv_bfloat16 l3 = __float2bfloat16(v.w - __bfloat162float(h3));
    *(__nv_bfloat162*)(hi + i)     = __halves2bfloat162(h0, h1);
    *(__nv_bfloat162*)(hi + i + 2) = __halves2bfloat162(h2, h3);
    *(__nv_bfloat162*)(lo + i)     = __halves2bfloat162(l0, l1);
    *(__nv_bfloat162*)(lo + i + 2) = __halves2bfloat162(l2, l3);
}

// ---------------------------------------------------------------------------
// MMA / async-copy helpers
// ---------------------------------------------------------------------------
__device__ __forceinline__ void ldsm_x4(uint32_t (&r)[4], uint32_t addr) {
    asm volatile("ldmatrix.sync.aligned.m8n8.x4.shared.b16 {%0,%1,%2,%3}, [%4];"
                 : "=r"(r[0]), "=r"(r[1]), "=r"(r[2]), "=r"(r[3]) : "r"(addr));
}
__device__ __forceinline__ void ldsm_x4_t(uint32_t (&r)[4], uint32_t addr) {
    asm volatile("ldmatrix.sync.aligned.m8n8.x4.trans.shared.b16 {%0,%1,%2,%3}, [%4];"
                 : "=r"(r[0]), "=r"(r[1]), "=r"(r[2]), "=r"(r[3]) : "r"(addr));
}
__device__ __forceinline__ void mma16816(float (&c)[4], const uint32_t (&a)[4],
                                         uint32_t b0, uint32_t b1) {
    asm volatile(
        "mma.sync.aligned.m16n8k16.row.col.f32.bf16.bf16.f32 "
        "{%0,%1,%2,%3}, {%4,%5,%6,%7}, {%8,%9}, {%0,%1,%2,%3};"
        : "+f"(c[0]), "+f"(c[1]), "+f"(c[2]), "+f"(c[3])
        : "r"(a[0]), "r"(a[1]), "r"(a[2]), "r"(a[3]), "r"(b0), "r"(b1));
}
__device__ __forceinline__ void cp16(uint32_t smem, const void* g) {
    asm volatile("cp.async.ca.shared.global [%0], [%1], 16;" :: "r"(smem), "l"(g));
}
__device__ __forceinline__ uint32_t packbf2(__nv_bfloat16 a, __nv_bfloat16 b) {
    __nv_bfloat162 t = __halves2bfloat162(a, b);
    return *(uint32_t*)&t;
}

// ---------------------------------------------------------------------------
// Split-bf16 GEMM (projections): C[M,N] = A[M,K] @ B[N,K]^T.
// 2-stage cp.async pipeline, k16 steps, 128x64 block tile.
// ---------------------------------------------------------------------------
__global__ __launch_bounds__(256) void gemm_nt_split(
    const __nv_bfloat16* __restrict__ Ah, const __nv_bfloat16* __restrict__ Al,
    const __nv_bfloat16* __restrict__ Bh, const __nv_bfloat16* __restrict__ Bl,
    float* __restrict__ C, int M, int N, int K) {
    __shared__ __align__(16) __nv_bfloat16 sA[2][2][128][24];  // [stage][hi/lo]
    __shared__ __align__(16) __nv_bfloat16 sB[2][2][64][24];

    const int tid = threadIdx.x;
    const int wid = tid >> 5, lane = tid & 31;
    const int wm = (wid & 3) * 32;
    const int wn = (wid >> 2) * 32;
    const int m0 = blockIdx.y * 128, n0 = blockIdx.x * 64;
    const int KSTEPS = K >> 4;

    float acc[2][4][4] = {};
    const uint32_t aBase = (uint32_t)__cvta_generic_to_shared(&sA[0][0][0][0]);
    const uint32_t bBase = (uint32_t)__cvta_generic_to_shared(&sB[0][0][0][0]);

    // per-thread load assignment (constant across stages)
    const int arow = tid >> 1;
    const int akc = (tid & 1) * 8;
    const int bt = tid & 127;
    const int brow = bt >> 1;
    const int bkc = (bt & 1) * 8;
    const int bh_sel = tid >> 7;   // 0: hi, 1: lo
    const __nv_bfloat16* Bp = bh_sel ? Bl : Bh;

    auto load_stage = [&](int st, int kidx) {
        int kg = kidx * 16;
        uint32_t aS = aBase + (uint32_t)(st * 2 * 128 * 24) * 2;
        cp16(aS + (uint32_t)(arow * 24 + akc) * 2,
             Ah + (size_t)(m0 + arow) * K + kg + akc);
        cp16(aS + (uint32_t)(128 * 24 + arow * 24 + akc) * 2,
             Al + (size_t)(m0 + arow) * K + kg + akc);
        cp16(bBase + (uint32_t)((st * 2 + bh_sel) * 64 * 24 + brow * 24 + bkc) * 2,
             Bp + (size_t)(n0 + brow) * K + kg + bkc);
    };

    load_stage(0, 0);
    asm volatile("cp.async.commit_group;");

    for (int kidx = 0; kidx < KSTEPS; kidx++) {
        int st = kidx & 1;
        if (kidx + 1 < KSTEPS) {
            load_stage(st ^ 1, kidx + 1);
            asm volatile("cp.async.commit_group;");
            asm volatile("cp.async.wait_group 1;");
        } else {
            asm volatile("cp.async.wait_group 0;");
        }
        __syncthreads();

        uint32_t aST = aBase + (uint32_t)(st * 2 * 128 * 24) * 2;
        uint32_t bST = bBase + (uint32_t)(st * 2 * 64 * 24) * 2;
        uint32_t aH[2][4], aL[2][4], bF[2][4];
#pragma unroll
        for (int mt = 0; mt < 2; mt++) {
            int row = wm + mt * 16 + (lane & 15);
            int koff = (lane >> 4) * 8;
            uint32_t ad = aST + (uint32_t)(row * 24 + koff) * 2;
            ldsm_x4(aH[mt], ad);
            ldsm_x4(aL[mt], ad + 128 * 24 * 2);
        }
        {
            int rowp = wn + ((lane >> 4) & 1) * 8 + (lane & 7);
            int koff = ((lane >> 3) & 1) * 8;
#pragma unroll
            for (int p = 0; p < 2; p++)
                ldsm_x4(bF[p], bST + (uint32_t)((rowp + p * 16) * 24 + koff) * 2);
        }
#pragma unroll
        for (int mt = 0; mt < 2; mt++)
#pragma unroll
            for (int nt = 0; nt < 4; nt++) {
                uint32_t b0 = bF[nt >> 1][(nt & 1) * 2];
                uint32_t b1 = bF[nt >> 1][(nt & 1) * 2 + 1];
                mma16816(acc[mt][nt], aH[mt], b0, b1);   // hi*hi
                mma16816(acc[mt][nt], aL[mt], b0, b1);   // lo*hi
            }
        {
            int rowp = wn + ((lane >> 4) & 1) * 8 + (lane & 7);
            int koff = ((lane >> 3) & 1) * 8;
#pragma unroll
            for (int p = 0; p < 2; p++)
                ldsm_x4(bF[p], bST + (uint32_t)(64 * 24 + (rowp + p * 16) * 24 + koff) * 2);
        }
#pragma unroll
        for (int mt = 0; mt < 2; mt++)
#pragma unroll
            for (int nt = 0; nt < 4; nt++) {
                uint32_t b0 = bF[nt >> 1][(nt & 1) * 2];
                uint32_t b1 = bF[nt >> 1][(nt & 1) * 2 + 1];
                mma16816(acc[mt][nt], aH[mt], b0, b1);   // hi*lo
            }
        __syncthreads();
    }

#pragma unroll
    for (int mt = 0; mt < 2; mt++)
#pragma unroll
        for (int nt = 0; nt < 4; nt++) {
            int r = m0 + wm + mt * 16 + (lane >> 2);
            int cc = n0 + wn + nt * 8 + (lane & 3) * 2;
            *(float2*)(C + (size_t)r * N + cc) = make_float2(acc[mt][nt][0], acc[mt][nt][1]);
            *(float2*)(C + (size_t)(r + 8) * N + cc) = make_float2(acc[mt][nt][2], acc[mt][nt][3]);
        }
}

// ---------------------------------------------------------------------------
// src: [B,S,H] fp32 -> hi/lo bf16 [B,nh,S,hd], optional RoPE.
// ---------------------------------------------------------------------------
__global__ __launch_bounds__(256) void rope_split(const float* __restrict__ src,
                                                  __nv_bfloat16* __restrict__ dh,
                                                  __nv_bfloat16* __restrict__ dl,
                                                  int apply_rope) {
    int idx = blockIdx.x * blockDim.x + threadIdx.x;
    if (idx >= Bsz * NH * S * 32) return;
    int d = idx & 31;
    int s = (idx >> 5) & (S - 1);
    int h = (idx >> 16) & (NH - 1);
    int b = idx >> 20;

    const float* p = src + (size_t)(b * S + s) * H + h * HD;
    float v0 = p[d];
    float v1 = p[d + 32];

    if (apply_rope) {
        float c = g_cos[s * 32 + d];
        float sn = g_sin[s * 32 + d];
        float n0 = v0 * c - v1 * sn;
        float n1 = v1 * c + v0 * sn;
        v0 = n0; v1 = n1;
    }

    size_t o = ((size_t)(b * NH + h) * S + s) * HD;
    __nv_bfloat16 h0 = __float2bfloat16(v0);
    __nv_bfloat16 h1 = __float2bfloat16(v1);
    dh[o + d] = h0;
    dh[o + d + 32] = h1;
    dl[o + d] = __float2bfloat16(v0 - __bfloat162float(h0));
    dl[o + d + 32] = __float2bfloat16(v1 - __bfloat162float(h1));
}

// ---------------------------------------------------------------------------
// Tensor-core scores: attn_raw = (Q K^T)/8 + bias, pad-mask -> -1e30.
// ---------------------------------------------------------------------------
__global__ __launch_bounds__(256) void scores_mma(
    const __nv_bfloat16* __restrict__ Qh, const __nv_bfloat16* __restrict__ Ql,
    const __nv_bfloat16* __restrict__ Kh, const __nv_bfloat16* __restrict__ Kl,
    const float* __restrict__ bias, const int* __restrict__ mask,
    float* __restrict__ attn) {
    const int bh = blockIdx.z;
    const int b = bh >> 4;
    const int m0 = blockIdx.y * 128;
    const int n0 = blockIdx.x * 128;
    if (n0 > m0 + 127) return;

    __shared__ __align__(16) __nv_bfloat16 sQ[2][128][40];
    __shared__ __align__(16) __nv_bfloat16 sK[2][128][40];

    const int tid = threadIdx.x;
    const int wid = tid >> 5, lane = tid & 31;
    const int wm = (wid & 3) * 32;
    const int wn = (wid >> 2) * 64;
    const __nv_bfloat16* Qhb = Qh + (size_t)bh * S * HD;
    const __nv_bfloat16* Qlb = Ql + (size_t)bh * S * HD;
    const __nv_bfloat16* Khb = Kh + (size_t)bh * S * HD;
    const __nv_bfloat16* Klb = Kl + (size_t)bh * S * HD;

    float acc[2][8][4] = {};
    const uint32_t qBase = (uint32_t)__cvta_generic_to_shared(&sQ[0][0][0]);
    const uint32_t kBase = (uint32_t)__cvta_generic_to_shared(&sK[0][0][0]);

    for (int kk = 0; kk < HD; kk += 32) {
#pragma unroll
        for (int i = 0; i < 2; i++) {
            int c = tid + i * 256;
            int row = c >> 2, kc = (c & 3) * 8;
            *(uint4*)&sQ[0][row][kc] = *(const uint4*)(Qhb + (size_t)(m0 + row) * HD + kk + kc);
            *(uint4*)&sQ[1][row][kc] = *(const uint4*)(Qlb + (size_t)(m0 + row) * HD + kk + kc);
            *(uint4*)&sK[0][row][kc] = *(const uint4*)(Khb + (size_t)(n0 + row) * HD + kk + kc);
            *(uint4*)&sK[1][row][kc] = *(const uint4*)(Klb + (size_t)(n0 + row) * HD + kk + kc);
        }
        __syncthreads();

#pragma unroll
        for (int s = 0; s < 2; s++) {
            uint32_t aH[2][4], aL[2][4], bF[4][4];
#pragma unroll
            for (int mt = 0; mt < 2; mt++) {
                int row = wm + mt * 16 + (lane & 15);
                int koff = s * 16 + (lane >> 4) * 8;
                uint32_t ad = qBase + (uint32_t)(row * 40 + koff) * 2;
                ldsm_x4(aH[mt], ad);
                ldsm_x4(aL[mt], ad + 128 * 40 * 2);
            }
            {
                int rowp = wn + ((lane >> 4) & 1) * 8 + (lane & 7);
                int koff = s * 16 + ((lane >> 3) & 1) * 8;
#pragma unroll
                for (int p = 0; p < 4; p++) {
                    uint32_t bd = kBase + (uint32_t)((rowp + p * 16) * 40 + koff) * 2;
                    ldsm_x4(bF[p], bd);
                }
            }
#pragma unroll
            for (int mt = 0; mt < 2; mt++)
#pragma unroll
                for (int nt = 0; nt < 8; nt++) {
                    uint32_t b0 = bF[nt >> 1][(nt & 1) * 2];
                    uint32_t b1 = bF[nt >> 1][(nt & 1) * 2 + 1];
                    mma16816(acc[mt][nt], aH[mt], b0, b1);   // hi*hi
                    mma16816(acc[mt][nt], aL[mt], b0, b1);   // lo*hi
                }
            {
                int rowp = wn + ((lane >> 4) & 1) * 8 + (lane & 7);
                int koff = s * 16 + ((lane >> 3) & 1) * 8;
#pragma unroll
                for (int p = 0; p < 4; p++) {
                    uint32_t bd = kBase + (uint32_t)((rowp + p * 16) * 40 + koff) * 2 + 128 * 40 * 2;
                    ldsm_x4(bF[p], bd);
                }
            }
#pragma unroll
            for (int mt = 0; mt < 2; mt++)
#pragma unroll
                for (int nt = 0; nt < 8; nt++) {
                    uint32_t b0 = bF[nt >> 1][(nt & 1) * 2];
                    uint32_t b1 = bF[nt >> 1][(nt & 1) * 2 + 1];
                    mma16816(acc[mt][nt], aH[mt], b0, b1);   // hi*lo
                }
        }
        __syncthreads();
    }

#pragma unroll
    for (int mt = 0; mt < 2; mt++)
#pragma unroll
        for (int nt = 0; nt < 8; nt++) {
            int c = n0 + wn + nt * 8 + (lane & 3) * 2;
            int mk0 = mask[b * S + c];
            int mk1 = mask[b * S + c + 1];
#pragma unroll
            for (int half = 0; half < 2; half++) {
                int r = m0 + wm + mt * 16 + (lane >> 2) + half * 8;
                const float* brow = bias + (size_t)r * S;
                float v0 = acc[mt][nt][half * 2 + 0] * 0.125f + brow[c];
                float v1 = acc[mt][nt][half * 2 + 1] * 0.125f + brow[c + 1];
                if (mk0 == 0) v0 = -1e30f;
                if (mk1 == 0) v1 = -1e30f;
                *(float2*)(attn + ((size_t)bh * S + r) * S + c) = make_float2(v0, v1);
            }
        }
}

// ---------------------------------------------------------------------------
// Row-wise causal softmax in-place (fp32 only; zeros beyond the diagonal).
// ---------------------------------------------------------------------------
__global__ __launch_bounds__(256) void softmax_kernel(float* __restrict__ attn) {
    __shared__ float sc[S];
    __shared__ float red[8];
    const int row = blockIdx.x;
    const int q = row & (S - 1);
    const int n = q + 1;
    float* a = attn + (size_t)row * S;
    const int tid = threadIdx.x;

    float m = -3e38f;
    for (int k = tid; k < n; k += 256) {
        float v = a[k];
        sc[k] = v;
        m = fmaxf(m, v);
    }
#pragma unroll
    for (int o = 16; o; o >>= 1) m = fmaxf(m, __shfl_xor_sync(0xffffffffu, m, o));
    if ((tid & 31) == 0) red[tid >> 5] = m;
    __syncthreads();
    m = red[0];
#pragma unroll
    for (int w = 1; w < 8; w++) m = fmaxf(m, red[w]);
    __syncthreads();

    float ssum = 0.f;
    for (int k = tid; k < n; k += 256) {
        float e = __expf(sc[k] - m);
        sc[k] = e;
        ssum += e;
    }
#pragma unroll
    for (int o = 16; o; o >>= 1) ssum += __shfl_xor_sync(0xffffffffu, ssum, o);
    if ((tid & 31) == 0) red[tid >> 5] = ssum;
    __syncthreads();
    ssum = 0.f;
#pragma unroll
    for (int w = 0; w < 8; w++) ssum += red[w];

    float inv = 1.f / ssum;
    for (int k = tid; k < S; k += 256) a[k] = (k < n) ? sc[k] * inv : 0.f;
}

// ---------------------------------------------------------------------------
// Tensor-core AV reading fp32 attn (split to bf16 hi/lo in registers).
// ---------------------------------------------------------------------------
__global__ __launch_bounds__(256) void av_mma(
    const float* __restrict__ attn,
    const __nv_bfloat16* __restrict__ Vh, const __nv_bfloat16* __restrict__ Vl,
    float* __restrict__ ctx) {
    const int bh = blockIdx.z;
    const int b = bh >> 4;
    const int h = bh & 15;
    const int m0 = blockIdx.x * 128;

    __shared__ __align__(16) __nv_bfloat16 sA[2][128][40];   // hi/lo attn q x k32
    __shared__ __align__(16) __nv_bfloat16 sV[2][32][72];    // k32 x 64dim

    const int tid = threadIdx.x;
    const int wid = tid >> 5, lane = tid & 31;
    const int wm = (wid & 3) * 32;
    const int wn = (wid >> 2) * 32;
    const float* Ab = attn + (size_t)bh * S * S;
    const __nv_bfloat16* Vhb = Vh + (size_t)bh * S * HD;
    const __nv_bfloat16* Vlb = Vl + (size_t)bh * S * HD;

    float acc[2][4][4] = {};
    const uint32_t aBase = (uint32_t)__cvta_generic_to_shared(&sA[0][0][0]);
    const uint32_t vBase = (uint32_t)__cvta_generic_to_shared(&sV[0][0][0]);

    const int arow = tid >> 1;
    const int akc = (tid & 1) * 16;

    const int kmax = m0 + 128;
    for (int k0 = 0; k0 < kmax; k0 += 32) {
        {   // A tile: fp32 -> split bf16 in registers -> smem
            const float* src = Ab + (size_t)(m0 + arow) * S + k0 + akc;
            float4 f0 = *(const float4*)(src + 0);
            float4 f1 = *(const float4*)(src + 4);
            float4 f2 = *(const float4*)(src + 8);
            float4 f3 = *(const float4*)(src + 12);
            float v[16] = {f0.x, f0.y, f0.z, f0.w, f1.x, f1.y, f1.z, f1.w,
                           f2.x, f2.y, f2.z, f2.w, f3.x, f3.y, f3.z, f3.w};
            uint32_t hw[8], lw[8];
#pragma unroll
            for (int i = 0; i < 8; i++) {
                float a0 = v[2 * i], a1 = v[2 * i + 1];
                __nv_bfloat16 h0 = __float2bfloat16(a0);
                __nv_bfloat16 h1 = __float2bfloat16(a1);
                hw[i] = packbf2(h0, h1);
                lw[i] = packbf2(__float2bfloat16(a0 - __bfloat162float(h0)),
                                __float2bfloat16(a1 - __bfloat162float(h1)));
            }
            *(uint4*)&sA[0][arow][akc]     = make_uint4(hw[0], hw[1], hw[2], hw[3]);
            *(uint4*)&sA[0][arow][akc + 8] = make_uint4(hw[4], hw[5], hw[6], hw[7]);
            *(uint4*)&sA[1][arow][akc]     = make_uint4(lw[0], lw[1], lw[2], lw[3]);
            *(uint4*)&sA[1][arow][akc + 8] = make_uint4(lw[4], lw[5], lw[6], lw[7]);
        }
        {
            int row = tid >> 3, col = (tid & 7) * 8;
            *(uint4*)&sV[0][row][col] = *(const uint4*)(Vhb + (size_t)(k0 + row) * HD + col);
            *(uint4*)&sV[1][row][col] = *(const uint4*)(Vlb + (size_t)(k0 + row) * HD + col);
        }
        __syncthreads();

#pragma unroll
        for (int s = 0; s < 2; s++) {
            uint32_t aH[2][4], aL[2][4], bF[2][4];
#pragma unroll
            for (int mt = 0; mt < 2; mt++) {
                int row = wm + mt * 16 + (lane & 15);
                int koff = s * 16 + (lane >> 4) * 8;
                uint32_t ad = aBase + (uint32_t)(row * 40 + koff) * 2;
                ldsm_x4(aH[mt], ad);
                ldsm_x4(aL[mt], ad + 128 * 40 * 2);
            }
            {
                int krow = s * 16 + (lane & 7) + ((lane >> 3) & 1) * 8;
                int col = wn + (lane >> 4) * 8;
#pragma unroll
                for (int p = 0; p < 2; p++) {
                    uint32_t bd = vBase + (uint32_t)(krow * 72 + col + p * 16) * 2;
                    ldsm_x4_t(bF[p], bd);
                }
            }
#pragma unroll
            for (int mt = 0; mt < 2; mt++)
#pragma unroll
                for (int nt = 0; nt < 4; nt++) {
                    uint32_t b0 = bF[nt >> 1][(nt & 1) * 2];
                    uint32_t b1 = bF[nt >> 1][(nt & 1) * 2 + 1];
                    mma16816(acc[mt][nt], aH[mt], b0, b1);   // hi*hi
                    mma16816(acc[mt][nt], aL[mt], b0, b1);   // lo*hi
                }
            {
                int krow = s * 16 + (lane & 7) + ((lane >> 3) & 1) * 8;
                int col = wn + (lane >> 4) * 8;
#pragma unroll
                for (int p = 0; p < 2; p++) {
                    uint32_t bd = vBase + (uint32_t)(krow * 72 + col + p * 16) * 2 + 32 * 72 * 2;
                    ldsm_x4_t(bF[p], bd);
                }
            }
#pragma unroll
            for (int mt = 0; mt < 2; mt++)
#pragma unroll
                for (int nt = 0; nt < 4; nt++) {
                    uint32_t b0 = bF[nt >> 1][(nt & 1) * 2];
                    uint32_t b1 = bF[nt >> 1][(nt & 1) * 2 + 1];
                    mma16816(acc[mt][nt], aH[mt], b0, b1);   // hi*lo
                }
        }
        __syncthreads();
    }

#pragma unroll
    for (int mt = 0; mt < 2; mt++)
#pragma unroll
        for (int nt = 0; nt < 4; nt++) {
            int c = wn + nt * 8 + (lane & 3) * 2;
#pragma unroll
            for (int half = 0; half < 2; half++) {
                int r = m0 + wm + mt * 16 + (lane >> 2) + half * 8;
                *(float2*)(ctx + ((size_t)(b * S + r) * NH + h) * HD + c) =
                    make_float2(acc[mt][nt][half * 2 + 0], acc[mt][nt][half * 2 + 1]);
            }
        }
}

// ---------------------------------------------------------------------------
extern "C" void kernel_launch(void* const* d_in, const int* in_sizes, int n_in,
                              void* d_out, int out_size) {
    const float* x    = (const float*)d_in[0];
    const int*   mask = (const int*)d_in[1];
    const float* Wq   = (const float*)d_in[2];
    const float* Wk   = (const float*)d_in[3];
    const float* Wv   = (const float*)d_in[4];
    const float* Wo   = (const float*)d_in[5];
    const float* bias = (const float*)d_in[6];

    float* out  = (float*)d_out;
    float* attn = out + (size_t)Bsz * S * H;

    float *tmp, *ctx;
    cudaGetSymbolAddress((void**)&tmp, g_tmp);
    cudaGetSymbolAddress((void**)&ctx, g_ctx);
    __nv_bfloat16 *xh, *xl, *ch, *cl, *wh, *wl;
    __nv_bfloat16 *qh, *ql, *kh, *kl, *vh, *vl;
    cudaGetSymbolAddress((void**)&xh, g_xh);
    cudaGetSymbolAddress((void**)&xl, g_xl);
    cudaGetSymbolAddress((void**)&ch, g_ch);
    cudaGetSymbolAddress((void**)&cl, g_cl);
    cudaGetSymbolAddress((void**)&wh, g_wh);
    cudaGetSymbolAddress((void**)&wl, g_wl);
    cudaGetSymbolAddress((void**)&qh, g_qh);
    cudaGetSymbolAddress((void**)&ql, g_ql);
    cudaGetSymbolAddress((void**)&kh, g_kh);
    cudaGetSymbolAddress((void**)&kl, g_kl);
    cudaGetSymbolAddress((void**)&vh, g_vh);
    cudaGetSymbolAddress((void**)&vl, g_vl);

    const int M = Bsz * S;                        // 4096
    const int MH = M * H;
    const int HH = H * H;
    dim3 gproj(H / 64, M / 128);                  // (16, 32)
    const int rope_threads = Bsz * NH * S * 32;

    rope_table_kernel<<<(S * 32) / 256, 256>>>();
    split_kernel<<<MH / 4 / 256, 256>>>(x, xh, xl, MH);
    split_kernel<<<HH / 4 / 256, 256>>>(Wq, wh + 0 * HH, wl + 0 * HH, HH);
    split_kernel<<<HH / 4 / 256, 256>>>(Wk, wh + 1 * HH, wl + 1 * HH, HH);
    split_kernel<<<HH / 4 / 256, 256>>>(Wv, wh + 2 * HH, wl + 2 * HH, HH);
    split_kernel<<<HH / 4 / 256, 256>>>(Wo, wh + 3 * HH, wl + 3 * HH, HH);

    gemm_nt_split<<<gproj, 256>>>(xh, xl, wh + 0 * HH, wl + 0 * HH, tmp, M, H, H);
    rope_split<<<rope_threads / 256, 256>>>(tmp, qh, ql, 1);

    gemm_nt_split<<<gproj, 256>>>(xh, xl, wh + 1 * HH, wl + 1 * HH, tmp, M, H, H);
    rope_split<<<rope_threads / 256, 256>>>(tmp, kh, kl, 1);

    gemm_nt_split<<<gproj, 256>>>(xh, xl, wh + 2 * HH, wl + 2 * HH, tmp, M, H, H);
    rope_split<<<rope_threads / 256, 256>>>(tmp, vh, vl, 0);

    scores_mma<<<dim3(S / 128, S / 128, Bsz * NH), 256>>>(qh, ql, kh, kl, bias, mask, attn);
    softmax_kernel<<<Bsz * NH * S, 256>>>(attn);
    av_mma<<<dim3(S / 128, 1, Bsz * NH), 256>>>(attn, vh, vl, ctx);

    split_kernel<<<MH / 4 / 256, 256>>>(ctx, ch, cl, MH);
    gemm_nt_split<<<gproj, 256>>>(ch, cl, wh + 3 * HH, wl + 3 * HH, out, M, H, H);
}

// round 6
// speedup vs baseline: 2.7861x; 1.1188x over previous
#include <cuda_runtime.h>
#include <cuda_bf16.h>
#include <math.h>
#include <stdint.h>

#define Bsz 2
#define S 2048
#define H 1024
#define NH 16
#define HD 64

// Scratch (allocation-free rule: __device__ globals)
__device__ float g_tmp[Bsz * S * 3 * H];   // fused QKV projection output
__device__ float g_ctx[Bsz * S * H];
__device__ float g_cos[S * 32];
__device__ float g_sin[S * 32];
// split-bf16 buffers
__device__ __nv_bfloat16 g_xh[Bsz * S * H];
__device__ __nv_bfloat16 g_xl[Bsz * S * H];
__device__ __nv_bfloat16 g_ch[Bsz * S * H];
__device__ __nv_bfloat16 g_cl[Bsz * S * H];
__device__ __nv_bfloat16 g_wh[4 * H * H];   // Wq,Wk,Wv contiguous = [3H,H]; Wo at 3*HH
__device__ __nv_bfloat16 g_wl[4 * H * H];
__device__ __nv_bfloat16 g_qh[Bsz * S * H];
__device__ __nv_bfloat16 g_ql[Bsz * S * H];
__device__ __nv_bfloat16 g_kh[Bsz * S * H];
__device__ __nv_bfloat16 g_kl[Bsz * S * H];
__device__ __nv_bfloat16 g_vh[Bsz * S * H];
__device__ __nv_bfloat16 g_vl[Bsz * S * H];

// ---------------------------------------------------------------------------
__global__ __launch_bounds__(256) void rope_table_kernel() {
    int idx = blockIdx.x * blockDim.x + threadIdx.x;
    if (idx >= S * 32) return;
    int d = idx & 31;
    int s = idx >> 5;
    double inv = pow(10000.0, -(double)(2 * d) / 64.0);
    double ang = (double)s * inv;
    double sd, cd;
    sincos(ang, &sd, &cd);
    g_cos[idx] = (float)cd;
    g_sin[idx] = (float)sd;
}

// ---------------------------------------------------------------------------
__global__ __launch_bounds__(256) void split_kernel(const float* __restrict__ src,
                                                    __nv_bfloat16* __restrict__ hi,
                                                    __nv_bfloat16* __restrict__ lo,
                                                    int n) {
    int i = (blockIdx.x * 256 + threadIdx.x) * 4;
    if (i >= n) return;
    float4 v = *(const float4*)(src + i);
    __nv_bfloat16 h0 = __float2bfloat16(v.x);
    __nv_bfloat16 h1 = __float2bfloat16(v.y);
    __nv_bfloat16 h2 = __float2bfloat16(v.z);
    __nv_bfloat16 h3 = __float2bfloat16(v.w);
    __nv_bfloat16 l0 = __float2bfloat16(v.x - __bfloat162float(h0));
    __nv_bfloat16 l1 = __float2bfloat16(v.y - __bfloat162float(h1));
    __nv_bfloat16 l2 = __float2bfloat16(v.z - __bfloat162float(h2));
    __nv_bfloat16 l3 = __float2bfloat16(v.w - __bfloat162float(h3));
    *(__nv_bfloat162*)(hi + i)     = __halves2bfloat162(h0, h1);
    *(__nv_bfloat162*)(hi + i + 2) = __halves2bfloat162(h2, h3);
    *(__nv_bfloat162*)(lo + i)     = __halves2bfloat162(l0, l1);
    *(__nv_bfloat162*)(lo + i + 2) = __halves2bfloat162(l2, l3);
}

// ---------------------------------------------------------------------------
// MMA / async-copy helpers
// ---------------------------------------------------------------------------
__device__ __forceinline__ void ldsm_x4(uint32_t (&r)[4], uint32_t addr) {
    asm volatile("ldmatrix.sync.aligned.m8n8.x4.shared.b16 {%0,%1,%2,%3}, [%4];"
                 : "=r"(r[0]), "=r"(r[1]), "=r"(r[2]), "=r"(r[3]) : "r"(addr));
}
__device__ __forceinline__ void ldsm_x4_t(uint32_t (&r)[4], uint32_t addr) {
    asm volatile("ldmatrix.sync.aligned.m8n8.x4.trans.shared.b16 {%0,%1,%2,%3}, [%4];"
                 : "=r"(r[0]), "=r"(r[1]), "=r"(r[2]), "=r"(r[3]) : "r"(addr));
}
__device__ __forceinline__ void mma16816(float (&c)[4], const uint32_t (&a)[4],
                                         uint32_t b0, uint32_t b1) {
    asm volatile(
        "mma.sync.aligned.m16n8k16.row.col.f32.bf16.bf16.f32 "
        "{%0,%1,%2,%3}, {%4,%5,%6,%7}, {%8,%9}, {%0,%1,%2,%3};"
        : "+f"(c[0]), "+f"(c[1]), "+f"(c[2]), "+f"(c[3])
        : "r"(a[0]), "r"(a[1]), "r"(a[2]), "r"(a[3]), "r"(b0), "r"(b1));
}
__device__ __forceinline__ void cp16(uint32_t smem, const void* g) {
    asm volatile("cp.async.ca.shared.global [%0], [%1], 16;" :: "r"(smem), "l"(g));
}
__device__ __forceinline__ uint32_t packbf2(__nv_bfloat16 a, __nv_bfloat16 b) {
    __nv_bfloat162 t = __halves2bfloat162(a, b);
    return *(uint32_t*)&t;
}

// ---------------------------------------------------------------------------
// Split-bf16 GEMM: C[M,N] = A[M,K] @ B[N,K]^T.
// 3-stage cp.async pipeline, k32 steps, 128x64 block tile, 8 warps (4x2).
// ---------------------------------------------------------------------------
__global__ __launch_bounds__(256) void gemm_nt_split(
    const __nv_bfloat16* __restrict__ Ah, const __nv_bfloat16* __restrict__ Al,
    const __nv_bfloat16* __restrict__ Bh, const __nv_bfloat16* __restrict__ Bl,
    float* __restrict__ C, int M, int N, int K) {
    __shared__ __align__(16) __nv_bfloat16 sA[3][2][128][40];  // [stage][hi/lo]
    __shared__ __align__(16) __nv_bfloat16 sB[3][2][64][40];

    const int tid = threadIdx.x;
    const int wid = tid >> 5, lane = tid & 31;
    const int wm = (wid & 3) * 32;
    const int wn = (wid >> 2) * 32;
    const int m0 = blockIdx.y * 128, n0 = blockIdx.x * 64;
    const int KSTEPS = K >> 5;   // k32 steps

    float acc[2][4][4] = {};
    const uint32_t aBase = (uint32_t)__cvta_generic_to_shared(&sA[0][0][0][0]);
    const uint32_t bBase = (uint32_t)__cvta_generic_to_shared(&sB[0][0][0][0]);

    auto load_stage = [&](int st, int kg) {
#pragma unroll
        for (int i = 0; i < 2; i++) {       // A hi/lo: 512 chunks each
            int c = tid + i * 256;
            int row = c >> 2, kc = (c & 3) * 8;
            uint32_t d0 = aBase + (uint32_t)((st * 2 + 0) * 128 * 40 + row * 40 + kc) * 2;
            uint32_t d1 = aBase + (uint32_t)((st * 2 + 1) * 128 * 40 + row * 40 + kc) * 2;
            cp16(d0, Ah + (size_t)(m0 + row) * K + kg + kc);
            cp16(d1, Al + (size_t)(m0 + row) * K + kg + kc);
        }
        {                                    // B hi/lo: 256 chunks each
            int row = tid >> 2, kc = (tid & 3) * 8;
            uint32_t d0 = bBase + (uint32_t)((st * 2 + 0) * 64 * 40 + row * 40 + kc) * 2;
            uint32_t d1 = bBase + (uint32_t)((st * 2 + 1) * 64 * 40 + row * 40 + kc) * 2;
            cp16(d0, Bh + (size_t)(n0 + row) * K + kg + kc);
            cp16(d1, Bl + (size_t)(n0 + row) * K + kg + kc);
        }
        asm volatile("cp.async.commit_group;");
    };

    load_stage(0, 0);
    load_stage(1, 32);

    int st = 0;
    for (int kidx = 0; kidx < KSTEPS; kidx++) {
        if (kidx + 2 < KSTEPS) {
            load_stage((st + 2) % 3, (kidx + 2) * 32);
            asm volatile("cp.async.wait_group 2;");
        } else if (kidx + 2 == KSTEPS) {
            asm volatile("cp.async.wait_group 1;");
        } else {
            asm volatile("cp.async.wait_group 0;");
        }
        __syncthreads();

        uint32_t aST = aBase + (uint32_t)(st * 2 * 128 * 40) * 2;
        uint32_t bST = bBase + (uint32_t)(st * 2 * 64 * 40) * 2;

#pragma unroll
        for (int s = 0; s < 2; s++) {
            uint32_t aH[2][4], aL[2][4], bF[2][4];
#pragma unroll
            for (int mt = 0; mt < 2; mt++) {
                int row = wm + mt * 16 + (lane & 15);
                int koff = s * 16 + (lane >> 4) * 8;
                uint32_t ad = aST + (uint32_t)(row * 40 + koff) * 2;
                ldsm_x4(aH[mt], ad);
                ldsm_x4(aL[mt], ad + 128 * 40 * 2);
            }
            {
                int rowp = wn + ((lane >> 4) & 1) * 8 + (lane & 7);
                int koff = s * 16 + ((lane >> 3) & 1) * 8;
#pragma unroll
                for (int p = 0; p < 2; p++)
                    ldsm_x4(bF[p], bST + (uint32_t)((rowp + p * 16) * 40 + koff) * 2);
            }
#pragma unroll
            for (int mt = 0; mt < 2; mt++)
#pragma unroll
                for (int nt = 0; nt < 4; nt++) {
                    uint32_t b0 = bF[nt >> 1][(nt & 1) * 2];
                    uint32_t b1 = bF[nt >> 1][(nt & 1) * 2 + 1];
                    mma16816(acc[mt][nt], aH[mt], b0, b1);   // hi*hi
                    mma16816(acc[mt][nt], aL[mt], b0, b1);   // lo*hi
                }
            {
                int rowp = wn + ((lane >> 4) & 1) * 8 + (lane & 7);
                int koff = s * 16 + ((lane >> 3) & 1) * 8;
#pragma unroll
                for (int p = 0; p < 2; p++)
                    ldsm_x4(bF[p], bST + (uint32_t)(64 * 40 + (rowp + p * 16) * 40 + koff) * 2);
            }
#pragma unroll
            for (int mt = 0; mt < 2; mt++)
#pragma unroll
                for (int nt = 0; nt < 4; nt++) {
                    uint32_t b0 = bF[nt >> 1][(nt & 1) * 2];
                    uint32_t b1 = bF[nt >> 1][(nt & 1) * 2 + 1];
                    mma16816(acc[mt][nt], aH[mt], b0, b1);   // hi*lo
                }
        }
        __syncthreads();
        st = (st + 1) % 3;
    }

#pragma unroll
    for (int mt = 0; mt < 2; mt++)
#pragma unroll
        for (int nt = 0; nt < 4; nt++) {
            int r = m0 + wm + mt * 16 + (lane >> 2);
            int cc = n0 + wn + nt * 8 + (lane & 3) * 2;
            *(float2*)(C + (size_t)r * N + cc) = make_float2(acc[mt][nt][0], acc[mt][nt][1]);
            *(float2*)(C + (size_t)(r + 8) * N + cc) = make_float2(acc[mt][nt][2], acc[mt][nt][3]);
        }
}

// ---------------------------------------------------------------------------
// Fused rope+split for QKV: tmp [B,S,3H] -> qh/ql,kh/kl (rope), vh/vl.
// ---------------------------------------------------------------------------
__global__ __launch_bounds__(256) void rope_qkv(const float* __restrict__ tmp,
                                                __nv_bfloat16* __restrict__ qh,
                                                __nv_bfloat16* __restrict__ ql,
                                                __nv_bfloat16* __restrict__ kh,
                                                __nv_bfloat16* __restrict__ kl,
                                                __nv_bfloat16* __restrict__ vh,
                                                __nv_bfloat16* __restrict__ vl) {
    int idx = blockIdx.x * blockDim.x + threadIdx.x;
    if (idx >= Bsz * NH * S * 32) return;
    int d = idx & 31;
    int s = (idx >> 5) & (S - 1);
    int h = (idx >> 16) & (NH - 1);
    int b = idx >> 20;

    const float* p = tmp + (size_t)(b * S + s) * (3 * H) + h * HD;
    float q0 = p[d], q1 = p[d + 32];
    float k0 = p[H + d], k1 = p[H + d + 32];
    float v0 = p[2 * H + d], v1 = p[2 * H + d + 32];

    float c = g_cos[s * 32 + d];
    float sn = g_sin[s * 32 + d];
    float nq0 = q0 * c - q1 * sn, nq1 = q1 * c + q0 * sn;
    float nk0 = k0 * c - k1 * sn, nk1 = k1 * c + k0 * sn;

    size_t o = ((size_t)(b * NH + h) * S + s) * HD;
    __nv_bfloat16 t;
    t = __float2bfloat16(nq0); qh[o + d] = t;      ql[o + d] = __float2bfloat16(nq0 - __bfloat162float(t));
    t = __float2bfloat16(nq1); qh[o + d + 32] = t; ql[o + d + 32] = __float2bfloat16(nq1 - __bfloat162float(t));
    t = __float2bfloat16(nk0); kh[o + d] = t;      kl[o + d] = __float2bfloat16(nk0 - __bfloat162float(t));
    t = __float2bfloat16(nk1); kh[o + d + 32] = t; kl[o + d + 32] = __float2bfloat16(nk1 - __bfloat162float(t));
    t = __float2bfloat16(v0);  vh[o + d] = t;      vl[o + d] = __float2bfloat16(v0 - __bfloat162float(t));
    t = __float2bfloat16(v1);  vh[o + d + 32] = t; vl[o + d + 32] = __float2bfloat16(v1 - __bfloat162float(t));
}

// ---------------------------------------------------------------------------
// Tensor-core scores: attn_raw = (Q K^T)/8 + bias, pad-mask -> -1e30.
// ---------------------------------------------------------------------------
__global__ __launch_bounds__(256) void scores_mma(
    const __nv_bfloat16* __restrict__ Qh, const __nv_bfloat16* __restrict__ Ql,
    const __nv_bfloat16* __restrict__ Kh, const __nv_bfloat16* __restrict__ Kl,
    const float* __restrict__ bias, const int* __restrict__ mask,
    float* __restrict__ attn) {
    const int bh = blockIdx.z;
    const int b = bh >> 4;
    const int m0 = blockIdx.y * 128;
    const int n0 = blockIdx.x * 128;
    if (n0 > m0 + 127) return;

    __shared__ __align__(16) __nv_bfloat16 sQ[2][128][40];
    __shared__ __align__(16) __nv_bfloat16 sK[2][128][40];

    const int tid = threadIdx.x;
    const int wid = tid >> 5, lane = tid & 31;
    const int wm = (wid & 3) * 32;
    const int wn = (wid >> 2) * 64;
    const __nv_bfloat16* Qhb = Qh + (size_t)bh * S * HD;
    const __nv_bfloat16* Qlb = Ql + (size_t)bh * S * HD;
    const __nv_bfloat16* Khb = Kh + (size_t)bh * S * HD;
    const __nv_bfloat16* Klb = Kl + (size_t)bh * S * HD;

    float acc[2][8][4] = {};
    const uint32_t qBase = (uint32_t)__cvta_generic_to_shared(&sQ[0][0][0]);
    const uint32_t kBase = (uint32_t)__cvta_generic_to_shared(&sK[0][0][0]);

    for (int kk = 0; kk < HD; kk += 32) {
#pragma unroll
        for (int i = 0; i < 2; i++) {
            int c = tid + i * 256;
            int row = c >> 2, kc = (c & 3) * 8;
            *(uint4*)&sQ[0][row][kc] = *(const uint4*)(Qhb + (size_t)(m0 + row) * HD + kk + kc);
            *(uint4*)&sQ[1][row][kc] = *(const uint4*)(Qlb + (size_t)(m0 + row) * HD + kk + kc);
            *(uint4*)&sK[0][row][kc] = *(const uint4*)(Khb + (size_t)(n0 + row) * HD + kk + kc);
            *(uint4*)&sK[1][row][kc] = *(const uint4*)(Klb + (size_t)(n0 + row) * HD + kk + kc);
        }
        __syncthreads();

#pragma unroll
        for (int s = 0; s < 2; s++) {
            uint32_t aH[2][4], aL[2][4], bF[4][4];
#pragma unroll
            for (int mt = 0; mt < 2; mt++) {
                int row = wm + mt * 16 + (lane & 15);
                int koff = s * 16 + (lane >> 4) * 8;
                uint32_t ad = qBase + (uint32_t)(row * 40 + koff) * 2;
                ldsm_x4(aH[mt], ad);
                ldsm_x4(aL[mt], ad + 128 * 40 * 2);
            }
            {
                int rowp = wn + ((lane >> 4) & 1) * 8 + (lane & 7);
                int koff = s * 16 + ((lane >> 3) & 1) * 8;
#pragma unroll
                for (int p = 0; p < 4; p++) {
                    uint32_t bd = kBase + (uint32_t)((rowp + p * 16) * 40 + koff) * 2;
                    ldsm_x4(bF[p], bd);
                }
            }
#pragma unroll
            for (int mt = 0; mt < 2; mt++)
#pragma unroll
                for (int nt = 0; nt < 8; nt++) {
                    uint32_t b0 = bF[nt >> 1][(nt & 1) * 2];
                    uint32_t b1 = bF[nt >> 1][(nt & 1) * 2 + 1];
                    mma16816(acc[mt][nt], aH[mt], b0, b1);   // hi*hi
                    mma16816(acc[mt][nt], aL[mt], b0, b1);   // lo*hi
                }
            {
                int rowp = wn + ((lane >> 4) & 1) * 8 + (lane & 7);
                int koff = s * 16 + ((lane >> 3) & 1) * 8;
#pragma unroll
                for (int p = 0; p < 4; p++) {
                    uint32_t bd = kBase + (uint32_t)((rowp + p * 16) * 40 + koff) * 2 + 128 * 40 * 2;
                    ldsm_x4(bF[p], bd);
                }
            }
#pragma unroll
            for (int mt = 0; mt < 2; mt++)
#pragma unroll
                for (int nt = 0; nt < 8; nt++) {
                    uint32_t b0 = bF[nt >> 1][(nt & 1) * 2];
                    uint32_t b1 = bF[nt >> 1][(nt & 1) * 2 + 1];
                    mma16816(acc[mt][nt], aH[mt], b0, b1);   // hi*lo
                }
        }
        __syncthreads();
    }

#pragma unroll
    for (int mt = 0; mt < 2; mt++)
#pragma unroll
        for (int nt = 0; nt < 8; nt++) {
            int c = n0 + wn + nt * 8 + (lane & 3) * 2;
            int mk0 = mask[b * S + c];
            int mk1 = mask[b * S + c + 1];
#pragma unroll
            for (int half = 0; half < 2; half++) {
                int r = m0 + wm + mt * 16 + (lane >> 2) + half * 8;
                const float* brow = bias + (size_t)r * S;
                float v0 = acc[mt][nt][half * 2 + 0] * 0.125f + brow[c];
                float v1 = acc[mt][nt][half * 2 + 1] * 0.125f + brow[c + 1];
                if (mk0 == 0) v0 = -1e30f;
                if (mk1 == 0) v1 = -1e30f;
                *(float2*)(attn + ((size_t)bh * S + r) * S + c) = make_float2(v0, v1);
            }
        }
}

// ---------------------------------------------------------------------------
// Row-wise causal softmax in-place (fp32 only; zeros beyond the diagonal).
// ---------------------------------------------------------------------------
__global__ __launch_bounds__(256) void softmax_kernel(float* __restrict__ attn) {
    __shared__ float sc[S];
    __shared__ float red[8];
    const int row = blockIdx.x;
    const int q = row & (S - 1);
    const int n = q + 1;
    float* a = attn + (size_t)row * S;
    const int tid = threadIdx.x;

    float m = -3e38f;
    for (int k = tid; k < n; k += 256) {
        float v = a[k];
        sc[k] = v;
        m = fmaxf(m, v);
    }
#pragma unroll
    for (int o = 16; o; o >>= 1) m = fmaxf(m, __shfl_xor_sync(0xffffffffu, m, o));
    if ((tid & 31) == 0) red[tid >> 5] = m;
    __syncthreads();
    m = red[0];
#pragma unroll
    for (int w = 1; w < 8; w++) m = fmaxf(m, red[w]);
    __syncthreads();

    float ssum = 0.f;
    for (int k = tid; k < n; k += 256) {
        float e = __expf(sc[k] - m);
        sc[k] = e;
        ssum += e;
    }
#pragma unroll
    for (int o = 16; o; o >>= 1) ssum += __shfl_xor_sync(0xffffffffu, ssum, o);
    if ((tid & 31) == 0) red[tid >> 5] = ssum;
    __syncthreads();
    ssum = 0.f;
#pragma unroll
    for (int w = 0; w < 8; w++) ssum += red[w];

    float inv = 1.f / ssum;
    for (int k = tid; k < S; k += 256) a[k] = (k < n) ? sc[k] * inv : 0.f;
}

// ---------------------------------------------------------------------------
// Tensor-core AV reading fp32 attn (split to bf16 hi/lo in registers).
// ---------------------------------------------------------------------------
__global__ __launch_bounds__(256) void av_mma(
    const float* __restrict__ attn,
    const __nv_bfloat16* __restrict__ Vh, const __nv_bfloat16* __restrict__ Vl,
    float* __restrict__ ctx) {
    const int bh = blockIdx.z;
    const int b = bh >> 4;
    const int h = bh & 15;
    const int m0 = blockIdx.x * 128;

    __shared__ __align__(16) __nv_bfloat16 sA[2][128][40];
    __shared__ __align__(16) __nv_bfloat16 sV[2][32][72];

    const int tid = threadIdx.x;
    const int wid = tid >> 5, lane = tid & 31;
    const int wm = (wid & 3) * 32;
    const int wn = (wid >> 2) * 32;
    const float* Ab = attn + (size_t)bh * S * S;
    const __nv_bfloat16* Vhb = Vh + (size_t)bh * S * HD;
    const __nv_bfloat16* Vlb = Vl + (size_t)bh * S * HD;

    float acc[2][4][4] = {};
    const uint32_t aBase = (uint32_t)__cvta_generic_to_shared(&sA[0][0][0]);
    const uint32_t vBase = (uint32_t)__cvta_generic_to_shared(&sV[0][0][0]);

    const int arow = tid >> 1;
    const int akc = (tid & 1) * 16;

    const int kmax = m0 + 128;
    for (int k0 = 0; k0 < kmax; k0 += 32) {
        {
            const float* src = Ab + (size_t)(m0 + arow) * S + k0 + akc;
            float4 f0 = *(const float4*)(src + 0);
            float4 f1 = *(const float4*)(src + 4);
            float4 f2 = *(const float4*)(src + 8);
            float4 f3 = *(const float4*)(src + 12);
            float v[16] = {f0.x, f0.y, f0.z, f0.w, f1.x, f1.y, f1.z, f1.w,
                           f2.x, f2.y, f2.z, f2.w, f3.x, f3.y, f3.z, f3.w};
            uint32_t hw[8], lw[8];
#pragma unroll
            for (int i = 0; i < 8; i++) {
                float a0 = v[2 * i], a1 = v[2 * i + 1];
                __nv_bfloat16 h0 = __float2bfloat16(a0);
                __nv_bfloat16 h1 = __float2bfloat16(a1);
                hw[i] = packbf2(h0, h1);
                lw[i] = packbf2(__float2bfloat16(a0 - __bfloat162float(h0)),
                                __float2bfloat16(a1 - __bfloat162float(h1)));
            }
            *(uint4*)&sA[0][arow][akc]     = make_uint4(hw[0], hw[1], hw[2], hw[3]);
            *(uint4*)&sA[0][arow][akc + 8] = make_uint4(hw[4], hw[5], hw[6], hw[7]);
            *(uint4*)&sA[1][arow][akc]     = make_uint4(lw[0], lw[1], lw[2], lw[3]);
            *(uint4*)&sA[1][arow][akc + 8] = make_uint4(lw[4], lw[5], lw[6], lw[7]);
        }
        {
            int row = tid >> 3, col = (tid & 7) * 8;
            *(uint4*)&sV[0][row][col] = *(const uint4*)(Vhb + (size_t)(k0 + row) * HD + col);
            *(uint4*)&sV[1][row][col] = *(const uint4*)(Vlb + (size_t)(k0 + row) * HD + col);
        }
        __syncthreads();

#pragma unroll
        for (int s = 0; s < 2; s++) {
            uint32_t aH[2][4], aL[2][4], bF[2][4];
#pragma unroll
            for (int mt = 0; mt < 2; mt++) {
                int row = wm + mt * 16 + (lane & 15);
                int koff = s * 16 + (lane >> 4) * 8;
                uint32_t ad = aBase + (uint32_t)(row * 40 + koff) * 2;
                ldsm_x4(aH[mt], ad);
                ldsm_x4(aL[mt], ad + 128 * 40 * 2);
            }
            {
                int krow = s * 16 + (lane & 7) + ((lane >> 3) & 1) * 8;
                int col = wn + (lane >> 4) * 8;
#pragma unroll
                for (int p = 0; p < 2; p++) {
                    uint32_t bd = vBase + (uint32_t)(krow * 72 + col + p * 16) * 2;
                    ldsm_x4_t(bF[p], bd);
                }
            }
#pragma unroll
            for (int mt = 0; mt < 2; mt++)
#pragma unroll
                for (int nt = 0; nt < 4; nt++) {
                    uint32_t b0 = bF[nt >> 1][(nt & 1) * 2];
                    uint32_t b1 = bF[nt >> 1][(nt & 1) * 2 + 1];
                    mma16816(acc[mt][nt], aH[mt], b0, b1);
                    mma16816(acc[mt][nt], aL[mt], b0, b1);
                }
            {
                int krow = s * 16 + (lane & 7) + ((lane >> 3) & 1) * 8;
                int col = wn + (lane >> 4) * 8;
#pragma unroll
                for (int p = 0; p < 2; p++) {
                    uint32_t bd = vBase + (uint32_t)(krow * 72 + col + p * 16) * 2 + 32 * 72 * 2;
                    ldsm_x4_t(bF[p], bd);
                }
            }
#pragma unroll
            for (int mt = 0; mt < 2; mt++)
#pragma unroll
                for (int nt = 0; nt < 4; nt++) {
                    uint32_t b0 = bF[nt >> 1][(nt & 1) * 2];
                    uint32_t b1 = bF[nt >> 1][(nt & 1) * 2 + 1];
                    mma16816(acc[mt][nt], aH[mt], b0, b1);
                }
        }
        __syncthreads();
    }

#pragma unroll
    for (int mt = 0; mt < 2; mt++)
#pragma unroll
        for (int nt = 0; nt < 4; nt++) {
            int c = wn + nt * 8 + (lane & 3) * 2;
#pragma unroll
            for (int half = 0; half < 2; half++) {
                int r = m0 + wm + mt * 16 + (lane >> 2) + half * 8;
                *(float2*)(ctx + ((size_t)(b * S + r) * NH + h) * HD + c) =
                    make_float2(acc[mt][nt][half * 2 + 0], acc[mt][nt][half * 2 + 1]);
            }
        }
}

// ---------------------------------------------------------------------------
extern "C" void kernel_launch(void* const* d_in, const int* in_sizes, int n_in,
                              void* d_out, int out_size) {
    const float* x    = (const float*)d_in[0];
    const int*   mask = (const int*)d_in[1];
    const float* Wq   = (const float*)d_in[2];
    const float* Wk   = (const float*)d_in[3];
    const float* Wv   = (const float*)d_in[4];
    const float* Wo   = (const float*)d_in[5];
    const float* bias = (const float*)d_in[6];

    float* out  = (float*)d_out;
    float* attn = out + (size_t)Bsz * S * H;

    float *tmp, *ctx;
    cudaGetSymbolAddress((void**)&tmp, g_tmp);
    cudaGetSymbolAddress((void**)&ctx, g_ctx);
    __nv_bfloat16 *xh, *xl, *ch, *cl, *wh, *wl;
    __nv_bfloat16 *qh, *ql, *kh, *kl, *vh, *vl;
    cudaGetSymbolAddress((void**)&xh, g_xh);
    cudaGetSymbolAddress((void**)&xl, g_xl);
    cudaGetSymbolAddress((void**)&ch, g_ch);
    cudaGetSymbolAddress((void**)&cl, g_cl);
    cudaGetSymbolAddress((void**)&wh, g_wh);
    cudaGetSymbolAddress((void**)&wl, g_wl);
    cudaGetSymbolAddress((void**)&qh, g_qh);
    cudaGetSymbolAddress((void**)&ql, g_ql);
    cudaGetSymbolAddress((void**)&kh, g_kh);
    cudaGetSymbolAddress((void**)&kl, g_kl);
    cudaGetSymbolAddress((void**)&vh, g_vh);
    cudaGetSymbolAddress((void**)&vl, g_vl);

    const int M = Bsz * S;                        // 4096
    const int MH = M * H;
    const int HH = H * H;
    const int rope_threads = Bsz * NH * S * 32;

    rope_table_kernel<<<(S * 32) / 256, 256>>>();
    split_kernel<<<MH / 4 / 256, 256>>>(x, xh, xl, MH);
    split_kernel<<<HH / 4 / 256, 256>>>(Wq, wh + 0 * HH, wl + 0 * HH, HH);
    split_kernel<<<HH / 4 / 256, 256>>>(Wk, wh + 1 * HH, wl + 1 * HH, HH);
    split_kernel<<<HH / 4 / 256, 256>>>(Wv, wh + 2 * HH, wl + 2 * HH, HH);
    split_kernel<<<HH / 4 / 256, 256>>>(Wo, wh + 3 * HH, wl + 3 * HH, HH);

    // Fused QKV projection: [M, 3H] = x @ [Wq;Wk;Wv]^T
    gemm_nt_split<<<dim3(3 * H / 64, M / 128), 256>>>(xh, xl, wh, wl, tmp, M, 3 * H, H);
    rope_qkv<<<rope_threads / 256, 256>>>(tmp, qh, ql, kh, kl, vh, vl);

    scores_mma<<<dim3(S / 128, S / 128, Bsz * NH), 256>>>(qh, ql, kh, kl, bias, mask, attn);
    softmax_kernel<<<Bsz * NH * S, 256>>>(attn);
    av_mma<<<dim3(S / 128, 1, Bsz * NH), 256>>>(attn, vh, vl, ctx);

    split_kernel<<<MH / 4 / 256, 256>>>(ctx, ch, cl, MH);
    gemm_nt_split<<<dim3(H / 64, M / 128), 256>>>(ch, cl, wh + 3 * HH, wl + 3 * HH, out, M, H, H);
}

// round 7
// speedup vs baseline: 2.8312x; 1.0162x over previous
#include <cuda_runtime.h>
#include <cuda_bf16.h>
#include <math.h>
#include <stdint.h>

#define Bsz 2
#define S 2048
#define H 1024
#define NH 16
#define HD 64

// Scratch (allocation-free rule: __device__ globals)
__device__ float g_tmp[Bsz * S * 3 * H];   // fused QKV projection output
__device__ float g_ctx[Bsz * S * H];
__device__ float g_cos[S * 32];
__device__ float g_sin[S * 32];
// split-bf16 buffers
__device__ __nv_bfloat16 g_xh[Bsz * S * H];
__device__ __nv_bfloat16 g_xl[Bsz * S * H];
__device__ __nv_bfloat16 g_ch[Bsz * S * H];
__device__ __nv_bfloat16 g_cl[Bsz * S * H];
__device__ __nv_bfloat16 g_wh[4 * H * H];   // Wq,Wk,Wv rows 0..3H; Wo at 3*HH
__device__ __nv_bfloat16 g_wl[4 * H * H];
__device__ __nv_bfloat16 g_qh[Bsz * S * H];
__device__ __nv_bfloat16 g_ql[Bsz * S * H];
__device__ __nv_bfloat16 g_kh[Bsz * S * H];
__device__ __nv_bfloat16 g_kl[Bsz * S * H];
__device__ __nv_bfloat16 g_vh[Bsz * S * H];
__device__ __nv_bfloat16 g_vl[Bsz * S * H];

// ---------------------------------------------------------------------------
// Fused: split x into hi/lo AND build the RoPE cos/sin table (double prec).
// ---------------------------------------------------------------------------
__global__ __launch_bounds__(256) void splitx_table(const float* __restrict__ src,
                                                    __nv_bfloat16* __restrict__ hi,
                                                    __nv_bfloat16* __restrict__ lo) {
    int idx = blockIdx.x * 256 + threadIdx.x;
    if (idx < S * 32) {
        int d = idx & 31;
        int s = idx >> 5;
        double inv = pow(10000.0, -(double)(2 * d) / 64.0);
        double ang = (double)s * inv;
        double sd, cd;
        sincos(ang, &sd, &cd);
        g_cos[idx] = (float)cd;
        g_sin[idx] = (float)sd;
    }
    int i = idx * 4;
    if (i >= Bsz * S * H) return;
    float4 v = *(const float4*)(src + i);
    __nv_bfloat16 h0 = __float2bfloat16(v.x);
    __nv_bfloat16 h1 = __float2bfloat16(v.y);
    __nv_bfloat16 h2 = __float2bfloat16(v.z);
    __nv_bfloat16 h3 = __float2bfloat16(v.w);
    *(__nv_bfloat162*)(hi + i)     = __halves2bfloat162(h0, h1);
    *(__nv_bfloat162*)(hi + i + 2) = __halves2bfloat162(h2, h3);
    *(__nv_bfloat162*)(lo + i)     = __halves2bfloat162(__float2bfloat16(v.x - __bfloat162float(h0)),
                                                        __float2bfloat16(v.y - __bfloat162float(h1)));
    *(__nv_bfloat162*)(lo + i + 2) = __halves2bfloat162(__float2bfloat16(v.z - __bfloat162float(h2)),
                                                        __float2bfloat16(v.w - __bfloat162float(h3)));
}

// ---------------------------------------------------------------------------
// Split all four weight matrices in one launch. blockIdx.y selects matrix.
// ---------------------------------------------------------------------------
__global__ __launch_bounds__(256) void split_w4(const float* __restrict__ w0,
                                                const float* __restrict__ w1,
                                                const float* __restrict__ w2,
                                                const float* __restrict__ w3,
                                                __nv_bfloat16* __restrict__ hi,
                                                __nv_bfloat16* __restrict__ lo) {
    const int HH = H * H;
    int y = blockIdx.y;
    const float* src = (y == 0) ? w0 : (y == 1) ? w1 : (y == 2) ? w2 : w3;
    int i = (blockIdx.x * 256 + threadIdx.x) * 4;
    if (i >= HH) return;
    float4 v = *(const float4*)(src + i);
    __nv_bfloat16* hp = hi + (size_t)y * HH;
    __nv_bfloat16* lp = lo + (size_t)y * HH;
    __nv_bfloat16 h0 = __float2bfloat16(v.x);
    __nv_bfloat16 h1 = __float2bfloat16(v.y);
    __nv_bfloat16 h2 = __float2bfloat16(v.z);
    __nv_bfloat16 h3 = __float2bfloat16(v.w);
    *(__nv_bfloat162*)(hp + i)     = __halves2bfloat162(h0, h1);
    *(__nv_bfloat162*)(hp + i + 2) = __halves2bfloat162(h2, h3);
    *(__nv_bfloat162*)(lp + i)     = __halves2bfloat162(__float2bfloat16(v.x - __bfloat162float(h0)),
                                                        __float2bfloat16(v.y - __bfloat162float(h1)));
    *(__nv_bfloat162*)(lp + i + 2) = __halves2bfloat162(__float2bfloat16(v.z - __bfloat162float(h2)),
                                                        __float2bfloat16(v.w - __bfloat162float(h3)));
}

// ---------------------------------------------------------------------------
// Plain split (for ctx before the output projection).
// ---------------------------------------------------------------------------
__global__ __launch_bounds__(256) void split_kernel(const float* __restrict__ src,
                                                    __nv_bfloat16* __restrict__ hi,
                                                    __nv_bfloat16* __restrict__ lo,
                                                    int n) {
    int i = (blockIdx.x * 256 + threadIdx.x) * 4;
    if (i >= n) return;
    float4 v = *(const float4*)(src + i);
    __nv_bfloat16 h0 = __float2bfloat16(v.x);
    __nv_bfloat16 h1 = __float2bfloat16(v.y);
    __nv_bfloat16 h2 = __float2bfloat16(v.z);
    __nv_bfloat16 h3 = __float2bfloat16(v.w);
    *(__nv_bfloat162*)(hi + i)     = __halves2bfloat162(h0, h1);
    *(__nv_bfloat162*)(hi + i + 2) = __halves2bfloat162(h2, h3);
    *(__nv_bfloat162*)(lo + i)     = __halves2bfloat162(__float2bfloat16(v.x - __bfloat162float(h0)),
                                                        __float2bfloat16(v.y - __bfloat162float(h1)));
    *(__nv_bfloat162*)(lo + i + 2) = __halves2bfloat162(__float2bfloat16(v.z - __bfloat162float(h2)),
                                                        __float2bfloat16(v.w - __bfloat162float(h3)));
}

// ---------------------------------------------------------------------------
// MMA / async-copy helpers
// ---------------------------------------------------------------------------
__device__ __forceinline__ void ldsm_x4(uint32_t (&r)[4], uint32_t addr) {
    asm volatile("ldmatrix.sync.aligned.m8n8.x4.shared.b16 {%0,%1,%2,%3}, [%4];"
                 : "=r"(r[0]), "=r"(r[1]), "=r"(r[2]), "=r"(r[3]) : "r"(addr));
}
__device__ __forceinline__ void ldsm_x4_t(uint32_t (&r)[4], uint32_t addr) {
    asm volatile("ldmatrix.sync.aligned.m8n8.x4.trans.shared.b16 {%0,%1,%2,%3}, [%4];"
                 : "=r"(r[0]), "=r"(r[1]), "=r"(r[2]), "=r"(r[3]) : "r"(addr));
}
__device__ __forceinline__ void mma16816(float (&c)[4], const uint32_t (&a)[4],
                                         uint32_t b0, uint32_t b1) {
    asm volatile(
        "mma.sync.aligned.m16n8k16.row.col.f32.bf16.bf16.f32 "
        "{%0,%1,%2,%3}, {%4,%5,%6,%7}, {%8,%9}, {%0,%1,%2,%3};"
        : "+f"(c[0]), "+f"(c[1]), "+f"(c[2]), "+f"(c[3])
        : "r"(a[0]), "r"(a[1]), "r"(a[2]), "r"(a[3]), "r"(b0), "r"(b1));
}
__device__ __forceinline__ void cp16(uint32_t smem, const void* g) {
    asm volatile("cp.async.ca.shared.global [%0], [%1], 16;" :: "r"(smem), "l"(g));
}
__device__ __forceinline__ uint32_t packbf2(__nv_bfloat16 a, __nv_bfloat16 b) {
    __nv_bfloat162 t = __halves2bfloat162(a, b);
    return *(uint32_t*)&t;
}

// ---------------------------------------------------------------------------
// Split-bf16 GEMM: C[M,N] = A[M,K] @ B[N,K]^T.
// 128x128 block tile, warp tile 32x64, 2-stage cp.async, k32 steps.
// ---------------------------------------------------------------------------
__global__ __launch_bounds__(256, 2) void gemm_nt_split(
    const __nv_bfloat16* __restrict__ Ah, const __nv_bfloat16* __restrict__ Al,
    const __nv_bfloat16* __restrict__ Bh, const __nv_bfloat16* __restrict__ Bl,
    float* __restrict__ C, int M, int N, int K) {
    __shared__ __align__(16) __nv_bfloat16 sA[2][2][128][40];  // [stage][hi/lo]
    __shared__ __align__(16) __nv_bfloat16 sB[2][2][128][40];

    const int tid = threadIdx.x;
    const int wid = tid >> 5, lane = tid & 31;
    const int wm = (wid & 3) * 32;
    const int wn = (wid >> 2) * 64;
    const int m0 = blockIdx.y * 128, n0 = blockIdx.x * 128;
    const int KSTEPS = K >> 5;

    float acc[2][8][4] = {};
    const uint32_t aBase = (uint32_t)__cvta_generic_to_shared(&sA[0][0][0][0]);
    const uint32_t bBase = (uint32_t)__cvta_generic_to_shared(&sB[0][0][0][0]);
    const uint32_t STG_A = 2 * 128 * 40 * 2;   // bytes per stage (hi+lo)

    auto load_stage = [&](int st, int kg) {
#pragma unroll
        for (int i = 0; i < 2; i++) {
            int c = tid + i * 256;
            int row = c >> 2, kc = (c & 3) * 8;
            uint32_t off = (uint32_t)(row * 40 + kc) * 2;
            cp16(aBase + st * STG_A + off, Ah + (size_t)(m0 + row) * K + kg + kc);
            cp16(aBase + st * STG_A + 128 * 40 * 2 + off, Al + (size_t)(m0 + row) * K + kg + kc);
            cp16(bBase + st * STG_A + off, Bh + (size_t)(n0 + row) * K + kg + kc);
            cp16(bBase + st * STG_A + 128 * 40 * 2 + off, Bl + (size_t)(n0 + row) * K + kg + kc);
        }
        asm volatile("cp.async.commit_group;");
    };

    load_stage(0, 0);

    int st = 0;
    for (int kidx = 0; kidx < KSTEPS; kidx++) {
        if (kidx + 1 < KSTEPS) {
            load_stage(st ^ 1, (kidx + 1) * 32);
            asm volatile("cp.async.wait_group 1;");
        } else {
            asm volatile("cp.async.wait_group 0;");
        }
        __syncthreads();

        uint32_t aST = aBase + st * STG_A;
        uint32_t bST = bBase + st * STG_A;

#pragma unroll
        for (int s = 0; s < 2; s++) {
            uint32_t aH[2][4], aL[2][4], bF[4][4];
#pragma unroll
            for (int mt = 0; mt < 2; mt++) {
                int row = wm + mt * 16 + (lane & 15);
                int koff = s * 16 + (lane >> 4) * 8;
                uint32_t ad = aST + (uint32_t)(row * 40 + koff) * 2;
                ldsm_x4(aH[mt], ad);
                ldsm_x4(aL[mt], ad + 128 * 40 * 2);
            }
            {
                int rowp = wn + ((lane >> 4) & 1) * 8 + (lane & 7);
                int koff = s * 16 + ((lane >> 3) & 1) * 8;
#pragma unroll
                for (int p = 0; p < 4; p++)
                    ldsm_x4(bF[p], bST + (uint32_t)((rowp + p * 16) * 40 + koff) * 2);
            }
#pragma unroll
            for (int mt = 0; mt < 2; mt++)
#pragma unroll
                for (int nt = 0; nt < 8; nt++) {
                    uint32_t b0 = bF[nt >> 1][(nt & 1) * 2];
                    uint32_t b1 = bF[nt >> 1][(nt & 1) * 2 + 1];
                    mma16816(acc[mt][nt], aH[mt], b0, b1);   // hi*hi
                    mma16816(acc[mt][nt], aL[mt], b0, b1);   // lo*hi
                }
            {
                int rowp = wn + ((lane >> 4) & 1) * 8 + (lane & 7);
                int koff = s * 16 + ((lane >> 3) & 1) * 8;
#pragma unroll
                for (int p = 0; p < 4; p++)
                    ldsm_x4(bF[p], bST + (uint32_t)(128 * 40 + (rowp + p * 16) * 40 + koff) * 2);
            }
#pragma unroll
            for (int mt = 0; mt < 2; mt++)
#pragma unroll
                for (int nt = 0; nt < 8; nt++) {
                    uint32_t b0 = bF[nt >> 1][(nt & 1) * 2];
                    uint32_t b1 = bF[nt >> 1][(nt & 1) * 2 + 1];
                    mma16816(acc[mt][nt], aH[mt], b0, b1);   // hi*lo
                }
        }
        __syncthreads();
        st ^= 1;
    }

#pragma unroll
    for (int mt = 0; mt < 2; mt++)
#pragma unroll
        for (int nt = 0; nt < 8; nt++) {
            int r = m0 + wm + mt * 16 + (lane >> 2);
            int cc = n0 + wn + nt * 8 + (lane & 3) * 2;
            *(float2*)(C + (size_t)r * N + cc) = make_float2(acc[mt][nt][0], acc[mt][nt][1]);
            *(float2*)(C + (size_t)(r + 8) * N + cc) = make_float2(acc[mt][nt][2], acc[mt][nt][3]);
        }
}

// ---------------------------------------------------------------------------
// Fused rope+split for QKV: tmp [B,S,3H] -> qh/ql,kh/kl (rope), vh/vl.
// ---------------------------------------------------------------------------
__global__ __launch_bounds__(256) void rope_qkv(const float* __restrict__ tmp,
                                                __nv_bfloat16* __restrict__ qh,
                                                __nv_bfloat16* __restrict__ ql,
                                                __nv_bfloat16* __restrict__ kh,
                                                __nv_bfloat16* __restrict__ kl,
                                                __nv_bfloat16* __restrict__ vh,
                                                __nv_bfloat16* __restrict__ vl) {
    int idx = blockIdx.x * blockDim.x + threadIdx.x;
    if (idx >= Bsz * NH * S * 32) return;
    int d = idx & 31;
    int s = (idx >> 5) & (S - 1);
    int h = (idx >> 16) & (NH - 1);
    int b = idx >> 20;

    const float* p = tmp + (size_t)(b * S + s) * (3 * H) + h * HD;
    float q0 = p[d], q1 = p[d + 32];
    float k0 = p[H + d], k1 = p[H + d + 32];
    float v0 = p[2 * H + d], v1 = p[2 * H + d + 32];

    float c = g_cos[s * 32 + d];
    float sn = g_sin[s * 32 + d];
    float nq0 = q0 * c - q1 * sn, nq1 = q1 * c + q0 * sn;
    float nk0 = k0 * c - k1 * sn, nk1 = k1 * c + k0 * sn;

    size_t o = ((size_t)(b * NH + h) * S + s) * HD;
    __nv_bfloat16 t;
    t = __float2bfloat16(nq0); qh[o + d] = t;      ql[o + d] = __float2bfloat16(nq0 - __bfloat162float(t));
    t = __float2bfloat16(nq1); qh[o + d + 32] = t; ql[o + d + 32] = __float2bfloat16(nq1 - __bfloat162float(t));
    t = __float2bfloat16(nk0); kh[o + d] = t;      kl[o + d] = __float2bfloat16(nk0 - __bfloat162float(t));
    t = __float2bfloat16(nk1); kh[o + d + 32] = t; kl[o + d + 32] = __float2bfloat16(nk1 - __bfloat162float(t));
    t = __float2bfloat16(v0);  vh[o + d] = t;      vl[o + d] = __float2bfloat16(v0 - __bfloat162float(t));
    t = __float2bfloat16(v1);  vh[o + d + 32] = t; vl[o + d + 32] = __float2bfloat16(v1 - __bfloat162float(t));
}

// ---------------------------------------------------------------------------
// Tensor-core scores: attn_raw = (Q K^T)/8 + bias, pad-mask -> -1e30.
// ---------------------------------------------------------------------------
__global__ __launch_bounds__(256) void scores_mma(
    const __nv_bfloat16* __restrict__ Qh, const __nv_bfloat16* __restrict__ Ql,
    const __nv_bfloat16* __restrict__ Kh, const __nv_bfloat16* __restrict__ Kl,
    const float* __restrict__ bias, const int* __restrict__ mask,
    float* __restrict__ attn) {
    const int bh = blockIdx.z;
    const int b = bh >> 4;
    const int m0 = blockIdx.y * 128;
    const int n0 = blockIdx.x * 128;
    if (n0 > m0 + 127) return;

    __shared__ __align__(16) __nv_bfloat16 sQ[2][128][40];
    __shared__ __align__(16) __nv_bfloat16 sK[2][128][40];

    const int tid = threadIdx.x;
    const int wid = tid >> 5, lane = tid & 31;
    const int wm = (wid & 3) * 32;
    const int wn = (wid >> 2) * 64;
    const __nv_bfloat16* Qhb = Qh + (size_t)bh * S * HD;
    const __nv_bfloat16* Qlb = Ql + (size_t)bh * S * HD;
    const __nv_bfloat16* Khb = Kh + (size_t)bh * S * HD;
    const __nv_bfloat16* Klb = Kl + (size_t)bh * S * HD;

    float acc[2][8][4] = {};
    const uint32_t qBase = (uint32_t)__cvta_generic_to_shared(&sQ[0][0][0]);
    const uint32_t kBase = (uint32_t)__cvta_generic_to_shared(&sK[0][0][0]);

    for (int kk = 0; kk < HD; kk += 32) {
#pragma unroll
        for (int i = 0; i < 2; i++) {
            int c = tid + i * 256;
            int row = c >> 2, kc = (c & 3) * 8;
            *(uint4*)&sQ[0][row][kc] = *(const uint4*)(Qhb + (size_t)(m0 + row) * HD + kk + kc);
            *(uint4*)&sQ[1][row][kc] = *(const uint4*)(Qlb + (size_t)(m0 + row) * HD + kk + kc);
            *(uint4*)&sK[0][row][kc] = *(const uint4*)(Khb + (size_t)(n0 + row) * HD + kk + kc);
            *(uint4*)&sK[1][row][kc] = *(const uint4*)(Klb + (size_t)(n0 + row) * HD + kk + kc);
        }
        __syncthreads();

#pragma unroll
        for (int s = 0; s < 2; s++) {
            uint32_t aH[2][4], aL[2][4], bF[4][4];
#pragma unroll
            for (int mt = 0; mt < 2; mt++) {
                int row = wm + mt * 16 + (lane & 15);
                int koff = s * 16 + (lane >> 4) * 8;
                uint32_t ad = qBase + (uint32_t)(row * 40 + koff) * 2;
                ldsm_x4(aH[mt], ad);
                ldsm_x4(aL[mt], ad + 128 * 40 * 2);
            }
            {
                int rowp = wn + ((lane >> 4) & 1) * 8 + (lane & 7);
                int koff = s * 16 + ((lane >> 3) & 1) * 8;
#pragma unroll
                for (int p = 0; p < 4; p++) {
                    uint32_t bd = kBase + (uint32_t)((rowp + p * 16) * 40 + koff) * 2;
                    ldsm_x4(bF[p], bd);
                }
            }
#pragma unroll
            for (int mt = 0; mt < 2; mt++)
#pragma unroll
                for (int nt = 0; nt < 8; nt++) {
                    uint32_t b0 = bF[nt >> 1][(nt & 1) * 2];
                    uint32_t b1 = bF[nt >> 1][(nt & 1) * 2 + 1];
                    mma16816(acc[mt][nt], aH[mt], b0, b1);   // hi*hi
                    mma16816(acc[mt][nt], aL[mt], b0, b1);   // lo*hi
                }
            {
                int rowp = wn + ((lane >> 4) & 1) * 8 + (lane & 7);
                int koff = s * 16 + ((lane >> 3) & 1) * 8;
#pragma unroll
                for (int p = 0; p < 4; p++) {
                    uint32_t bd = kBase + (uint32_t)((rowp + p * 16) * 40 + koff) * 2 + 128 * 40 * 2;
                    ldsm_x4(bF[p], bd);
                }
            }
#pragma unroll
            for (int mt = 0; mt < 2; mt++)
#pragma unroll
                for (int nt = 0; nt < 8; nt++) {
                    uint32_t b0 = bF[nt >> 1][(nt & 1) * 2];
                    uint32_t b1 = bF[nt >> 1][(nt & 1) * 2 + 1];
                    mma16816(acc[mt][nt], aH[mt], b0, b1);   // hi*lo
                }
        }
        __syncthreads();
    }

#pragma unroll
    for (int mt = 0; mt < 2; mt++)
#pragma unroll
        for (int nt = 0; nt < 8; nt++) {
            int c = n0 + wn + nt * 8 + (lane & 3) * 2;
            int mk0 = mask[b * S + c];
            int mk1 = mask[b * S + c + 1];
#pragma unroll
            for (int half = 0; half < 2; half++) {
                int r = m0 + wm + mt * 16 + (lane >> 2) + half * 8;
                const float* brow = bias + (size_t)r * S;
                float v0 = acc[mt][nt][half * 2 + 0] * 0.125f + brow[c];
                float v1 = acc[mt][nt][half * 2 + 1] * 0.125f + brow[c + 1];
                if (mk0 == 0) v0 = -1e30f;
                if (mk1 == 0) v1 = -1e30f;
                *(float2*)(attn + ((size_t)bh * S + r) * S + c) = make_float2(v0, v1);
            }
        }
}

// ---------------------------------------------------------------------------
// Row-wise causal softmax: 512 threads, one float4 per thread, all in regs.
// ---------------------------------------------------------------------------
__global__ __launch_bounds__(512) void softmax_kernel(float* __restrict__ attn) {
    __shared__ float red[16];
    const int row = blockIdx.x;
    const int q = row & (S - 1);
    const int n = q + 1;
    float* a = attn + (size_t)row * S;
    const int tid = threadIdx.x;
    const int base = tid * 4;

    float4 v;
    if (base < n) v = *(const float4*)(a + base);
    else v = make_float4(-3e38f, -3e38f, -3e38f, -3e38f);
    // mask tail elements within the float4
    if (base + 1 >= n) v.y = -3e38f;
    if (base + 2 >= n) v.z = -3e38f;
    if (base + 3 >= n) v.w = -3e38f;
    if (base >= n) v.x = -3e38f;

    float m = fmaxf(fmaxf(v.x, v.y), fmaxf(v.z, v.w));
#pragma unroll
    for (int o = 16; o; o >>= 1) m = fmaxf(m, __shfl_xor_sync(0xffffffffu, m, o));
    if ((tid & 31) == 0) red[tid >> 5] = m;
    __syncthreads();
    m = red[0];
#pragma unroll
    for (int w = 1; w < 16; w++) m = fmaxf(m, red[w]);
    __syncthreads();

    float4 e;
    e.x = (base + 0 < n) ? __expf(v.x - m) : 0.f;
    e.y = (base + 1 < n) ? __expf(v.y - m) : 0.f;
    e.z = (base + 2 < n) ? __expf(v.z - m) : 0.f;
    e.w = (base + 3 < n) ? __expf(v.w - m) : 0.f;
    float ssum = e.x + e.y + e.z + e.w;
#pragma unroll
    for (int o = 16; o; o >>= 1) ssum += __shfl_xor_sync(0xffffffffu, ssum, o);
    if ((tid & 31) == 0) red[tid >> 5] = ssum;
    __syncthreads();
    ssum = 0.f;
#pragma unroll
    for (int w = 0; w < 16; w++) ssum += red[w];

    float inv = 1.f / ssum;
    e.x *= inv; e.y *= inv; e.z *= inv; e.w *= inv;
    *(float4*)(a + base) = e;
}

// ---------------------------------------------------------------------------
// Tensor-core AV reading fp32 attn (split to bf16 hi/lo in registers).
// ---------------------------------------------------------------------------
__global__ __launch_bounds__(256) void av_mma(
    const float* __restrict__ attn,
    const __nv_bfloat16* __restrict__ Vh, const __nv_bfloat16* __restrict__ Vl,
    float* __restrict__ ctx) {
    const int bh = blockIdx.z;
    const int b = bh >> 4;
    const int h = bh & 15;
    const int m0 = blockIdx.x * 128;

    __shared__ __align__(16) __nv_bfloat16 sA[2][128][40];
    __shared__ __align__(16) __nv_bfloat16 sV[2][32][72];

    const int tid = threadIdx.x;
    const int wid = tid >> 5, lane = tid & 31;
    const int wm = (wid & 3) * 32;
    const int wn = (wid >> 2) * 32;
    const float* Ab = attn + (size_t)bh * S * S;
    const __nv_bfloat16* Vhb = Vh + (size_t)bh * S * HD;
    const __nv_bfloat16* Vlb = Vl + (size_t)bh * S * HD;

    float acc[2][4][4] = {};
    const uint32_t aBase = (uint32_t)__cvta_generic_to_shared(&sA[0][0][0]);
    const uint32_t vBase = (uint32_t)__cvta_generic_to_shared(&sV[0][0][0]);

    const int arow = tid >> 1;
    const int akc = (tid & 1) * 16;

    const int kmax = m0 + 128;
    for (int k0 = 0; k0 < kmax; k0 += 32) {
        {
            const float* src = Ab + (size_t)(m0 + arow) * S + k0 + akc;
            float4 f0 = *(const float4*)(src + 0);
            float4 f1 = *(const float4*)(src + 4);
            float4 f2 = *(const float4*)(src + 8);
            float4 f3 = *(const float4*)(src + 12);
            float v[16] = {f0.x, f0.y, f0.z, f0.w, f1.x, f1.y, f1.z, f1.w,
                           f2.x, f2.y, f2.z, f2.w, f3.x, f3.y, f3.z, f3.w};
            uint32_t hw[8], lw[8];
#pragma unroll
            for (int i = 0; i < 8; i++) {
                float a0 = v[2 * i], a1 = v[2 * i + 1];
                __nv_bfloat16 h0 = __float2bfloat16(a0);
                __nv_bfloat16 h1 = __float2bfloat16(a1);
                hw[i] = packbf2(h0, h1);
                lw[i] = packbf2(__float2bfloat16(a0 - __bfloat162float(h0)),
                                __float2bfloat16(a1 - __bfloat162float(h1)));
            }
            *(uint4*)&sA[0][arow][akc]     = make_uint4(hw[0], hw[1], hw[2], hw[3]);
            *(uint4*)&sA[0][arow][akc + 8] = make_uint4(hw[4], hw[5], hw[6], hw[7]);
            *(uint4*)&sA[1][arow][akc]     = make_uint4(lw[0], lw[1], lw[2], lw[3]);
            *(uint4*)&sA[1][arow][akc + 8] = make_uint4(lw[4], lw[5], lw[6], lw[7]);
        }
        {
            int row = tid >> 3, col = (tid & 7) * 8;
            *(uint4*)&sV[0][row][col] = *(const uint4*)(Vhb + (size_t)(k0 + row) * HD + col);
            *(uint4*)&sV[1][row][col] = *(const uint4*)(Vlb + (size_t)(k0 + row) * HD + col);
        }
        __syncthreads();

#pragma unroll
        for (int s = 0; s < 2; s++) {
            uint32_t aH[2][4], aL[2][4], bF[2][4];
#pragma unroll
            for (int mt = 0; mt < 2; mt++) {
                int row = wm + mt * 16 + (lane & 15);
                int koff = s * 16 + (lane >> 4) * 8;
                uint32_t ad = aBase + (uint32_t)(row * 40 + koff) * 2;
                ldsm_x4(aH[mt], ad);
                ldsm_x4(aL[mt], ad + 128 * 40 * 2);
            }
            {
                int krow = s * 16 + (lane & 7) + ((lane >> 3) & 1) * 8;
                int col = wn + (lane >> 4) * 8;
#pragma unroll
                for (int p = 0; p < 2; p++) {
                    uint32_t bd = vBase + (uint32_t)(krow * 72 + col + p * 16) * 2;
                    ldsm_x4_t(bF[p], bd);
                }
            }
#pragma unroll
            for (int mt = 0; mt < 2; mt++)
#pragma unroll
                for (int nt = 0; nt < 4; nt++) {
                    uint32_t b0 = bF[nt >> 1][(nt & 1) * 2];
                    uint32_t b1 = bF[nt >> 1][(nt & 1) * 2 + 1];
                    mma16816(acc[mt][nt], aH[mt], b0, b1);
                    mma16816(acc[mt][nt], aL[mt], b0, b1);
                }
            {
                int krow = s * 16 + (lane & 7) + ((lane >> 3) & 1) * 8;
                int col = wn + (lane >> 4) * 8;
#pragma unroll
                for (int p = 0; p < 2; p++) {
                    uint32_t bd = vBase + (uint32_t)(krow * 72 + col + p * 16) * 2 + 32 * 72 * 2;
                    ldsm_x4_t(bF[p], bd);
                }
            }
#pragma unroll
            for (int mt = 0; mt < 2; mt++)
#pragma unroll
                for (int nt = 0; nt < 4; nt++) {
                    uint32_t b0 = bF[nt >> 1][(nt & 1) * 2];
                    uint32_t b1 = bF[nt >> 1][(nt & 1) * 2 + 1];
                    mma16816(acc[mt][nt], aH[mt], b0, b1);
                }
        }
        __syncthreads();
    }

#pragma unroll
    for (int mt = 0; mt < 2; mt++)
#pragma unroll
        for (int nt = 0; nt < 4; nt++) {
            int c = wn + nt * 8 + (lane & 3) * 2;
#pragma unroll
            for (int half = 0; half < 2; half++) {
                int r = m0 + wm + mt * 16 + (lane >> 2) + half * 8;
                *(float2*)(ctx + ((size_t)(b * S + r) * NH + h) * HD + c) =
                    make_float2(acc[mt][nt][half * 2 + 0], acc[mt][nt][half * 2 + 1]);
            }
        }
}

// ---------------------------------------------------------------------------
extern "C" void kernel_launch(void* const* d_in, const int* in_sizes, int n_in,
                              void* d_out, int out_size) {
    const float* x    = (const float*)d_in[0];
    const int*   mask = (const int*)d_in[1];
    const float* Wq   = (const float*)d_in[2];
    const float* Wk   = (const float*)d_in[3];
    const float* Wv   = (const float*)d_in[4];
    const float* Wo   = (const float*)d_in[5];
    const float* bias = (const float*)d_in[6];

    float* out  = (float*)d_out;
    float* attn = out + (size_t)Bsz * S * H;

    float *tmp, *ctx;
    cudaGetSymbolAddress((void**)&tmp, g_tmp);
    cudaGetSymbolAddress((void**)&ctx, g_ctx);
    __nv_bfloat16 *xh, *xl, *ch, *cl, *wh, *wl;
    __nv_bfloat16 *qh, *ql, *kh, *kl, *vh, *vl;
    cudaGetSymbolAddress((void**)&xh, g_xh);
    cudaGetSymbolAddress((void**)&xl, g_xl);
    cudaGetSymbolAddress((void**)&ch, g_ch);
    cudaGetSymbolAddress((void**)&cl, g_cl);
    cudaGetSymbolAddress((void**)&wh, g_wh);
    cudaGetSymbolAddress((void**)&wl, g_wl);
    cudaGetSymbolAddress((void**)&qh, g_qh);
    cudaGetSymbolAddress((void**)&ql, g_ql);
    cudaGetSymbolAddress((void**)&kh, g_kh);
    cudaGetSymbolAddress((void**)&kl, g_kl);
    cudaGetSymbolAddress((void**)&vh, g_vh);
    cudaGetSymbolAddress((void**)&vl, g_vl);

    const int M = Bsz * S;                        // 4096
    const int MH = M * H;
    const int HH = H * H;
    const int rope_threads = Bsz * NH * S * 32;

    // Launch order arranged so ncu (-s 5 -c 1) captures softmax (6th launch).
    splitx_table<<<MH / 4 / 256, 256>>>(x, xh, xl);                            // 1
    split_w4<<<dim3(HH / 4 / 256, 4), 256>>>(Wq, Wk, Wv, Wo, wh, wl);          // 2
    gemm_nt_split<<<dim3(3 * H / 128, M / 128), 256>>>(xh, xl, wh, wl, tmp,
                                                       M, 3 * H, H);           // 3
    rope_qkv<<<rope_threads / 256, 256>>>(tmp, qh, ql, kh, kl, vh, vl);        // 4
    scores_mma<<<dim3(S / 128, S / 128, Bsz * NH), 256>>>(qh, ql, kh, kl,
                                                          bias, mask, attn);   // 5
    softmax_kernel<<<Bsz * NH * S, 512>>>(attn);                               // 6 <- profiled
    av_mma<<<dim3(S / 128, 1, Bsz * NH), 256>>>(attn, vh, vl, ctx);            // 7
    split_kernel<<<MH / 4 / 256, 256>>>(ctx, ch, cl, MH);                      // 8
    gemm_nt_split<<<dim3(H / 128, M / 128), 256>>>(ch, cl, wh + 3 * HH,
                                                   wl + 3 * HH, out, M, H, H); // 9
}

// round 8
// speedup vs baseline: 3.3140x; 1.1705x over previous
#include <cuda_runtime.h>
#include <cuda_bf16.h>
#include <math.h>
#include <stdint.h>

#define Bsz 2
#define S 2048
#define H 1024
#define NH 16
#define HD 64

// Scratch (allocation-free rule: __device__ globals)
__device__ float g_tmp[Bsz * S * 3 * H];   // fused QKV projection output
__device__ float g_ctx[Bsz * S * H];
__device__ float g_cos[S * 32];
__device__ float g_sin[S * 32];
// split-bf16 buffers
__device__ __nv_bfloat16 g_xh[Bsz * S * H];
__device__ __nv_bfloat16 g_xl[Bsz * S * H];
__device__ __nv_bfloat16 g_ch[Bsz * S * H];
__device__ __nv_bfloat16 g_cl[Bsz * S * H];
__device__ __nv_bfloat16 g_wh[4 * H * H];   // Wq,Wk,Wv rows 0..3H; Wo at 3*HH
__device__ __nv_bfloat16 g_wl[4 * H * H];
__device__ __nv_bfloat16 g_qh[Bsz * S * H];
__device__ __nv_bfloat16 g_ql[Bsz * S * H];
__device__ __nv_bfloat16 g_kh[Bsz * S * H];
__device__ __nv_bfloat16 g_kl[Bsz * S * H];
__device__ __nv_bfloat16 g_vh[Bsz * S * H];
__device__ __nv_bfloat16 g_vl[Bsz * S * H];

// ---------------------------------------------------------------------------
// Fused: split x into hi/lo AND build the RoPE cos/sin table (double prec).
// ---------------------------------------------------------------------------
__global__ __launch_bounds__(256) void splitx_table(const float* __restrict__ src,
                                                    __nv_bfloat16* __restrict__ hi,
                                                    __nv_bfloat16* __restrict__ lo) {
    int idx = blockIdx.x * 256 + threadIdx.x;
    if (idx < S * 32) {
        int d = idx & 31;
        int s = idx >> 5;
        double inv = pow(10000.0, -(double)(2 * d) / 64.0);
        double ang = (double)s * inv;
        double sd, cd;
        sincos(ang, &sd, &cd);
        g_cos[idx] = (float)cd;
        g_sin[idx] = (float)sd;
    }
    int i = idx * 4;
    if (i >= Bsz * S * H) return;
    float4 v = *(const float4*)(src + i);
    __nv_bfloat16 h0 = __float2bfloat16(v.x);
    __nv_bfloat16 h1 = __float2bfloat16(v.y);
    __nv_bfloat16 h2 = __float2bfloat16(v.z);
    __nv_bfloat16 h3 = __float2bfloat16(v.w);
    *(__nv_bfloat162*)(hi + i)     = __halves2bfloat162(h0, h1);
    *(__nv_bfloat162*)(hi + i + 2) = __halves2bfloat162(h2, h3);
    *(__nv_bfloat162*)(lo + i)     = __halves2bfloat162(__float2bfloat16(v.x - __bfloat162float(h0)),
                                                        __float2bfloat16(v.y - __bfloat162float(h1)));
    *(__nv_bfloat162*)(lo + i + 2) = __halves2bfloat162(__float2bfloat16(v.z - __bfloat162float(h2)),
                                                        __float2bfloat16(v.w - __bfloat162float(h3)));
}

// ---------------------------------------------------------------------------
__global__ __launch_bounds__(256) void split_w4(const float* __restrict__ w0,
                                                const float* __restrict__ w1,
                                                const float* __restrict__ w2,
                                                const float* __restrict__ w3,
                                                __nv_bfloat16* __restrict__ hi,
                                                __nv_bfloat16* __restrict__ lo) {
    const int HH = H * H;
    int y = blockIdx.y;
    const float* src = (y == 0) ? w0 : (y == 1) ? w1 : (y == 2) ? w2 : w3;
    int i = (blockIdx.x * 256 + threadIdx.x) * 4;
    if (i >= HH) return;
    float4 v = *(const float4*)(src + i);
    __nv_bfloat16* hp = hi + (size_t)y * HH;
    __nv_bfloat16* lp = lo + (size_t)y * HH;
    __nv_bfloat16 h0 = __float2bfloat16(v.x);
    __nv_bfloat16 h1 = __float2bfloat16(v.y);
    __nv_bfloat16 h2 = __float2bfloat16(v.z);
    __nv_bfloat16 h3 = __float2bfloat16(v.w);
    *(__nv_bfloat162*)(hp + i)     = __halves2bfloat162(h0, h1);
    *(__nv_bfloat162*)(hp + i + 2) = __halves2bfloat162(h2, h3);
    *(__nv_bfloat162*)(lp + i)     = __halves2bfloat162(__float2bfloat16(v.x - __bfloat162float(h0)),
                                                        __float2bfloat16(v.y - __bfloat162float(h1)));
    *(__nv_bfloat162*)(lp + i + 2) = __halves2bfloat162(__float2bfloat16(v.z - __bfloat162float(h2)),
                                                        __float2bfloat16(v.w - __bfloat162float(h3)));
}

// ---------------------------------------------------------------------------
__global__ __launch_bounds__(256) void split_kernel(const float* __restrict__ src,
                                                    __nv_bfloat16* __restrict__ hi,
                                                    __nv_bfloat16* __restrict__ lo,
                                                    int n) {
    int i = (blockIdx.x * 256 + threadIdx.x) * 4;
    if (i >= n) return;
    float4 v = *(const float4*)(src + i);
    __nv_bfloat16 h0 = __float2bfloat16(v.x);
    __nv_bfloat16 h1 = __float2bfloat16(v.y);
    __nv_bfloat16 h2 = __float2bfloat16(v.z);
    __nv_bfloat16 h3 = __float2bfloat16(v.w);
    *(__nv_bfloat162*)(hi + i)     = __halves2bfloat162(h0, h1);
    *(__nv_bfloat162*)(hi + i + 2) = __halves2bfloat162(h2, h3);
    *(__nv_bfloat162*)(lo + i)     = __halves2bfloat162(__float2bfloat16(v.x - __bfloat162float(h0)),
                                                        __float2bfloat16(v.y - __bfloat162float(h1)));
    *(__nv_bfloat162*)(lo + i + 2) = __halves2bfloat162(__float2bfloat16(v.z - __bfloat162float(h2)),
                                                        __float2bfloat16(v.w - __bfloat162float(h3)));
}

// ---------------------------------------------------------------------------
// MMA / async-copy helpers
// ---------------------------------------------------------------------------
__device__ __forceinline__ void ldsm_x4(uint32_t (&r)[4], uint32_t addr) {
    asm volatile("ldmatrix.sync.aligned.m8n8.x4.shared.b16 {%0,%1,%2,%3}, [%4];"
                 : "=r"(r[0]), "=r"(r[1]), "=r"(r[2]), "=r"(r[3]) : "r"(addr));
}
__device__ __forceinline__ void ldsm_x4_t(uint32_t (&r)[4], uint32_t addr) {
    asm volatile("ldmatrix.sync.aligned.m8n8.x4.trans.shared.b16 {%0,%1,%2,%3}, [%4];"
                 : "=r"(r[0]), "=r"(r[1]), "=r"(r[2]), "=r"(r[3]) : "r"(addr));
}
__device__ __forceinline__ void mma16816(float (&c)[4], const uint32_t (&a)[4],
                                         uint32_t b0, uint32_t b1) {
    asm volatile(
        "mma.sync.aligned.m16n8k16.row.col.f32.bf16.bf16.f32 "
        "{%0,%1,%2,%3}, {%4,%5,%6,%7}, {%8,%9}, {%0,%1,%2,%3};"
        : "+f"(c[0]), "+f"(c[1]), "+f"(c[2]), "+f"(c[3])
        : "r"(a[0]), "r"(a[1]), "r"(a[2]), "r"(a[3]), "r"(b0), "r"(b1));
}
__device__ __forceinline__ void cp16(uint32_t smem, const void* g) {
    asm volatile("cp.async.ca.shared.global [%0], [%1], 16;" :: "r"(smem), "l"(g));
}
__device__ __forceinline__ uint32_t packbf2(__nv_bfloat16 a, __nv_bfloat16 b) {
    __nv_bfloat162 t = __halves2bfloat162(a, b);
    return *(uint32_t*)&t;
}

// ---------------------------------------------------------------------------
// Split-bf16 GEMM: C[M,N] = A[M,K] @ B[N,K]^T.
// 128x128 block tile, warp tile 32x64, 2-stage cp.async, k32 steps.
// ---------------------------------------------------------------------------
__global__ __launch_bounds__(256, 2) void gemm_nt_split(
    const __nv_bfloat16* __restrict__ Ah, const __nv_bfloat16* __restrict__ Al,
    const __nv_bfloat16* __restrict__ Bh, const __nv_bfloat16* __restrict__ Bl,
    float* __restrict__ C, int M, int N, int K) {
    __shared__ __align__(16) __nv_bfloat16 sA[2][2][128][40];
    __shared__ __align__(16) __nv_bfloat16 sB[2][2][128][40];

    const int tid = threadIdx.x;
    const int wid = tid >> 5, lane = tid & 31;
    const int wm = (wid & 3) * 32;
    const int wn = (wid >> 2) * 64;
    const int m0 = blockIdx.y * 128, n0 = blockIdx.x * 128;
    const int KSTEPS = K >> 5;

    float acc[2][8][4] = {};
    const uint32_t aBase = (uint32_t)__cvta_generic_to_shared(&sA[0][0][0][0]);
    const uint32_t bBase = (uint32_t)__cvta_generic_to_shared(&sB[0][0][0][0]);
    const uint32_t STG_A = 2 * 128 * 40 * 2;

    auto load_stage = [&](int st, int kg) {
#pragma unroll
        for (int i = 0; i < 2; i++) {
            int c = tid + i * 256;
            int row = c >> 2, kc = (c & 3) * 8;
            uint32_t off = (uint32_t)(row * 40 + kc) * 2;
            cp16(aBase + st * STG_A + off, Ah + (size_t)(m0 + row) * K + kg + kc);
            cp16(aBase + st * STG_A + 128 * 40 * 2 + off, Al + (size_t)(m0 + row) * K + kg + kc);
            cp16(bBase + st * STG_A + off, Bh + (size_t)(n0 + row) * K + kg + kc);
            cp16(bBase + st * STG_A + 128 * 40 * 2 + off, Bl + (size_t)(n0 + row) * K + kg + kc);
        }
        asm volatile("cp.async.commit_group;");
    };

    load_stage(0, 0);

    int st = 0;
    for (int kidx = 0; kidx < KSTEPS; kidx++) {
        if (kidx + 1 < KSTEPS) {
            load_stage(st ^ 1, (kidx + 1) * 32);
            asm volatile("cp.async.wait_group 1;");
        } else {
            asm volatile("cp.async.wait_group 0;");
        }
        __syncthreads();

        uint32_t aST = aBase + st * STG_A;
        uint32_t bST = bBase + st * STG_A;

#pragma unroll
        for (int s = 0; s < 2; s++) {
            uint32_t aH[2][4], aL[2][4], bF[4][4];
#pragma unroll
            for (int mt = 0; mt < 2; mt++) {
                int row = wm + mt * 16 + (lane & 15);
                int koff = s * 16 + (lane >> 4) * 8;
                uint32_t ad = aST + (uint32_t)(row * 40 + koff) * 2;
                ldsm_x4(aH[mt], ad);
                ldsm_x4(aL[mt], ad + 128 * 40 * 2);
            }
            {
                int rowp = wn + ((lane >> 4) & 1) * 8 + (lane & 7);
                int koff = s * 16 + ((lane >> 3) & 1) * 8;
#pragma unroll
                for (int p = 0; p < 4; p++)
                    ldsm_x4(bF[p], bST + (uint32_t)((rowp + p * 16) * 40 + koff) * 2);
            }
#pragma unroll
            for (int mt = 0; mt < 2; mt++)
#pragma unroll
                for (int nt = 0; nt < 8; nt++) {
                    uint32_t b0 = bF[nt >> 1][(nt & 1) * 2];
                    uint32_t b1 = bF[nt >> 1][(nt & 1) * 2 + 1];
                    mma16816(acc[mt][nt], aH[mt], b0, b1);
                    mma16816(acc[mt][nt], aL[mt], b0, b1);
                }
            {
                int rowp = wn + ((lane >> 4) & 1) * 8 + (lane & 7);
                int koff = s * 16 + ((lane >> 3) & 1) * 8;
#pragma unroll
                for (int p = 0; p < 4; p++)
                    ldsm_x4(bF[p], bST + (uint32_t)(128 * 40 + (rowp + p * 16) * 40 + koff) * 2);
            }
#pragma unroll
            for (int mt = 0; mt < 2; mt++)
#pragma unroll
                for (int nt = 0; nt < 8; nt++) {
                    uint32_t b0 = bF[nt >> 1][(nt & 1) * 2];
                    uint32_t b1 = bF[nt >> 1][(nt & 1) * 2 + 1];
                    mma16816(acc[mt][nt], aH[mt], b0, b1);
                }
        }
        __syncthreads();
        st ^= 1;
    }

#pragma unroll
    for (int mt = 0; mt < 2; mt++)
#pragma unroll
        for (int nt = 0; nt < 8; nt++) {
            int r = m0 + wm + mt * 16 + (lane >> 2);
            int cc = n0 + wn + nt * 8 + (lane & 3) * 2;
            *(float2*)(C + (size_t)r * N + cc) = make_float2(acc[mt][nt][0], acc[mt][nt][1]);
            *(float2*)(C + (size_t)(r + 8) * N + cc) = make_float2(acc[mt][nt][2], acc[mt][nt][3]);
        }
}

// ---------------------------------------------------------------------------
// Fused rope+split for QKV: tmp [B,S,3H] -> qh/ql,kh/kl (rope), vh/vl.
// ---------------------------------------------------------------------------
__global__ __launch_bounds__(256) void rope_qkv(const float* __restrict__ tmp,
                                                __nv_bfloat16* __restrict__ qh,
                                                __nv_bfloat16* __restrict__ ql,
                                                __nv_bfloat16* __restrict__ kh,
                                                __nv_bfloat16* __restrict__ kl,
                                                __nv_bfloat16* __restrict__ vh,
                                                __nv_bfloat16* __restrict__ vl) {
    int idx = blockIdx.x * blockDim.x + threadIdx.x;
    if (idx >= Bsz * NH * S * 32) return;
    int d = idx & 31;
    int s = (idx >> 5) & (S - 1);
    int h = (idx >> 16) & (NH - 1);
    int b = idx >> 20;

    const float* p = tmp + (size_t)(b * S + s) * (3 * H) + h * HD;
    float q0 = p[d], q1 = p[d + 32];
    float k0 = p[H + d], k1 = p[H + d + 32];
    float v0 = p[2 * H + d], v1 = p[2 * H + d + 32];

    float c = g_cos[s * 32 + d];
    float sn = g_sin[s * 32 + d];
    float nq0 = q0 * c - q1 * sn, nq1 = q1 * c + q0 * sn;
    float nk0 = k0 * c - k1 * sn, nk1 = k1 * c + k0 * sn;

    size_t o = ((size_t)(b * NH + h) * S + s) * HD;
    __nv_bfloat16 t;
    t = __float2bfloat16(nq0); qh[o + d] = t;      ql[o + d] = __float2bfloat16(nq0 - __bfloat162float(t));
    t = __float2bfloat16(nq1); qh[o + d + 32] = t; ql[o + d + 32] = __float2bfloat16(nq1 - __bfloat162float(t));
    t = __float2bfloat16(nk0); kh[o + d] = t;      kl[o + d] = __float2bfloat16(nk0 - __bfloat162float(t));
    t = __float2bfloat16(nk1); kh[o + d + 32] = t; kl[o + d + 32] = __float2bfloat16(nk1 - __bfloat162float(t));
    t = __float2bfloat16(v0);  vh[o + d] = t;      vl[o + d] = __float2bfloat16(v0 - __bfloat162float(t));
    t = __float2bfloat16(v1);  vh[o + d + 32] = t; vl[o + d + 32] = __float2bfloat16(v1 - __bfloat162float(t));
}

// ---------------------------------------------------------------------------
// QK^T 128x128 tile via 3-pass split MMA. sQ/sK: [2][128][72] (hi/lo).
// ---------------------------------------------------------------------------
__device__ __forceinline__ void qk_tile_compute(float (&acc)[2][8][4],
                                                uint32_t qBase, uint32_t kBase,
                                                int wm, int wn, int lane) {
#pragma unroll
    for (int mt = 0; mt < 2; mt++)
#pragma unroll
        for (int nt = 0; nt < 8; nt++)
#pragma unroll
            for (int j = 0; j < 4; j++) acc[mt][nt][j] = 0.f;
#pragma unroll
    for (int s = 0; s < 4; s++) {
        uint32_t aH[2][4], aL[2][4], bF[4][4];
#pragma unroll
        for (int mt = 0; mt < 2; mt++) {
            int row = wm + mt * 16 + (lane & 15);
            int koff = s * 16 + (lane >> 4) * 8;
            uint32_t ad = qBase + (uint32_t)(row * 72 + koff) * 2;
            ldsm_x4(aH[mt], ad);
            ldsm_x4(aL[mt], ad + 128 * 72 * 2);
        }
        int rowp = wn + ((lane >> 4) & 1) * 8 + (lane & 7);
        int koff2 = s * 16 + ((lane >> 3) & 1) * 8;
#pragma unroll
        for (int p = 0; p < 4; p++)
            ldsm_x4(bF[p], kBase + (uint32_t)((rowp + p * 16) * 72 + koff2) * 2);
#pragma unroll
        for (int mt = 0; mt < 2; mt++)
#pragma unroll
            for (int nt = 0; nt < 8; nt++) {
                uint32_t b0 = bF[nt >> 1][(nt & 1) * 2];
                uint32_t b1 = bF[nt >> 1][(nt & 1) * 2 + 1];
                mma16816(acc[mt][nt], aH[mt], b0, b1);
                mma16816(acc[mt][nt], aL[mt], b0, b1);
            }
#pragma unroll
        for (int p = 0; p < 4; p++)
            ldsm_x4(bF[p], kBase + (uint32_t)((rowp + p * 16) * 72 + koff2) * 2 + 128 * 72 * 2);
#pragma unroll
        for (int mt = 0; mt < 2; mt++)
#pragma unroll
            for (int nt = 0; nt < 8; nt++) {
                uint32_t b0 = bF[nt >> 1][(nt & 1) * 2];
                uint32_t b1 = bF[nt >> 1][(nt & 1) * 2 + 1];
                mma16816(acc[mt][nt], aH[mt], b0, b1);
            }
    }
}

// ---------------------------------------------------------------------------
// Fused attention: per (128-query strip, head): pass A computes row stats
// online (no gmem writes), pass B recomputes scores, writes normalized attn,
// and accumulates O = P V via in-register fragment conversion.
// ---------------------------------------------------------------------------
__global__ __launch_bounds__(256, 1) void fused_attn(
    const __nv_bfloat16* __restrict__ Qh, const __nv_bfloat16* __restrict__ Ql,
    const __nv_bfloat16* __restrict__ Kh, const __nv_bfloat16* __restrict__ Kl,
    const __nv_bfloat16* __restrict__ Vh, const __nv_bfloat16* __restrict__ Vl,
    const float* __restrict__ bias, const int* __restrict__ mask,
    float* __restrict__ attn, float* __restrict__ ctx) {
    __shared__ __align__(16) __nv_bfloat16 sQ[2][128][72];
    __shared__ __align__(16) __nv_bfloat16 sK[2][128][72];
    __shared__ __align__(16) __nv_bfloat16 sV[2][128][72];
    __shared__ float sO[128][66];
    __shared__ float sStat[2][2][128];   // [warp-group][m|l][row]
    __shared__ float sM[128], sInvL[128];
    __shared__ int sMask[128];

    const int bh = blockIdx.y;
    const int b = bh >> 4;
    const int h = bh & 15;
    const int m0 = (int)(gridDim.x - 1 - blockIdx.x) * 128;  // big strips first
    const int kmax = m0 + 128;
    const int tid = threadIdx.x;
    const int wid = tid >> 5, lane = tid & 31;
    const int wm = (wid & 3) * 32;
    const int wg = wid >> 2;
    const int wn = wg * 64;

    const __nv_bfloat16* Qhb = Qh + (size_t)bh * S * HD;
    const __nv_bfloat16* Qlb = Ql + (size_t)bh * S * HD;
    const __nv_bfloat16* Khb = Kh + (size_t)bh * S * HD;
    const __nv_bfloat16* Klb = Kl + (size_t)bh * S * HD;
    const __nv_bfloat16* Vhb = Vh + (size_t)bh * S * HD;
    const __nv_bfloat16* Vlb = Vl + (size_t)bh * S * HD;
    float* attnB = attn + (size_t)bh * S * S;

    const uint32_t qBase = (uint32_t)__cvta_generic_to_shared(&sQ[0][0][0]);
    const uint32_t kBase = (uint32_t)__cvta_generic_to_shared(&sK[0][0][0]);
    const uint32_t vBase = (uint32_t)__cvta_generic_to_shared(&sV[0][0][0]);

    // Zero upper-triangle tail of this strip (cols kmax..S).
    {
        int r = tid >> 1;
        float4 z = make_float4(0.f, 0.f, 0.f, 0.f);
        for (int c = kmax + (tid & 1) * 4; c < S; c += 8)
            *(float4*)(attnB + (size_t)(m0 + r) * S + c) = z;
    }

    // Load Q strip (hi/lo) once.
#pragma unroll
    for (int i = 0; i < 4; i++) {
        int c = tid + i * 256;
        int row = c >> 3, col = (c & 7) * 8;
        *(uint4*)&sQ[0][row][col] = *(const uint4*)(Qhb + (size_t)(m0 + row) * HD + col);
        *(uint4*)&sQ[1][row][col] = *(const uint4*)(Qlb + (size_t)(m0 + row) * HD + col);
    }

    float m_run[4] = {-1e30f, -1e30f, -1e30f, -1e30f};
    float l_run[4] = {};

    // ---------------- PASS A: stats ----------------
    for (int n0 = 0; n0 < kmax; n0 += 128) {
        __syncthreads();
#pragma unroll
        for (int i = 0; i < 4; i++) {
            int c = tid + i * 256;
            int row = c >> 3, col = (c & 7) * 8;
            *(uint4*)&sK[0][row][col] = *(const uint4*)(Khb + (size_t)(n0 + row) * HD + col);
            *(uint4*)&sK[1][row][col] = *(const uint4*)(Klb + (size_t)(n0 + row) * HD + col);
        }
        if (tid < 128) sMask[tid] = mask[b * S + n0 + tid];
        __syncthreads();

        float acc[2][8][4];
        qk_tile_compute(acc, qBase, kBase, wm, wn, lane);

#pragma unroll
        for (int mt = 0; mt < 2; mt++) {
#pragma unroll
            for (int half = 0; half < 2; half++) {
                int rs = mt * 2 + half;
                int r = m0 + wm + mt * 16 + (lane >> 2) + half * 8;
                const float* brow = bias + (size_t)r * S;
                float tv[16];
#pragma unroll
                for (int nt = 0; nt < 8; nt++) {
                    int cl = wn + nt * 8 + (lane & 3) * 2;
                    int c = n0 + cl;
                    float2 bv = *(const float2*)(brow + c);
                    float s0 = fmaf(acc[mt][nt][half * 2 + 0], 0.125f, bv.x);
                    float s1 = fmaf(acc[mt][nt][half * 2 + 1], 0.125f, bv.y);
                    if (c > r || sMask[cl] == 0) s0 = -1e30f;
                    if (c + 1 > r || sMask[cl + 1] == 0) s1 = -1e30f;
                    tv[nt * 2] = s0; tv[nt * 2 + 1] = s1;
                }
                float tm = tv[0];
#pragma unroll
                for (int j = 1; j < 16; j++) tm = fmaxf(tm, tv[j]);
                float mn = fmaxf(m_run[rs], tm);
                float add = 0.f;
#pragma unroll
                for (int j = 0; j < 16; j++) add += __expf(tv[j] - mn);
                l_run[rs] = l_run[rs] * __expf(m_run[rs] - mn) + add;
                m_run[rs] = mn;
            }
        }
    }

    // Merge stats: quad (lane&3) then across the 2 warp groups.
#pragma unroll
    for (int rs = 0; rs < 4; rs++) {
#pragma unroll
        for (int o = 1; o <= 2; o <<= 1) {
            float mo = __shfl_xor_sync(0xffffffffu, m_run[rs], o);
            float lo = __shfl_xor_sync(0xffffffffu, l_run[rs], o);
            float mn = fmaxf(m_run[rs], mo);
            l_run[rs] = l_run[rs] * __expf(m_run[rs] - mn) + lo * __expf(mo - mn);
            m_run[rs] = mn;
        }
    }
    if ((lane & 3) == 0) {
#pragma unroll
        for (int mt = 0; mt < 2; mt++)
#pragma unroll
            for (int half = 0; half < 2; half++) {
                int rs = mt * 2 + half;
                int row = wm + mt * 16 + (lane >> 2) + half * 8;
                sStat[wg][0][row] = m_run[rs];
                sStat[wg][1][row] = l_run[rs];
            }
    }
    __syncthreads();
    if (tid < 128) {
        float mA = sStat[0][0][tid], lA = sStat[0][1][tid];
        float mB = sStat[1][0][tid], lB = sStat[1][1][tid];
        float M = fmaxf(mA, mB);
        float L = lA * __expf(mA - M) + lB * __expf(mB - M);
        sM[tid] = M;
        sInvL[tid] = 1.f / L;
    }
    __syncthreads();

    float Mr[4], iLr[4];
#pragma unroll
    for (int mt = 0; mt < 2; mt++)
#pragma unroll
        for (int half = 0; half < 2; half++) {
            int rs = mt * 2 + half;
            int row = wm + mt * 16 + (lane >> 2) + half * 8;
            Mr[rs] = sM[row];
            iLr[rs] = sInvL[row];
        }

    // ---------------- PASS B: recompute, write P, accumulate O ----------------
    float accO[2][8][4] = {};
    for (int n0 = 0; n0 < kmax; n0 += 128) {
        __syncthreads();
#pragma unroll
        for (int i = 0; i < 4; i++) {
            int c = tid + i * 256;
            int row = c >> 3, col = (c & 7) * 8;
            *(uint4*)&sK[0][row][col] = *(const uint4*)(Khb + (size_t)(n0 + row) * HD + col);
            *(uint4*)&sK[1][row][col] = *(const uint4*)(Klb + (size_t)(n0 + row) * HD + col);
            *(uint4*)&sV[0][row][col] = *(const uint4*)(Vhb + (size_t)(n0 + row) * HD + col);
            *(uint4*)&sV[1][row][col] = *(const uint4*)(Vlb + (size_t)(n0 + row) * HD + col);
        }
        if (tid < 128) sMask[tid] = mask[b * S + n0 + tid];
        __syncthreads();

        float acc[2][8][4];
        qk_tile_compute(acc, qBase, kBase, wm, wn, lane);

        // Normalize to P, write attn, keep P in acc for the AV MMA.
#pragma unroll
        for (int mt = 0; mt < 2; mt++) {
#pragma unroll
            for (int half = 0; half < 2; half++) {
                int rs = mt * 2 + half;
                int r = m0 + wm + mt * 16 + (lane >> 2) + half * 8;
                const float* brow = bias + (size_t)r * S;
                float* arow = attnB + (size_t)r * S;
#pragma unroll
                for (int nt = 0; nt < 8; nt++) {
                    int cl = wn + nt * 8 + (lane & 3) * 2;
                    int c = n0 + cl;
                    float2 bv = *(const float2*)(brow + c);
                    float s0 = fmaf(acc[mt][nt][half * 2 + 0], 0.125f, bv.x);
                    float s1 = fmaf(acc[mt][nt][half * 2 + 1], 0.125f, bv.y);
                    if (c > r || sMask[cl] == 0) s0 = -1e30f;
                    if (c + 1 > r || sMask[cl + 1] == 0) s1 = -1e30f;
                    float p0 = __expf(s0 - Mr[rs]) * iLr[rs];
                    float p1 = __expf(s1 - Mr[rs]) * iLr[rs];
                    *(float2*)(arow + c) = make_float2(p0, p1);
                    acc[mt][nt][half * 2 + 0] = p0;
                    acc[mt][nt][half * 2 + 1] = p1;
                }
            }
        }

        // AV: convert P fragments -> A operands in registers; V via ldmatrix.trans.
#pragma unroll
        for (int s2 = 0; s2 < 4; s2++) {
            uint32_t bVh[4][4], bVl[4][4];
            int krow = wn + s2 * 16 + (lane & 7) + ((lane >> 3) & 1) * 8;
#pragma unroll
            for (int p = 0; p < 4; p++) {
                int col = (lane >> 4) * 8 + p * 16;
                uint32_t ad = vBase + (uint32_t)(krow * 72 + col) * 2;
                ldsm_x4_t(bVh[p], ad);
                ldsm_x4_t(bVl[p], ad + 128 * 72 * 2);
            }
#pragma unroll
            for (int mt = 0; mt < 2; mt++) {
                uint32_t aP[4], aPl[4];
#pragma unroll
                for (int q2 = 0; q2 < 2; q2++) {
                    int nt = 2 * s2 + q2;
                    float v0 = acc[mt][nt][0], v1 = acc[mt][nt][1];
                    float v2 = acc[mt][nt][2], v3 = acc[mt][nt][3];
                    __nv_bfloat16 h0 = __float2bfloat16(v0), h1 = __float2bfloat16(v1);
                    __nv_bfloat16 h2 = __float2bfloat16(v2), h3 = __float2bfloat16(v3);
                    aP[q2 * 2 + 0] = packbf2(h0, h1);
                    aP[q2 * 2 + 1] = packbf2(h2, h3);
                    aPl[q2 * 2 + 0] = packbf2(__float2bfloat16(v0 - __bfloat162float(h0)),
                                              __float2bfloat16(v1 - __bfloat162float(h1)));
                    aPl[q2 * 2 + 1] = packbf2(__float2bfloat16(v2 - __bfloat162float(h2)),
                                              __float2bfloat16(v3 - __bfloat162float(h3)));
                }
#pragma unroll
                for (int nt = 0; nt < 8; nt++) {
                    uint32_t b0 = bVh[nt >> 1][(nt & 1) * 2];
                    uint32_t b1 = bVh[nt >> 1][(nt & 1) * 2 + 1];
                    mma16816(accO[mt][nt], aP, b0, b1);    // Ph*Vh
                    mma16816(accO[mt][nt], aPl, b0, b1);   // Pl*Vh
                    uint32_t c0 = bVl[nt >> 1][(nt & 1) * 2];
                    uint32_t c1 = bVl[nt >> 1][(nt & 1) * 2 + 1];
                    mma16816(accO[mt][nt], aP, c0, c1);    // Ph*Vl
                }
            }
        }
    }

    // Merge O across the two warp groups, write ctx [B,S,NH,HD].
    __syncthreads();
    if (wg == 1) {
#pragma unroll
        for (int mt = 0; mt < 2; mt++)
#pragma unroll
            for (int nt = 0; nt < 8; nt++)
#pragma unroll
                for (int half = 0; half < 2; half++) {
                    int rl = wm + mt * 16 + (lane >> 2) + half * 8;
                    int c = nt * 8 + (lane & 3) * 2;
                    sO[rl][c] = accO[mt][nt][half * 2 + 0];
                    sO[rl][c + 1] = accO[mt][nt][half * 2 + 1];
                }
    }
    __syncthreads();
    if (wg == 0) {
#pragma unroll
        for (int mt = 0; mt < 2; mt++)
#pragma unroll
            for (int nt = 0; nt < 8; nt++)
#pragma unroll
                for (int half = 0; half < 2; half++) {
                    int rl = wm + mt * 16 + (lane >> 2) + half * 8;
                    int c = nt * 8 + (lane & 3) * 2;
                    float o0 = accO[mt][nt][half * 2 + 0] + sO[rl][c];
                    float o1 = accO[mt][nt][half * 2 + 1] + sO[rl][c + 1];
                    *(float2*)(ctx + ((size_t)(b * S + m0 + rl) * NH + h) * HD + c) =
                        make_float2(o0, o1);
                }
    }
}

// ---------------------------------------------------------------------------
extern "C" void kernel_launch(void* const* d_in, const int* in_sizes, int n_in,
                              void* d_out, int out_size) {
    const float* x    = (const float*)d_in[0];
    const int*   mask = (const int*)d_in[1];
    const float* Wq   = (const float*)d_in[2];
    const float* Wk   = (const float*)d_in[3];
    const float* Wv   = (const float*)d_in[4];
    const float* Wo   = (const float*)d_in[5];
    const float* bias = (const float*)d_in[6];

    float* out  = (float*)d_out;
    float* attn = out + (size_t)Bsz * S * H;

    float *tmp, *ctx;
    cudaGetSymbolAddress((void**)&tmp, g_tmp);
    cudaGetSymbolAddress((void**)&ctx, g_ctx);
    __nv_bfloat16 *xh, *xl, *ch, *cl, *wh, *wl;
    __nv_bfloat16 *qh, *ql, *kh, *kl, *vh, *vl;
    cudaGetSymbolAddress((void**)&xh, g_xh);
    cudaGetSymbolAddress((void**)&xl, g_xl);
    cudaGetSymbolAddress((void**)&ch, g_ch);
    cudaGetSymbolAddress((void**)&cl, g_cl);
    cudaGetSymbolAddress((void**)&wh, g_wh);
    cudaGetSymbolAddress((void**)&wl, g_wl);
    cudaGetSymbolAddress((void**)&qh, g_qh);
    cudaGetSymbolAddress((void**)&ql, g_ql);
    cudaGetSymbolAddress((void**)&kh, g_kh);
    cudaGetSymbolAddress((void**)&kl, g_kl);
    cudaGetSymbolAddress((void**)&vh, g_vh);
    cudaGetSymbolAddress((void**)&vl, g_vl);

    const int M = Bsz * S;                        // 4096
    const int MH = M * H;
    const int HH = H * H;
    const int rope_threads = Bsz * NH * S * 32;

    splitx_table<<<MH / 4 / 256, 256>>>(x, xh, xl);
    split_w4<<<dim3(HH / 4 / 256, 4), 256>>>(Wq, Wk, Wv, Wo, wh, wl);
    gemm_nt_split<<<dim3(3 * H / 128, M / 128), 256>>>(xh, xl, wh, wl, tmp,
                                                       M, 3 * H, H);
    rope_qkv<<<rope_threads / 256, 256>>>(tmp, qh, ql, kh, kl, vh, vl);
    fused_attn<<<dim3(S / 128, Bsz * NH), 256>>>(qh, ql, kh, kl, vh, vl,
                                                 bias, mask, attn, ctx);
    split_kernel<<<MH / 4 / 256, 256>>>(ctx, ch, cl, MH);
    gemm_nt_split<<<dim3(H / 128, M / 128), 256>>>(ch, cl, wh + 3 * HH,
                                                   wl + 3 * HH, out, M, H, H);
}